// round 7
// baseline (speedup 1.0000x reference)
#include <cuda_runtime.h>
#include <cuda_bf16.h>
#include <math.h>
#include <stdint.h>

// Problem constants
#define BB   2
#define LL   8192
#define DD   1024
#define HH   8
#define DH   128
#define NROW (BB*LL)     // 16384
#define DFF  (2*DD)      // 2048
#define LC   512
#define NCH  (LL/LC)     // 16
#define KSC  128         // ksum chunk count
#define KSL  (LL/KSC)    // 64 rows per ksum chunk
#define ATTN_EPS 1e-6f
#define LN_EPS   1e-5f

// ---------------------------------------------------------------------------
// Scratch (device globals: allocation-free per harness rules)
// ---------------------------------------------------------------------------
__device__ float g_q[NROW*DD];                  // x @ Wq (fp32, attention input)
__device__ float g_tmp[NROW*DD];                // msg@Wm fp32 (LN1 input), then mlp out
__device__ float g_kvp[BB*HH*NCH*DH*DH];        // KV partials per L-chunk
__device__ float g_kv[BB*HH*DH*DH];             // KV
__device__ float g_ksp[BB*HH*KSC*DH];           // Ksum partials
__device__ float g_ks[BB*HH*DH];                // Ksum
__device__ float g_z[NROW*HH];                  // 1/(Q.Ksum + eps)

// bf16 hi/lo split operands for tensor-core GEMMs
__device__ __nv_bfloat16 g_x_hi[NROW*DD],   g_x_lo[NROW*DD];
__device__ __nv_bfloat16 g_msg_hi[NROW*DD], g_msg_lo[NROW*DD];
__device__ __nv_bfloat16 g_tmp_hi[NROW*DD], g_tmp_lo[NROW*DD];
__device__ __nv_bfloat16 g_h1_hi[NROW*DFF], g_h1_lo[NROW*DFF];
// transposed+split weights: [N, K] K-major
__device__ __nv_bfloat16 g_wq_hi[DD*DD],  g_wq_lo[DD*DD];
__device__ __nv_bfloat16 g_wm_hi[DD*DD],  g_wm_lo[DD*DD];
__device__ __nv_bfloat16 g_w1_hi[DFF*DD], g_w1_lo[DFF*DD];
__device__ __nv_bfloat16 g_w2_hi[DD*DFF], g_w2_lo[DD*DFF];

// ---------------------------------------------------------------------------
// Helpers
// ---------------------------------------------------------------------------
__device__ __forceinline__ uint32_t smem_u32(const void* p) {
    uint32_t a;
    asm("{ .reg .u64 t; cvta.to.shared.u64 t, %1; cvt.u32.u64 %0, t; }" : "=r"(a) : "l"(p));
    return a;
}

__device__ __forceinline__ void splitf(float v, __nv_bfloat16& h, __nv_bfloat16& l) {
    h = __float2bfloat16(v);
    l = __float2bfloat16(v - __bfloat162float(h));
}

__device__ __forceinline__ float featf(float v) {
    return v > 0.f ? v + 1.f : expf(v);
}

#define LDSM4(r0, r1, r2, r3, addr) \
    asm volatile("ldmatrix.sync.aligned.m8n8.x4.shared.b16 {%0,%1,%2,%3}, [%4];" \
                 : "=r"(r0), "=r"(r1), "=r"(r2), "=r"(r3) : "r"(addr))

#define CP16(dst, src) \
    asm volatile("cp.async.cg.shared.global [%0], [%1], 16;" :: "r"(dst), "l"(src))
#define CP_COMMIT() asm volatile("cp.async.commit_group;" ::: "memory")
#define CP_WAIT1()  asm volatile("cp.async.wait_group 1;" ::: "memory")
#define CP_WAIT0()  asm volatile("cp.async.wait_group 0;" ::: "memory")

__device__ __forceinline__ void mma16816(float* c, const uint32_t* a,
                                         uint32_t b0, uint32_t b1) {
    asm volatile("mma.sync.aligned.m16n8k16.row.col.f32.bf16.bf16.f32 "
                 "{%0,%1,%2,%3}, {%4,%5,%6,%7}, {%8,%9}, {%0,%1,%2,%3};"
                 : "+f"(c[0]), "+f"(c[1]), "+f"(c[2]), "+f"(c[3])
                 : "r"(a[0]), "r"(a[1]), "r"(a[2]), "r"(a[3]), "r"(b0), "r"(b1));
}

// ---------------------------------------------------------------------------
// HMMA GEMM: C[M,N] = (Ahi+Alo)[M,K] @ (Bhi+Blo)^T, B stored [N,K] K-major.
// Block tile 128x128, K-chunk 32, 4 warps (2x2), warp tile 64x64.
// cp.async double-buffered. Hi/lo 3-pass with software-pipelined LDSM:
//   LDSM(ah,bh); LDSM(al) -> MMA(ah,bh); LDSM(bl) -> MMA(al,bh) -> MMA(ah,bl)
// EPI: 0 = fp32 C; 1 = fp32 C + bf16 hi/lo; 2 = relu then bf16 hi/lo only.
// ---------------------------------------------------------------------------
#define SROW  80
#define GTILE (128 * SROW)      // one array (128 rows x 32 bf16, padded)
#define GSTG  (4 * GTILE)       // Ah, Al, Bh, Bl
#define GSMEM (2 * GSTG)        // 81920 bytes, two stages

template <int EPI>
__global__ void __launch_bounds__(128, 2)
hgemm_k(const __nv_bfloat16* __restrict__ Ahi, const __nv_bfloat16* __restrict__ Alo,
        const __nv_bfloat16* __restrict__ Bhi, const __nv_bfloat16* __restrict__ Blo,
        float* __restrict__ C, __nv_bfloat16* __restrict__ Chi,
        __nv_bfloat16* __restrict__ Clo, int Nn, int K) {
    extern __shared__ __align__(16) char smem[];
    const uint32_t sb = smem_u32(smem);
    const int tid = threadIdx.x, warp = tid >> 5, lane = tid & 31;
    const int wm = warp >> 1, wn = warp & 1;           // 2 x 2 warp grid
    const int m0 = blockIdx.y * 128, n0 = blockIdx.x * 128;

    float acc[4][8][4] = {};   // [mtile][ntile][reg]

    // ldmatrix per-lane offsets (within one array tile)
    const uint32_t aoff = (uint32_t)(wm * 64 + (lane & 15)) * SROW + ((lane >> 4) << 4);
    const int nloc = (lane & 7) + ((lane >> 4) << 3);
    const uint32_t boff = (uint32_t)(wn * 64 + nloc) * SROW + (((lane >> 3) & 1) << 4);

    // cp.async per-thread: each thread loads 4 rows x 16B per array
    const int lrow = tid >> 2, lseg = tid & 3;

    auto load_stage = [&](int s, int kc) {
        const uint32_t base = sb + (uint32_t)s * GSTG;
#pragma unroll
        for (int i = 0; i < 4; i++) {
            const int r = lrow + i * 32;
            const uint32_t so = (uint32_t)r * SROW + lseg * 16;
            const size_t ga = (size_t)(m0 + r) * K + kc + lseg * 8;
            const size_t gb = (size_t)(n0 + r) * K + kc + lseg * 8;
            CP16(base + 0 * GTILE + so, Ahi + ga);
            CP16(base + 1 * GTILE + so, Alo + ga);
            CP16(base + 2 * GTILE + so, Bhi + gb);
            CP16(base + 3 * GTILE + so, Blo + gb);
        }
    };

    const int nch = K / 32;
    load_stage(0, 0);
    CP_COMMIT();

    for (int c = 0; c < nch; c++) {
        if (c + 1 < nch) {
            load_stage((c + 1) & 1, (c + 1) * 32);
            CP_COMMIT();
            CP_WAIT1();
        } else {
            CP_WAIT0();
        }
        __syncthreads();
        const uint32_t base = sb + (uint32_t)(c & 1) * GSTG;
#pragma unroll
        for (int ks = 0; ks < 2; ks++) {
            const uint32_t kso = (uint32_t)ks * 32;    // 16 bf16 = 32 bytes
            uint32_t ah[4][4], al[4][4], bh[4][4], bl[4][4];
            // stage 0: load ah, bh
#pragma unroll
            for (int mt = 0; mt < 4; mt++)
                LDSM4(ah[mt][0], ah[mt][1], ah[mt][2], ah[mt][3],
                      base + 0 * GTILE + aoff + (uint32_t)mt * 16 * SROW + kso);
#pragma unroll
            for (int p = 0; p < 4; p++)
                LDSM4(bh[p][0], bh[p][1], bh[p][2], bh[p][3],
                      base + 2 * GTILE + boff + (uint32_t)p * 16 * SROW + kso);
            // prefetch al (consumed in pass 2)
#pragma unroll
            for (int mt = 0; mt < 4; mt++)
                LDSM4(al[mt][0], al[mt][1], al[mt][2], al[mt][3],
                      base + 1 * GTILE + aoff + (uint32_t)mt * 16 * SROW + kso);
            // pass 1: ah * bh
#pragma unroll
            for (int mt = 0; mt < 4; mt++)
#pragma unroll
                for (int p = 0; p < 4; p++) {
                    mma16816(acc[mt][p * 2 + 0], ah[mt], bh[p][0], bh[p][1]);
                    mma16816(acc[mt][p * 2 + 1], ah[mt], bh[p][2], bh[p][3]);
                }
            // prefetch bl (consumed in pass 3)
#pragma unroll
            for (int p = 0; p < 4; p++)
                LDSM4(bl[p][0], bl[p][1], bl[p][2], bl[p][3],
                      base + 3 * GTILE + boff + (uint32_t)p * 16 * SROW + kso);
            // pass 2: al * bh
#pragma unroll
            for (int mt = 0; mt < 4; mt++)
#pragma unroll
                for (int p = 0; p < 4; p++) {
                    mma16816(acc[mt][p * 2 + 0], al[mt], bh[p][0], bh[p][1]);
                    mma16816(acc[mt][p * 2 + 1], al[mt], bh[p][2], bh[p][3]);
                }
            // pass 3: ah * bl
#pragma unroll
            for (int mt = 0; mt < 4; mt++)
#pragma unroll
                for (int p = 0; p < 4; p++) {
                    mma16816(acc[mt][p * 2 + 0], ah[mt], bl[p][0], bl[p][1]);
                    mma16816(acc[mt][p * 2 + 1], ah[mt], bl[p][2], bl[p][3]);
                }
        }
        __syncthreads();
    }

    // Epilogue: m16n8 acc mapping: c0,c1=(gid, t4*2,+1); c2,c3=(gid+8, ...)
    const int gid = lane >> 2, t4 = lane & 3;
#pragma unroll
    for (int mt = 0; mt < 4; mt++) {
#pragma unroll
        for (int nt = 0; nt < 8; nt++) {
            const float* c = acc[mt][nt];
            const int r0 = m0 + wm * 64 + mt * 16 + gid;
            const int cc = n0 + wn * 64 + nt * 8 + t4 * 2;
#pragma unroll
            for (int half = 0; half < 2; half++) {
                const int r = r0 + half * 8;
                float v0 = c[half * 2 + 0], v1 = c[half * 2 + 1];
                if (EPI <= 1) {
                    float2 f; f.x = v0; f.y = v1;
                    *(float2*)(C + (size_t)r * Nn + cc) = f;
                }
                if (EPI >= 1) {
                    if (EPI == 2) { v0 = fmaxf(v0, 0.f); v1 = fmaxf(v1, 0.f); }
                    __nv_bfloat16 h0, l0, h1, l1;
                    splitf(v0, h0, l0);
                    splitf(v1, h1, l1);
                    __nv_bfloat162 hh; hh.x = h0; hh.y = h1;
                    __nv_bfloat162 ll; ll.x = l0; ll.y = l1;
                    *(__nv_bfloat162*)(Chi + (size_t)r * Nn + cc) = hh;
                    *(__nv_bfloat162*)(Clo + (size_t)r * Nn + cc) = ll;
                }
            }
        }
    }
}

// ---------------------------------------------------------------------------
// Conversion kernels
// ---------------------------------------------------------------------------
__global__ void split_k(const float* __restrict__ in, __nv_bfloat16* __restrict__ hi,
                        __nv_bfloat16* __restrict__ lo, int n) {
    int i = blockIdx.x * 256 + threadIdx.x;
    if (i < n) {
        __nv_bfloat16 h, l;
        splitf(in[i], h, l);
        hi[i] = h;
        lo[i] = l;
    }
}

// W [K,N] fp32 -> Wt_hi/lo [N,K] bf16, tiled transpose (coalesced both sides)
__global__ void wtrans_k(const float* __restrict__ W, __nv_bfloat16* __restrict__ Thi,
                         __nv_bfloat16* __restrict__ Tlo, int K, int N) {
    __shared__ float t[32][33];
    const int k0 = blockIdx.y * 32, n0 = blockIdx.x * 32;
    const int tx = threadIdx.x, ty = threadIdx.y;   // 32 x 8
#pragma unroll
    for (int i = 0; i < 4; i++)
        t[ty + i * 8][tx] = W[(size_t)(k0 + ty + i * 8) * N + n0 + tx];
    __syncthreads();
#pragma unroll
    for (int i = 0; i < 4; i++) {
        float v = t[tx][ty + i * 8];
        __nv_bfloat16 h, l;
        splitf(v, h, l);
        const size_t o = (size_t)(n0 + ty + i * 8) * K + k0 + tx;
        Thi[o] = h;
        Tlo[o] = l;
    }
}

// ---------------------------------------------------------------------------
// Attention pieces
// ---------------------------------------------------------------------------
#define BK16 16

__global__ void __launch_bounds__(256) kv_part_k() {
    const int ch = blockIdx.x, bh = blockIdx.y;
    const int b = bh >> 3, h = bh & 7;
    __shared__ __align__(16) float Fs[BK16][DH];
    __shared__ __align__(16) float Vs[BK16][DH];
    const float invL = 1.0f / (float)LL;
    const int tid = threadIdx.x;
    const int rowL = tid >> 5;
    const int colL = (tid & 31) * 4;
    const int tr = (tid >> 4) * 8, tc = (tid & 15) * 8;
    float acc[8][8] = {};

    for (int l0 = ch * LC; l0 < ch * LC + LC; l0 += BK16) {
#pragma unroll
        for (int i = 0; i < 2; i++) {
            int l = l0 + rowL + i * 8;
            const float* p = g_q + (size_t)(b * LL + l) * DD + h * DH + colL;
            float4 v = *(const float4*)p;
            float4 f;
            f.x = featf(v.x); f.y = featf(v.y); f.z = featf(v.z); f.w = featf(v.w);
            *(float4*)&Fs[rowL + i * 8][colL] = f;
            float4 vv; vv.x = v.x * invL; vv.y = v.y * invL; vv.z = v.z * invL; vv.w = v.w * invL;
            *(float4*)&Vs[rowL + i * 8][colL] = vv;
        }
        __syncthreads();
#pragma unroll
        for (int kk = 0; kk < BK16; kk++) {
            float4 a0 = *(const float4*)&Fs[kk][tr];
            float4 a1 = *(const float4*)&Fs[kk][tr + 4];
            float4 b0 = *(const float4*)&Vs[kk][tc];
            float4 b1 = *(const float4*)&Vs[kk][tc + 4];
            float ra[8] = {a0.x, a0.y, a0.z, a0.w, a1.x, a1.y, a1.z, a1.w};
            float rb[8] = {b0.x, b0.y, b0.z, b0.w, b1.x, b1.y, b1.z, b1.w};
#pragma unroll
            for (int i = 0; i < 8; i++)
#pragma unroll
                for (int j = 0; j < 8; j++)
                    acc[i][j] = fmaf(ra[i], rb[j], acc[i][j]);
        }
        __syncthreads();
    }
    float* outp = g_kvp + (size_t)(bh * NCH + ch) * (DH * DH);
#pragma unroll
    for (int i = 0; i < 8; i++)
#pragma unroll
        for (int j = 0; j < 8; j += 4) {
            float4 v;
            v.x = acc[i][j]; v.y = acc[i][j + 1]; v.z = acc[i][j + 2]; v.w = acc[i][j + 3];
            *(float4*)(outp + (tr + i) * DH + tc + j) = v;
        }
}

__global__ void kv_reduce_k() {
    int idx = blockIdx.x * 256 + threadIdx.x;
    int bh = idx >> 14;
    int e = idx & 16383;
    float s = 0.f;
#pragma unroll
    for (int c = 0; c < NCH; c++)
        s += g_kvp[(size_t)(bh * NCH + c) * (DH * DH) + e];
    g_kv[idx] = s;
}

// Ksum partials: grid (KSC, B*H), 128 threads, 64 rows per chunk (unrolled)
__global__ void __launch_bounds__(128) ksum_part_k() {
    const int ch = blockIdx.x, bh = blockIdx.y;
    const int b = bh >> 3, h = bh & 7;
    const int i = threadIdx.x;
    float s = 0.f;
    const float* base = g_q + (size_t)(b * LL + ch * KSL) * DD + h * DH + i;
#pragma unroll 8
    for (int l = 0; l < KSL; l++)
        s += featf(base[(size_t)l * DD]);
    g_ksp[(bh * KSC + ch) * DH + i] = s;
}

__global__ void ksum_reduce_k() {
    int idx = blockIdx.x * 256 + threadIdx.x;
    int bh = idx >> 7;
    int i = idx & 127;
    float s = 0.f;
#pragma unroll
    for (int c = 0; c < KSC; c++)
        s += g_ksp[(bh * KSC + c) * DH + i];
    g_ks[idx] = s;
}

// Z: one warp per (n,h) pair; lanes split the 128-dim dot product.
__global__ void __launch_bounds__(256) z_k() {
    __shared__ float sk[BB * HH * DH];
    for (int i = threadIdx.x; i < BB * HH * DH; i += 256) sk[i] = g_ks[i];
    __syncthreads();
    const int wi = threadIdx.x >> 5, lane = threadIdx.x & 31;
    const int idx = blockIdx.x * 8 + wi;    // (n*H + h)
    const int n = idx >> 3, h = idx & 7;
    const int b = n >> 13;
    const float* qp = g_q + (size_t)n * DD + h * DH + lane * 4;
    const float* kp = sk + (b * HH + h) * DH + lane * 4;
    float4 v = *(const float4*)qp;
    float dot = featf(v.x) * kp[0] + featf(v.y) * kp[1] +
                featf(v.z) * kp[2] + featf(v.w) * kp[3];
#pragma unroll
    for (int o = 16; o > 0; o >>= 1) dot += __shfl_xor_sync(0xffffffffu, dot, o);
    if (lane == 0) g_z[idx] = 1.0f / (dot + ATTN_EPS);
}

// msg -> bf16 hi/lo directly (consumed only by the Wm GEMM)
__global__ void __launch_bounds__(256) msg_k() {
    const int bh = blockIdx.y;
    const int b = bh >> 3, h = bh & 7;
    const int l0 = blockIdx.x * 128;
    __shared__ __align__(16) float As[BK16][128];
    __shared__ __align__(16) float Ks[BK16][DH];
    const int tid = threadIdx.x;
    const int rowA = tid >> 2;
    const int colA = (tid & 3) * 4;
    const int rowB = tid >> 5;
    const int colB = (tid & 31) * 4;
    const int tr = (tid >> 4) * 8, tc = (tid & 15) * 8;
    float acc[8][8] = {};
    const float* kvb = g_kv + (size_t)bh * (DH * DH);

    for (int k0 = 0; k0 < DH; k0 += BK16) {
#pragma unroll
        for (int i = 0; i < 2; i++) {
            int l = l0 + rowA + i * 64;
            float4 v = *(const float4*)(g_q + (size_t)(b * LL + l) * DD + h * DH + k0 + colA);
            As[colA + 0][rowA + i * 64] = featf(v.x);
            As[colA + 1][rowA + i * 64] = featf(v.y);
            As[colA + 2][rowA + i * 64] = featf(v.z);
            As[colA + 3][rowA + i * 64] = featf(v.w);
        }
#pragma unroll
        for (int i = 0; i < 2; i++) {
            float4 v = *(const float4*)(kvb + (size_t)(k0 + rowB + i * 8) * DH + colB);
            *(float4*)(&Ks[rowB + i * 8][colB]) = v;
        }
        __syncthreads();
#pragma unroll
        for (int kk = 0; kk < BK16; kk++) {
            float4 a0 = *(const float4*)&As[kk][tr];
            float4 a1 = *(const float4*)&As[kk][tr + 4];
            float4 b0 = *(const float4*)&Ks[kk][tc];
            float4 b1 = *(const float4*)&Ks[kk][tc + 4];
            float ra[8] = {a0.x, a0.y, a0.z, a0.w, a1.x, a1.y, a1.z, a1.w};
            float rb[8] = {b0.x, b0.y, b0.z, b0.w, b1.x, b1.y, b1.z, b1.w};
#pragma unroll
            for (int i = 0; i < 8; i++)
#pragma unroll
                for (int j = 0; j < 8; j++)
                    acc[i][j] = fmaf(ra[i], rb[j], acc[i][j]);
        }
        __syncthreads();
    }
#pragma unroll
    for (int i = 0; i < 8; i++) {
        int n = b * LL + l0 + tr + i;
        float zs = g_z[n * HH + h] * (float)LL;
        __nv_bfloat16* hp = g_msg_hi + (size_t)n * DD + h * DH + tc;
        __nv_bfloat16* lp = g_msg_lo + (size_t)n * DD + h * DH + tc;
#pragma unroll
        for (int j = 0; j < 8; j += 2) {
            float a = acc[i][j] * zs, bq = acc[i][j + 1] * zs;
            __nv_bfloat16 ha, la, hb, lb;
            splitf(a, ha, la);
            splitf(bq, hb, lb);
            __nv_bfloat162 hh; hh.x = ha; hh.y = hb;
            __nv_bfloat162 ll; ll.x = la; ll.y = lb;
            *(__nv_bfloat162*)(hp + j) = hh;
            *(__nv_bfloat162*)(lp + j) = ll;
        }
    }
}

// ---------------------------------------------------------------------------
// LayerNorm + residual
// ---------------------------------------------------------------------------
__device__ __forceinline__ float warpReduceSum(float v) {
#pragma unroll
    for (int o = 16; o > 0; o >>= 1) v += __shfl_xor_sync(0xffffffffu, v, o);
    return v;
}

__global__ void __launch_bounds__(256) ln_k(const float* __restrict__ t,
                                            const float* __restrict__ base,
                                            const float* __restrict__ gam,
                                            const float* __restrict__ bet,
                                            float* __restrict__ out) {
    const int n = blockIdx.x;
    __shared__ float row[DD];
    __shared__ float rs[8], rs2[8];
    __shared__ float smu, srstd;
    const float* tp = t + (size_t)n * DD;
    float s = 0.f, s2 = 0.f;
    for (int d = threadIdx.x; d < DD; d += 256) {
        float v = tp[d];
        row[d] = v;
        s += v;
        s2 = fmaf(v, v, s2);
    }
    s = warpReduceSum(s);
    s2 = warpReduceSum(s2);
    int lane = threadIdx.x & 31, wid = threadIdx.x >> 5;
    if (lane == 0) { rs[wid] = s; rs2[wid] = s2; }
    __syncthreads();
    if (threadIdx.x < 32) {
        float a = (threadIdx.x < 8) ? rs[threadIdx.x] : 0.f;
        float b2 = (threadIdx.x < 8) ? rs2[threadIdx.x] : 0.f;
        a = warpReduceSum(a);
        b2 = warpReduceSum(b2);
        if (threadIdx.x == 0) {
            float mu = a * (1.0f / DD);
            float var = b2 * (1.0f / DD) - mu * mu;
            smu = mu;
            srstd = rsqrtf(var + LN_EPS);
        }
    }
    __syncthreads();
    float mu = smu, rstd = srstd;
    const float* bp = base + (size_t)n * DD;
    float* op = out + (size_t)n * DD;
    for (int d = threadIdx.x; d < DD; d += 256)
        op[d] = bp[d] + (row[d] - mu) * rstd * gam[d] + bet[d];
}

// ---------------------------------------------------------------------------
extern "C" void kernel_launch(void* const* d_in, const int* in_sizes, int n_in,
                              void* d_out, int out_size) {
    (void)in_sizes; (void)n_in; (void)out_size;
    const float* x  = (const float*)d_in[0];
    const float* Wq = (const float*)d_in[1];
    const float* Wm = (const float*)d_in[2];
    const float* W1 = (const float*)d_in[3];
    const float* W2 = (const float*)d_in[4];
    const float* g1 = (const float*)d_in[5];
    const float* b1 = (const float*)d_in[6];
    const float* g2 = (const float*)d_in[7];
    const float* b2 = (const float*)d_in[8];
    float* out = (float*)d_out;

    float *q, *tmp;
    __nv_bfloat16 *x_hi, *x_lo, *msg_hi, *msg_lo, *tmp_hi, *tmp_lo, *h1_hi, *h1_lo;
    __nv_bfloat16 *wq_hi, *wq_lo, *wm_hi, *wm_lo, *w1_hi, *w1_lo, *w2_hi, *w2_lo;
    cudaGetSymbolAddress((void**)&q,      g_q);
    cudaGetSymbolAddress((void**)&tmp,    g_tmp);
    cudaGetSymbolAddress((void**)&x_hi,   g_x_hi);
    cudaGetSymbolAddress((void**)&x_lo,   g_x_lo);
    cudaGetSymbolAddress((void**)&msg_hi, g_msg_hi);
    cudaGetSymbolAddress((void**)&msg_lo, g_msg_lo);
    cudaGetSymbolAddress((void**)&tmp_hi, g_tmp_hi);
    cudaGetSymbolAddress((void**)&tmp_lo, g_tmp_lo);
    cudaGetSymbolAddress((void**)&h1_hi,  g_h1_hi);
    cudaGetSymbolAddress((void**)&h1_lo,  g_h1_lo);
    cudaGetSymbolAddress((void**)&wq_hi,  g_wq_hi);
    cudaGetSymbolAddress((void**)&wq_lo,  g_wq_lo);
    cudaGetSymbolAddress((void**)&wm_hi,  g_wm_hi);
    cudaGetSymbolAddress((void**)&wm_lo,  g_wm_lo);
    cudaGetSymbolAddress((void**)&w1_hi,  g_w1_hi);
    cudaGetSymbolAddress((void**)&w1_lo,  g_w1_lo);
    cudaGetSymbolAddress((void**)&w2_hi,  g_w2_hi);
    cudaGetSymbolAddress((void**)&w2_lo,  g_w2_lo);

    cudaFuncSetAttribute(hgemm_k<0>, cudaFuncAttributeMaxDynamicSharedMemorySize, GSMEM);
    cudaFuncSetAttribute(hgemm_k<1>, cudaFuncAttributeMaxDynamicSharedMemorySize, GSMEM);
    cudaFuncSetAttribute(hgemm_k<2>, cudaFuncAttributeMaxDynamicSharedMemorySize, GSMEM);

    // 0. Convert inputs: x split; weights transpose+split
    split_k<<<(NROW * DD + 255) / 256, 256>>>(x, x_hi, x_lo, NROW * DD);
    wtrans_k<<<dim3(DD / 32, DD / 32), dim3(32, 8)>>>(Wq, wq_hi, wq_lo, DD, DD);
    wtrans_k<<<dim3(DFF / 32, DD / 32), dim3(32, 8)>>>(W1, w1_hi, w1_lo, DD, DFF);
    wtrans_k<<<dim3(DD / 32, DD / 32), dim3(32, 8)>>>(Wm, wm_hi, wm_lo, DD, DD);
    wtrans_k<<<dim3(DD / 32, DFF / 32), dim3(32, 8)>>>(W2, w2_hi, w2_lo, DFF, DD);

    // 1. q = x @ Wq (fp32 out for attention)
    hgemm_k<0><<<dim3(DD / 128, NROW / 128), 128, GSMEM>>>(
        x_hi, x_lo, wq_hi, wq_lo, q, nullptr, nullptr, DD, DD);
    // 2. attention reductions
    kv_part_k<<<dim3(NCH, BB * HH), 256>>>();
    kv_reduce_k<<<BB * HH * DH * DH / 256, 256>>>();
    ksum_part_k<<<dim3(KSC, BB * HH), 128>>>();
    ksum_reduce_k<<<BB * HH * DH / 256, 256>>>();
    z_k<<<NROW * HH / 8, 256>>>();
    // 3. msg (bf16 hi/lo out)
    msg_k<<<dim3(LL / 128, BB * HH), 256>>>();
    // 4. tmp = msg @ Wm (fp32 + hi/lo)  -- this is the rebinded "msg"
    hgemm_k<1><<<dim3(DD / 128, NROW / 128), 128, GSMEM>>>(
        msg_hi, msg_lo, wm_hi, wm_lo, tmp, tmp_hi, tmp_lo, DD, DD);
    // 5. out = x + LN(tmp)
    ln_k<<<NROW, 256>>>(tmp, x, g1, b1, out);
    // 6. h1 = relu(tmp @ W1) (hi/lo only)
    hgemm_k<2><<<dim3(DFF / 128, NROW / 128), 128, GSMEM>>>(
        tmp_hi, tmp_lo, w1_hi, w1_lo, nullptr, h1_hi, h1_lo, DFF, DD);
    // 7. tmp = h1 @ W2 (fp32)
    hgemm_k<0><<<dim3(DD / 128, NROW / 128), 128, GSMEM>>>(
        h1_hi, h1_lo, w2_hi, w2_lo, tmp, nullptr, nullptr, DD, DFF);
    // 8. out += LN(tmp)
    ln_k<<<NROW, 256>>>(tmp, out, g2, b2, out);
}

// round 8
// speedup vs baseline: 1.2953x; 1.2953x over previous
#include <cuda_runtime.h>
#include <cuda_fp16.h>
#include <math.h>
#include <stdint.h>

// Problem constants
#define BB   2
#define LL   8192
#define DD   1024
#define HH   8
#define DH   128
#define NROW (BB*LL)     // 16384
#define DFF  (2*DD)      // 2048
#define LC   512
#define NCH  (LL/LC)     // 16
#define KSC  128         // ksum chunk count
#define KSL  (LL/KSC)    // 64 rows per ksum chunk
#define ATTN_EPS 1e-6f
#define LN_EPS   1e-5f

// ---------------------------------------------------------------------------
// Scratch (device globals: allocation-free per harness rules)
// ---------------------------------------------------------------------------
__device__ float g_q[NROW*DD];                  // x @ Wq (fp32, attention input)
__device__ float g_tmp[NROW*DD];                // msg@Wm fp32 (LN1 input), then mlp out
__device__ float g_kvp[BB*HH*NCH*DH*DH];        // KV partials per L-chunk
__device__ float g_kv[BB*HH*DH*DH];             // KV
__device__ float g_ksp[BB*HH*KSC*DH];           // Ksum partials
__device__ float g_ks[BB*HH*DH];                // Ksum
__device__ float g_z[NROW*HH];                  // 1/(Q.Ksum + eps)

// fp16 operands. Activations single f16 except x (hi/lo for the Wq GEMM).
__device__ __half g_x_h[NROW*DD], g_x_l[NROW*DD];
__device__ __half g_msg_f[NROW*DD];
__device__ __half g_tmp_f[NROW*DD];
__device__ __half g_h1_f[NROW*DFF];
// transposed weights [N, K] K-major, fp16 hi/lo
__device__ __half g_wq_h[DD*DD],  g_wq_l[DD*DD];
__device__ __half g_wm_h[DD*DD],  g_wm_l[DD*DD];
__device__ __half g_w1_h[DFF*DD], g_w1_l[DFF*DD];
__device__ __half g_w2_h[DD*DFF], g_w2_l[DD*DFF];

// ---------------------------------------------------------------------------
// Helpers
// ---------------------------------------------------------------------------
__device__ __forceinline__ uint32_t smem_u32(const void* p) {
    uint32_t a;
    asm("{ .reg .u64 t; cvta.to.shared.u64 t, %1; cvt.u32.u64 %0, t; }" : "=r"(a) : "l"(p));
    return a;
}

__device__ __forceinline__ void splith(float v, __half& h, __half& l) {
    h = __float2half(v);
    l = __float2half(v - __half2float(h));
}

__device__ __forceinline__ float featf(float v) {
    return v > 0.f ? v + 1.f : expf(v);
}

#define LDSM4(r0, r1, r2, r3, addr) \
    asm volatile("ldmatrix.sync.aligned.m8n8.x4.shared.b16 {%0,%1,%2,%3}, [%4];" \
                 : "=r"(r0), "=r"(r1), "=r"(r2), "=r"(r3) : "r"(addr))

#define CP16(dst, src) \
    asm volatile("cp.async.cg.shared.global [%0], [%1], 16;" :: "r"(dst), "l"(src))
#define CP_COMMIT() asm volatile("cp.async.commit_group;" ::: "memory")
#define CP_WAIT1()  asm volatile("cp.async.wait_group 1;" ::: "memory")
#define CP_WAIT0()  asm volatile("cp.async.wait_group 0;" ::: "memory")

__device__ __forceinline__ void mma16816(float* c, const uint32_t* a,
                                         uint32_t b0, uint32_t b1) {
    asm volatile("mma.sync.aligned.m16n8k16.row.col.f32.f16.f16.f32 "
                 "{%0,%1,%2,%3}, {%4,%5,%6,%7}, {%8,%9}, {%0,%1,%2,%3};"
                 : "+f"(c[0]), "+f"(c[1]), "+f"(c[2]), "+f"(c[3])
                 : "r"(a[0]), "r"(a[1]), "r"(a[2]), "r"(a[3]), "r"(b0), "r"(b1));
}

// ---------------------------------------------------------------------------
// HMMA GEMM: C[M,N] = A[M,K] @ (Bh+Bl)^T  (SA=false, 2 passes)
//         or C[M,N] = (Ah+Al)[M,K] @ (Bh+Bl)^T (SA=true, 3 passes: ah*bh+al*bh+ah*bl)
// B stored [N,K] K-major, all fp16, fp32 accumulate.
// Block tile 128x128, K-chunk 32, 4 warps (2x2), warp tile 64x64, cp.async 2-stage.
// EPI: 0 = fp32 C; 1 = fp32 C + f16 Cf; 2 = relu then f16 Cf only.
// ---------------------------------------------------------------------------
#define SROW  80
#define GTILE (128 * SROW)      // one array (128 rows x 32 f16, padded)
#define GSTG  (4 * GTILE)       // slots: Ah, Bh, Bl, Al(optional)
#define GSMEM (2 * GSTG)        // 81920 bytes, two stages

template <int EPI, bool SA>
__global__ void __launch_bounds__(128, 2)
hgemm_k(const __half* __restrict__ Ah, const __half* __restrict__ Al,
        const __half* __restrict__ Bh, const __half* __restrict__ Bl,
        float* __restrict__ C, __half* __restrict__ Cf, int Nn, int K) {
    extern __shared__ __align__(16) char smem[];
    const uint32_t sb = smem_u32(smem);
    const int tid = threadIdx.x, warp = tid >> 5, lane = tid & 31;
    const int wm = warp >> 1, wn = warp & 1;           // 2 x 2 warp grid
    const int m0 = blockIdx.y * 128, n0 = blockIdx.x * 128;

    float acc[4][8][4] = {};   // [mtile][ntile][reg]

    const uint32_t aoff = (uint32_t)(wm * 64 + (lane & 15)) * SROW + ((lane >> 4) << 4);
    const int nloc = (lane & 7) + ((lane >> 4) << 3);
    const uint32_t boff = (uint32_t)(wn * 64 + nloc) * SROW + (((lane >> 3) & 1) << 4);

    const int lrow = tid >> 2, lseg = tid & 3;

    auto load_stage = [&](int s, int kc) {
        const uint32_t base = sb + (uint32_t)s * GSTG;
#pragma unroll
        for (int i = 0; i < 4; i++) {
            const int r = lrow + i * 32;
            const uint32_t so = (uint32_t)r * SROW + lseg * 16;
            const size_t ga = (size_t)(m0 + r) * K + kc + lseg * 8;
            const size_t gb = (size_t)(n0 + r) * K + kc + lseg * 8;
            CP16(base + 0 * GTILE + so, Ah + ga);
            CP16(base + 1 * GTILE + so, Bh + gb);
            CP16(base + 2 * GTILE + so, Bl + gb);
            if (SA) CP16(base + 3 * GTILE + so, Al + ga);
        }
    };

    const int nch = K / 32;
    load_stage(0, 0);
    CP_COMMIT();

    for (int c = 0; c < nch; c++) {
        if (c + 1 < nch) {
            load_stage((c + 1) & 1, (c + 1) * 32);
            CP_COMMIT();
            CP_WAIT1();
        } else {
            CP_WAIT0();
        }
        __syncthreads();
        const uint32_t base = sb + (uint32_t)(c & 1) * GSTG;
#pragma unroll
        for (int ks = 0; ks < 2; ks++) {
            const uint32_t kso = (uint32_t)ks * 32;    // 16 f16 = 32 bytes
            uint32_t ah[4][4], bh[4][4], bl[4][4];
#pragma unroll
            for (int mt = 0; mt < 4; mt++)
                LDSM4(ah[mt][0], ah[mt][1], ah[mt][2], ah[mt][3],
                      base + 0 * GTILE + aoff + (uint32_t)mt * 16 * SROW + kso);
#pragma unroll
            for (int p = 0; p < 4; p++)
                LDSM4(bh[p][0], bh[p][1], bh[p][2], bh[p][3],
                      base + 1 * GTILE + boff + (uint32_t)p * 16 * SROW + kso);
            // pass 1: ah * bh
#pragma unroll
            for (int mt = 0; mt < 4; mt++)
#pragma unroll
                for (int p = 0; p < 4; p++) {
                    mma16816(acc[mt][p * 2 + 0], ah[mt], bh[p][0], bh[p][1]);
                    mma16816(acc[mt][p * 2 + 1], ah[mt], bh[p][2], bh[p][3]);
                }
#pragma unroll
            for (int p = 0; p < 4; p++)
                LDSM4(bl[p][0], bl[p][1], bl[p][2], bl[p][3],
                      base + 2 * GTILE + boff + (uint32_t)p * 16 * SROW + kso);
            if (SA) {
                uint32_t al[4][4];
#pragma unroll
                for (int mt = 0; mt < 4; mt++)
                    LDSM4(al[mt][0], al[mt][1], al[mt][2], al[mt][3],
                          base + 3 * GTILE + aoff + (uint32_t)mt * 16 * SROW + kso);
                // pass: al * bh
#pragma unroll
                for (int mt = 0; mt < 4; mt++)
#pragma unroll
                    for (int p = 0; p < 4; p++) {
                        mma16816(acc[mt][p * 2 + 0], al[mt], bh[p][0], bh[p][1]);
                        mma16816(acc[mt][p * 2 + 1], al[mt], bh[p][2], bh[p][3]);
                    }
            }
            // pass: ah * bl
#pragma unroll
            for (int mt = 0; mt < 4; mt++)
#pragma unroll
                for (int p = 0; p < 4; p++) {
                    mma16816(acc[mt][p * 2 + 0], ah[mt], bl[p][0], bl[p][1]);
                    mma16816(acc[mt][p * 2 + 1], ah[mt], bl[p][2], bl[p][3]);
                }
        }
        __syncthreads();
    }

    // Epilogue: m16n8 acc mapping: c0,c1=(gid, t4*2,+1); c2,c3=(gid+8, ...)
    const int gid = lane >> 2, t4 = lane & 3;
#pragma unroll
    for (int mt = 0; mt < 4; mt++) {
#pragma unroll
        for (int nt = 0; nt < 8; nt++) {
            const float* c = acc[mt][nt];
            const int r0 = m0 + wm * 64 + mt * 16 + gid;
            const int cc = n0 + wn * 64 + nt * 8 + t4 * 2;
#pragma unroll
            for (int half_ = 0; half_ < 2; half_++) {
                const int r = r0 + half_ * 8;
                float v0 = c[half_ * 2 + 0], v1 = c[half_ * 2 + 1];
                if (EPI <= 1) {
                    float2 f; f.x = v0; f.y = v1;
                    *(float2*)(C + (size_t)r * Nn + cc) = f;
                }
                if (EPI >= 1) {
                    if (EPI == 2) { v0 = fmaxf(v0, 0.f); v1 = fmaxf(v1, 0.f); }
                    __half2 hh;
                    hh.x = __float2half(v0);
                    hh.y = __float2half(v1);
                    *(__half2*)(Cf + (size_t)r * Nn + cc) = hh;
                }
            }
        }
    }
}

// ---------------------------------------------------------------------------
// Conversion kernels
// ---------------------------------------------------------------------------
// x fp32 -> f16 hi/lo
__global__ void splitx_k(const float* __restrict__ in, __half* __restrict__ hi,
                         __half* __restrict__ lo, int n) {
    int i = blockIdx.x * 256 + threadIdx.x;
    if (i < n) {
        __half h, l;
        splith(in[i], h, l);
        hi[i] = h;
        lo[i] = l;
    }
}

// W [K,N] fp32 -> Wt_hi/lo [N,K] f16, tiled transpose (coalesced both sides)
__global__ void wtrans_k(const float* __restrict__ W, __half* __restrict__ Thi,
                         __half* __restrict__ Tlo, int K, int N) {
    __shared__ float t[32][33];
    const int k0 = blockIdx.y * 32, n0 = blockIdx.x * 32;
    const int tx = threadIdx.x, ty = threadIdx.y;   // 32 x 8
#pragma unroll
    for (int i = 0; i < 4; i++)
        t[ty + i * 8][tx] = W[(size_t)(k0 + ty + i * 8) * N + n0 + tx];
    __syncthreads();
#pragma unroll
    for (int i = 0; i < 4; i++) {
        float v = t[tx][ty + i * 8];
        __half h, l;
        splith(v, h, l);
        const size_t o = (size_t)(n0 + ty + i * 8) * K + k0 + tx;
        Thi[o] = h;
        Tlo[o] = l;
    }
}

// ---------------------------------------------------------------------------
// Attention pieces (fp32 SIMT)
// ---------------------------------------------------------------------------
#define BK16 16

__global__ void __launch_bounds__(256) kv_part_k() {
    const int ch = blockIdx.x, bh = blockIdx.y;
    const int b = bh >> 3, h = bh & 7;
    __shared__ __align__(16) float Fs[BK16][DH];
    __shared__ __align__(16) float Vs[BK16][DH];
    const float invL = 1.0f / (float)LL;
    const int tid = threadIdx.x;
    const int rowL = tid >> 5;
    const int colL = (tid & 31) * 4;
    const int tr = (tid >> 4) * 8, tc = (tid & 15) * 8;
    float acc[8][8] = {};

    for (int l0 = ch * LC; l0 < ch * LC + LC; l0 += BK16) {
#pragma unroll
        for (int i = 0; i < 2; i++) {
            int l = l0 + rowL + i * 8;
            const float* p = g_q + (size_t)(b * LL + l) * DD + h * DH + colL;
            float4 v = *(const float4*)p;
            float4 f;
            f.x = featf(v.x); f.y = featf(v.y); f.z = featf(v.z); f.w = featf(v.w);
            *(float4*)&Fs[rowL + i * 8][colL] = f;
            float4 vv; vv.x = v.x * invL; vv.y = v.y * invL; vv.z = v.z * invL; vv.w = v.w * invL;
            *(float4*)&Vs[rowL + i * 8][colL] = vv;
        }
        __syncthreads();
#pragma unroll
        for (int kk = 0; kk < BK16; kk++) {
            float4 a0 = *(const float4*)&Fs[kk][tr];
            float4 a1 = *(const float4*)&Fs[kk][tr + 4];
            float4 b0 = *(const float4*)&Vs[kk][tc];
            float4 b1 = *(const float4*)&Vs[kk][tc + 4];
            float ra[8] = {a0.x, a0.y, a0.z, a0.w, a1.x, a1.y, a1.z, a1.w};
            float rb[8] = {b0.x, b0.y, b0.z, b0.w, b1.x, b1.y, b1.z, b1.w};
#pragma unroll
            for (int i = 0; i < 8; i++)
#pragma unroll
                for (int j = 0; j < 8; j++)
                    acc[i][j] = fmaf(ra[i], rb[j], acc[i][j]);
        }
        __syncthreads();
    }
    float* outp = g_kvp + (size_t)(bh * NCH + ch) * (DH * DH);
#pragma unroll
    for (int i = 0; i < 8; i++)
#pragma unroll
        for (int j = 0; j < 8; j += 4) {
            float4 v;
            v.x = acc[i][j]; v.y = acc[i][j + 1]; v.z = acc[i][j + 2]; v.w = acc[i][j + 3];
            *(float4*)(outp + (tr + i) * DH + tc + j) = v;
        }
}

__global__ void kv_reduce_k() {
    int idx = blockIdx.x * 256 + threadIdx.x;
    int bh = idx >> 14;
    int e = idx & 16383;
    float s = 0.f;
#pragma unroll
    for (int c = 0; c < NCH; c++)
        s += g_kvp[(size_t)(bh * NCH + c) * (DH * DH) + e];
    g_kv[idx] = s;
}

__global__ void __launch_bounds__(128) ksum_part_k() {
    const int ch = blockIdx.x, bh = blockIdx.y;
    const int b = bh >> 3, h = bh & 7;
    const int i = threadIdx.x;
    float s = 0.f;
    const float* base = g_q + (size_t)(b * LL + ch * KSL) * DD + h * DH + i;
#pragma unroll 8
    for (int l = 0; l < KSL; l++)
        s += featf(base[(size_t)l * DD]);
    g_ksp[(bh * KSC + ch) * DH + i] = s;
}

__global__ void ksum_reduce_k() {
    int idx = blockIdx.x * 256 + threadIdx.x;
    int bh = idx >> 7;
    int i = idx & 127;
    float s = 0.f;
#pragma unroll
    for (int c = 0; c < KSC; c++)
        s += g_ksp[(bh * KSC + c) * DH + i];
    g_ks[idx] = s;
}

// Z: one warp per (n,h) pair; lanes split the 128-dim dot product.
__global__ void __launch_bounds__(256) z_k() {
    __shared__ float sk[BB * HH * DH];
    for (int i = threadIdx.x; i < BB * HH * DH; i += 256) sk[i] = g_ks[i];
    __syncthreads();
    const int wi = threadIdx.x >> 5, lane = threadIdx.x & 31;
    const int idx = blockIdx.x * 8 + wi;    // (n*H + h)
    const int n = idx >> 3, h = idx & 7;
    const int b = n >> 13;
    const float* qp = g_q + (size_t)n * DD + h * DH + lane * 4;
    const float* kp = sk + (b * HH + h) * DH + lane * 4;
    float4 v = *(const float4*)qp;
    float dot = featf(v.x) * kp[0] + featf(v.y) * kp[1] +
                featf(v.z) * kp[2] + featf(v.w) * kp[3];
#pragma unroll
    for (int o = 16; o > 0; o >>= 1) dot += __shfl_xor_sync(0xffffffffu, dot, o);
    if (lane == 0) g_z[idx] = 1.0f / (dot + ATTN_EPS);
}

// msg -> f16 single (consumed only by the Wm GEMM)
__global__ void __launch_bounds__(256) msg_k() {
    const int bh = blockIdx.y;
    const int b = bh >> 3, h = bh & 7;
    const int l0 = blockIdx.x * 128;
    __shared__ __align__(16) float As[BK16][128];
    __shared__ __align__(16) float Ks[BK16][DH];
    const int tid = threadIdx.x;
    const int rowA = tid >> 2;
    const int colA = (tid & 3) * 4;
    const int rowB = tid >> 5;
    const int colB = (tid & 31) * 4;
    const int tr = (tid >> 4) * 8, tc = (tid & 15) * 8;
    float acc[8][8] = {};
    const float* kvb = g_kv + (size_t)bh * (DH * DH);

    for (int k0 = 0; k0 < DH; k0 += BK16) {
#pragma unroll
        for (int i = 0; i < 2; i++) {
            int l = l0 + rowA + i * 64;
            float4 v = *(const float4*)(g_q + (size_t)(b * LL + l) * DD + h * DH + k0 + colA);
            As[colA + 0][rowA + i * 64] = featf(v.x);
            As[colA + 1][rowA + i * 64] = featf(v.y);
            As[colA + 2][rowA + i * 64] = featf(v.z);
            As[colA + 3][rowA + i * 64] = featf(v.w);
        }
#pragma unroll
        for (int i = 0; i < 2; i++) {
            float4 v = *(const float4*)(kvb + (size_t)(k0 + rowB + i * 8) * DH + colB);
            *(float4*)(&Ks[rowB + i * 8][colB]) = v;
        }
        __syncthreads();
#pragma unroll
        for (int kk = 0; kk < BK16; kk++) {
            float4 a0 = *(const float4*)&As[kk][tr];
            float4 a1 = *(const float4*)&As[kk][tr + 4];
            float4 b0 = *(const float4*)&Ks[kk][tc];
            float4 b1 = *(const float4*)&Ks[kk][tc + 4];
            float ra[8] = {a0.x, a0.y, a0.z, a0.w, a1.x, a1.y, a1.z, a1.w};
            float rb[8] = {b0.x, b0.y, b0.z, b0.w, b1.x, b1.y, b1.z, b1.w};
#pragma unroll
            for (int i = 0; i < 8; i++)
#pragma unroll
                for (int j = 0; j < 8; j++)
                    acc[i][j] = fmaf(ra[i], rb[j], acc[i][j]);
        }
        __syncthreads();
    }
#pragma unroll
    for (int i = 0; i < 8; i++) {
        int n = b * LL + l0 + tr + i;
        float zs = g_z[n * HH + h] * (float)LL;
        __half* hp = g_msg_f + (size_t)n * DD + h * DH + tc;
#pragma unroll
        for (int j = 0; j < 8; j += 2) {
            __half2 hh;
            hh.x = __float2half(acc[i][j] * zs);
            hh.y = __float2half(acc[i][j + 1] * zs);
            *(__half2*)(hp + j) = hh;
        }
    }
}

// ---------------------------------------------------------------------------
// LayerNorm + residual
// ---------------------------------------------------------------------------
__device__ __forceinline__ float warpReduceSum(float v) {
#pragma unroll
    for (int o = 16; o > 0; o >>= 1) v += __shfl_xor_sync(0xffffffffu, v, o);
    return v;
}

__global__ void __launch_bounds__(256) ln_k(const float* __restrict__ t,
                                            const float* __restrict__ base,
                                            const float* __restrict__ gam,
                                            const float* __restrict__ bet,
                                            float* __restrict__ out) {
    const int n = blockIdx.x;
    __shared__ float row[DD];
    __shared__ float rs[8], rs2[8];
    __shared__ float smu, srstd;
    const float* tp = t + (size_t)n * DD;
    float s = 0.f, s2 = 0.f;
    for (int d = threadIdx.x; d < DD; d += 256) {
        float v = tp[d];
        row[d] = v;
        s += v;
        s2 = fmaf(v, v, s2);
    }
    s = warpReduceSum(s);
    s2 = warpReduceSum(s2);
    int lane = threadIdx.x & 31, wid = threadIdx.x >> 5;
    if (lane == 0) { rs[wid] = s; rs2[wid] = s2; }
    __syncthreads();
    if (threadIdx.x < 32) {
        float a = (threadIdx.x < 8) ? rs[threadIdx.x] : 0.f;
        float b2 = (threadIdx.x < 8) ? rs2[threadIdx.x] : 0.f;
        a = warpReduceSum(a);
        b2 = warpReduceSum(b2);
        if (threadIdx.x == 0) {
            float mu = a * (1.0f / DD);
            float var = b2 * (1.0f / DD) - mu * mu;
            smu = mu;
            srstd = rsqrtf(var + LN_EPS);
        }
    }
    __syncthreads();
    float mu = smu, rstd = srstd;
    const float* bp = base + (size_t)n * DD;
    float* op = out + (size_t)n * DD;
    for (int d = threadIdx.x; d < DD; d += 256)
        op[d] = bp[d] + (row[d] - mu) * rstd * gam[d] + bet[d];
}

// ---------------------------------------------------------------------------
extern "C" void kernel_launch(void* const* d_in, const int* in_sizes, int n_in,
                              void* d_out, int out_size) {
    (void)in_sizes; (void)n_in; (void)out_size;
    const float* x  = (const float*)d_in[0];
    const float* Wq = (const float*)d_in[1];
    const float* Wm = (const float*)d_in[2];
    const float* W1 = (const float*)d_in[3];
    const float* W2 = (const float*)d_in[4];
    const float* g1 = (const float*)d_in[5];
    const float* b1 = (const float*)d_in[6];
    const float* g2 = (const float*)d_in[7];
    const float* b2 = (const float*)d_in[8];
    float* out = (float*)d_out;

    float *q, *tmp;
    __half *x_h, *x_l, *msg_f, *tmp_f, *h1_f;
    __half *wq_h, *wq_l, *wm_h, *wm_l, *w1_h, *w1_l, *w2_h, *w2_l;
    cudaGetSymbolAddress((void**)&q,     g_q);
    cudaGetSymbolAddress((void**)&tmp,   g_tmp);
    cudaGetSymbolAddress((void**)&x_h,   g_x_h);
    cudaGetSymbolAddress((void**)&x_l,   g_x_l);
    cudaGetSymbolAddress((void**)&msg_f, g_msg_f);
    cudaGetSymbolAddress((void**)&tmp_f, g_tmp_f);
    cudaGetSymbolAddress((void**)&h1_f,  g_h1_f);
    cudaGetSymbolAddress((void**)&wq_h,  g_wq_h);
    cudaGetSymbolAddress((void**)&wq_l,  g_wq_l);
    cudaGetSymbolAddress((void**)&wm_h,  g_wm_h);
    cudaGetSymbolAddress((void**)&wm_l,  g_wm_l);
    cudaGetSymbolAddress((void**)&w1_h,  g_w1_h);
    cudaGetSymbolAddress((void**)&w1_l,  g_w1_l);
    cudaGetSymbolAddress((void**)&w2_h,  g_w2_h);
    cudaGetSymbolAddress((void**)&w2_l,  g_w2_l);

    cudaFuncSetAttribute(hgemm_k<0, true>,  cudaFuncAttributeMaxDynamicSharedMemorySize, GSMEM);
    cudaFuncSetAttribute(hgemm_k<0, false>, cudaFuncAttributeMaxDynamicSharedMemorySize, GSMEM);
    cudaFuncSetAttribute(hgemm_k<1, false>, cudaFuncAttributeMaxDynamicSharedMemorySize, GSMEM);
    cudaFuncSetAttribute(hgemm_k<2, false>, cudaFuncAttributeMaxDynamicSharedMemorySize, GSMEM);

    // 0. Convert inputs
    splitx_k<<<(NROW * DD + 255) / 256, 256>>>(x, x_h, x_l, NROW * DD);
    wtrans_k<<<dim3(DD / 32, DD / 32), dim3(32, 8)>>>(Wq, wq_h, wq_l, DD, DD);
    wtrans_k<<<dim3(DFF / 32, DD / 32), dim3(32, 8)>>>(W1, w1_h, w1_l, DD, DFF);
    wtrans_k<<<dim3(DD / 32, DD / 32), dim3(32, 8)>>>(Wm, wm_h, wm_l, DD, DD);
    wtrans_k<<<dim3(DD / 32, DFF / 32), dim3(32, 8)>>>(W2, w2_h, w2_l, DFF, DD);

    // 1. q = x @ Wq (3-pass: x split — attention amplifies q error)
    hgemm_k<0, true><<<dim3(DD / 128, NROW / 128), 128, GSMEM>>>(
        x_h, x_l, wq_h, wq_l, q, nullptr, DD, DD);
    // 2. attention reductions (fp32)
    kv_part_k<<<dim3(NCH, BB * HH), 256>>>();
    kv_reduce_k<<<BB * HH * DH * DH / 256, 256>>>();
    ksum_part_k<<<dim3(KSC, BB * HH), 128>>>();
    ksum_reduce_k<<<BB * HH * DH / 256, 256>>>();
    z_k<<<NROW * HH / 8, 256>>>();
    // 3. msg (f16 out)
    msg_k<<<dim3(LL / 128, BB * HH), 256>>>();
    // 4. tmp = msg @ Wm (2-pass; fp32 + f16)  -- this is the rebinded "msg"
    hgemm_k<1, false><<<dim3(DD / 128, NROW / 128), 128, GSMEM>>>(
        msg_f, nullptr, wm_h, wm_l, tmp, tmp_f, DD, DD);
    // 5. out = x + LN(tmp)
    ln_k<<<NROW, 256>>>(tmp, x, g1, b1, out);
    // 6. h1 = relu(tmp @ W1) (2-pass; f16 only)
    hgemm_k<2, false><<<dim3(DFF / 128, NROW / 128), 128, GSMEM>>>(
        tmp_f, nullptr, w1_h, w1_l, nullptr, h1_f, DFF, DD);
    // 7. tmp = h1 @ W2 (2-pass; fp32)
    hgemm_k<0, false><<<dim3(DD / 128, NROW / 128), 128, GSMEM>>>(
        h1_f, nullptr, w2_h, w2_l, tmp, nullptr, DD, DFF);
    // 8. out += LN(tmp)
    ln_k<<<NROW, 256>>>(tmp, out, g2, b2, out);
}

// round 9
// speedup vs baseline: 1.7140x; 1.3233x over previous
#include <cuda_runtime.h>
#include <cuda_fp16.h>
#include <math.h>
#include <stdint.h>

// Problem constants
#define BB   2
#define LL   8192
#define DD   1024
#define HH   8
#define DH   128
#define NROW (BB*LL)     // 16384
#define DFF  (2*DD)      // 2048
#define LC   512
#define NCH  (LL/LC)     // 16
#define KSC  128         // ksum chunk count
#define KSL  (LL/KSC)    // 64 rows per ksum chunk
#define ATTN_EPS 1e-6f
#define LN_EPS   1e-5f

// ---------------------------------------------------------------------------
// Scratch (device globals: allocation-free per harness rules)
// ---------------------------------------------------------------------------
__device__ float g_q[NROW*DD];                  // x @ Wq (fp32, attention input)
__device__ float g_tmp[NROW*DD];                // msg@Wm fp32 (LN1 input), then mlp out
__device__ float g_kvp[BB*HH*NCH*DH*DH];        // KV partials per L-chunk
__device__ float g_kv[BB*HH*DH*DH];             // KV
__device__ float g_ksp[BB*HH*KSC*DH];           // Ksum partials
__device__ float g_ks[BB*HH*DH];                // Ksum
__device__ float g_z[NROW*HH];                  // 1/(Q.Ksum + eps)

// fp16 operands. Activations single f16 except x (hi/lo for the Wq GEMM).
__device__ __half g_x_h[NROW*DD], g_x_l[NROW*DD];
__device__ __half g_msg_f[NROW*DD];
__device__ __half g_tmp_f[NROW*DD];
__device__ __half g_h1_f[NROW*DFF];
// transposed weights [N, K] K-major, fp16. Only Wq needs the lo part.
__device__ __half g_wq_h[DD*DD],  g_wq_l[DD*DD];
__device__ __half g_wm_h[DD*DD];
__device__ __half g_w1_h[DFF*DD];
__device__ __half g_w2_h[DD*DFF];

// ---------------------------------------------------------------------------
// Helpers
// ---------------------------------------------------------------------------
__device__ __forceinline__ uint32_t smem_u32(const void* p) {
    uint32_t a;
    asm("{ .reg .u64 t; cvta.to.shared.u64 t, %1; cvt.u32.u64 %0, t; }" : "=r"(a) : "l"(p));
    return a;
}

__device__ __forceinline__ void splith(float v, __half& h, __half& l) {
    h = __float2half(v);
    l = __float2half(v - __half2float(h));
}

__device__ __forceinline__ float featf(float v) {
    return v > 0.f ? v + 1.f : expf(v);
}

#define LDSM4(r0, r1, r2, r3, addr) \
    asm volatile("ldmatrix.sync.aligned.m8n8.x4.shared.b16 {%0,%1,%2,%3}, [%4];" \
                 : "=r"(r0), "=r"(r1), "=r"(r2), "=r"(r3) : "r"(addr))

#define CP16(dst, src) \
    asm volatile("cp.async.cg.shared.global [%0], [%1], 16;" :: "r"(dst), "l"(src))
#define CP_COMMIT() asm volatile("cp.async.commit_group;" ::: "memory")
#define CP_WAIT1()  asm volatile("cp.async.wait_group 1;" ::: "memory")
#define CP_WAIT0()  asm volatile("cp.async.wait_group 0;" ::: "memory")

__device__ __forceinline__ void mma16816(float* c, const uint32_t* a,
                                         uint32_t b0, uint32_t b1) {
    asm volatile("mma.sync.aligned.m16n8k16.row.col.f32.f16.f16.f32 "
                 "{%0,%1,%2,%3}, {%4,%5,%6,%7}, {%8,%9}, {%0,%1,%2,%3};"
                 : "+f"(c[0]), "+f"(c[1]), "+f"(c[2]), "+f"(c[3])
                 : "r"(a[0]), "r"(a[1]), "r"(a[2]), "r"(a[3]), "r"(b0), "r"(b1));
}

// ---------------------------------------------------------------------------
// HMMA GEMM, B stored [N,K] K-major, fp16 in / fp32 accumulate.
// PASSES=1: C = A @ Bh^T                 (single f16 both sides)
// PASSES=3: C = (Ah+Al) @ (Bh+Bl)^T     (ah*bh + al*bh + ah*bl)
// Block tile 128x128, K-chunk 32, 4 warps (2x2), warp tile 64x64, cp.async 2-stage.
// EPI: 0 = fp32 C; 1 = fp32 C + f16 Cf; 2 = relu then f16 Cf only.
// ---------------------------------------------------------------------------
#define SROW  80
#define GTILE (128 * SROW)      // one array (128 rows x 32 f16, padded)

template <int EPI, int PASSES>
__global__ void __launch_bounds__(128, 2)
hgemm_k(const __half* __restrict__ Ah, const __half* __restrict__ Al,
        const __half* __restrict__ Bh, const __half* __restrict__ Bl,
        float* __restrict__ C, __half* __restrict__ Cf, int Nn, int K) {
    constexpr int NSLOT = (PASSES == 1) ? 2 : 4;    // Ah,Bh[,Bl,Al]
    constexpr int GSTG = NSLOT * GTILE;
    extern __shared__ __align__(16) char smem[];
    const uint32_t sb = smem_u32(smem);
    const int tid = threadIdx.x, warp = tid >> 5, lane = tid & 31;
    const int wm = warp >> 1, wn = warp & 1;           // 2 x 2 warp grid
    const int m0 = blockIdx.y * 128, n0 = blockIdx.x * 128;

    float acc[4][8][4] = {};   // [mtile][ntile][reg]

    const uint32_t aoff = (uint32_t)(wm * 64 + (lane & 15)) * SROW + ((lane >> 4) << 4);
    const int nloc = (lane & 7) + ((lane >> 4) << 3);
    const uint32_t boff = (uint32_t)(wn * 64 + nloc) * SROW + (((lane >> 3) & 1) << 4);

    const int lrow = tid >> 2, lseg = tid & 3;

    auto load_stage = [&](int s, int kc) {
        const uint32_t base = sb + (uint32_t)s * GSTG;
#pragma unroll
        for (int i = 0; i < 4; i++) {
            const int r = lrow + i * 32;
            const uint32_t so = (uint32_t)r * SROW + lseg * 16;
            const size_t ga = (size_t)(m0 + r) * K + kc + lseg * 8;
            const size_t gb = (size_t)(n0 + r) * K + kc + lseg * 8;
            CP16(base + 0 * GTILE + so, Ah + ga);
            CP16(base + 1 * GTILE + so, Bh + gb);
            if (PASSES == 3) {
                CP16(base + 2 * GTILE + so, Bl + gb);
                CP16(base + 3 * GTILE + so, Al + ga);
            }
        }
    };

    const int nch = K / 32;
    load_stage(0, 0);
    CP_COMMIT();

    for (int c = 0; c < nch; c++) {
        if (c + 1 < nch) {
            load_stage((c + 1) & 1, (c + 1) * 32);
            CP_COMMIT();
            CP_WAIT1();
        } else {
            CP_WAIT0();
        }
        __syncthreads();
        const uint32_t base = sb + (uint32_t)(c & 1) * GSTG;
#pragma unroll
        for (int ks = 0; ks < 2; ks++) {
            const uint32_t kso = (uint32_t)ks * 32;    // 16 f16 = 32 bytes
            uint32_t ah[4][4], bh[4][4];
#pragma unroll
            for (int mt = 0; mt < 4; mt++)
                LDSM4(ah[mt][0], ah[mt][1], ah[mt][2], ah[mt][3],
                      base + 0 * GTILE + aoff + (uint32_t)mt * 16 * SROW + kso);
#pragma unroll
            for (int p = 0; p < 4; p++)
                LDSM4(bh[p][0], bh[p][1], bh[p][2], bh[p][3],
                      base + 1 * GTILE + boff + (uint32_t)p * 16 * SROW + kso);
            // pass 1: ah * bh
#pragma unroll
            for (int mt = 0; mt < 4; mt++)
#pragma unroll
                for (int p = 0; p < 4; p++) {
                    mma16816(acc[mt][p * 2 + 0], ah[mt], bh[p][0], bh[p][1]);
                    mma16816(acc[mt][p * 2 + 1], ah[mt], bh[p][2], bh[p][3]);
                }
            if (PASSES == 3) {
                uint32_t al[4][4], bl[4][4];
#pragma unroll
                for (int p = 0; p < 4; p++)
                    LDSM4(bl[p][0], bl[p][1], bl[p][2], bl[p][3],
                          base + 2 * GTILE + boff + (uint32_t)p * 16 * SROW + kso);
#pragma unroll
                for (int mt = 0; mt < 4; mt++)
                    LDSM4(al[mt][0], al[mt][1], al[mt][2], al[mt][3],
                          base + 3 * GTILE + aoff + (uint32_t)mt * 16 * SROW + kso);
                // pass 2: al * bh
#pragma unroll
                for (int mt = 0; mt < 4; mt++)
#pragma unroll
                    for (int p = 0; p < 4; p++) {
                        mma16816(acc[mt][p * 2 + 0], al[mt], bh[p][0], bh[p][1]);
                        mma16816(acc[mt][p * 2 + 1], al[mt], bh[p][2], bh[p][3]);
                    }
                // pass 3: ah * bl
#pragma unroll
                for (int mt = 0; mt < 4; mt++)
#pragma unroll
                    for (int p = 0; p < 4; p++) {
                        mma16816(acc[mt][p * 2 + 0], ah[mt], bl[p][0], bl[p][1]);
                        mma16816(acc[mt][p * 2 + 1], ah[mt], bl[p][2], bl[p][3]);
                    }
            }
        }
        __syncthreads();
    }

    // Epilogue: m16n8 acc mapping: c0,c1=(gid, t4*2,+1); c2,c3=(gid+8, ...)
    const int gid = lane >> 2, t4 = lane & 3;
#pragma unroll
    for (int mt = 0; mt < 4; mt++) {
#pragma unroll
        for (int nt = 0; nt < 8; nt++) {
            const float* c = acc[mt][nt];
            const int r0 = m0 + wm * 64 + mt * 16 + gid;
            const int cc = n0 + wn * 64 + nt * 8 + t4 * 2;
#pragma unroll
            for (int half_ = 0; half_ < 2; half_++) {
                const int r = r0 + half_ * 8;
                float v0 = c[half_ * 2 + 0], v1 = c[half_ * 2 + 1];
                if (EPI <= 1) {
                    float2 f; f.x = v0; f.y = v1;
                    *(float2*)(C + (size_t)r * Nn + cc) = f;
                }
                if (EPI >= 1) {
                    if (EPI == 2) { v0 = fmaxf(v0, 0.f); v1 = fmaxf(v1, 0.f); }
                    __half2 hh;
                    hh.x = __float2half(v0);
                    hh.y = __float2half(v1);
                    *(__half2*)(Cf + (size_t)r * Nn + cc) = hh;
                }
            }
        }
    }
}

// ---------------------------------------------------------------------------
// Conversion kernels
// ---------------------------------------------------------------------------
// x fp32 -> f16 hi/lo
__global__ void splitx_k(const float* __restrict__ in, __half* __restrict__ hi,
                         __half* __restrict__ lo, int n) {
    int i = blockIdx.x * 256 + threadIdx.x;
    if (i < n) {
        __half h, l;
        splith(in[i], h, l);
        hi[i] = h;
        lo[i] = l;
    }
}

// W [K,N] fp32 -> Wt hi (and optional lo) [N,K] f16, tiled transpose
__global__ void wtrans_k(const float* __restrict__ W, __half* __restrict__ Thi,
                         __half* __restrict__ Tlo, int K, int N) {
    __shared__ float t[32][33];
    const int k0 = blockIdx.y * 32, n0 = blockIdx.x * 32;
    const int tx = threadIdx.x, ty = threadIdx.y;   // 32 x 8
#pragma unroll
    for (int i = 0; i < 4; i++)
        t[ty + i * 8][tx] = W[(size_t)(k0 + ty + i * 8) * N + n0 + tx];
    __syncthreads();
#pragma unroll
    for (int i = 0; i < 4; i++) {
        float v = t[tx][ty + i * 8];
        __half h, l;
        splith(v, h, l);
        const size_t o = (size_t)(n0 + ty + i * 8) * K + k0 + tx;
        Thi[o] = h;
        if (Tlo) Tlo[o] = l;
    }
}

// ---------------------------------------------------------------------------
// Attention pieces (fp32 SIMT)
// ---------------------------------------------------------------------------
#define BK16 16

__global__ void __launch_bounds__(256) kv_part_k() {
    const int ch = blockIdx.x, bh = blockIdx.y;
    const int b = bh >> 3, h = bh & 7;
    __shared__ __align__(16) float Fs[BK16][DH];
    __shared__ __align__(16) float Vs[BK16][DH];
    const float invL = 1.0f / (float)LL;
    const int tid = threadIdx.x;
    const int rowL = tid >> 5;
    const int colL = (tid & 31) * 4;
    const int tr = (tid >> 4) * 8, tc = (tid & 15) * 8;
    float acc[8][8] = {};

    for (int l0 = ch * LC; l0 < ch * LC + LC; l0 += BK16) {
#pragma unroll
        for (int i = 0; i < 2; i++) {
            int l = l0 + rowL + i * 8;
            const float* p = g_q + (size_t)(b * LL + l) * DD + h * DH + colL;
            float4 v = *(const float4*)p;
            float4 f;
            f.x = featf(v.x); f.y = featf(v.y); f.z = featf(v.z); f.w = featf(v.w);
            *(float4*)&Fs[rowL + i * 8][colL] = f;
            float4 vv; vv.x = v.x * invL; vv.y = v.y * invL; vv.z = v.z * invL; vv.w = v.w * invL;
            *(float4*)&Vs[rowL + i * 8][colL] = vv;
        }
        __syncthreads();
#pragma unroll
        for (int kk = 0; kk < BK16; kk++) {
            float4 a0 = *(const float4*)&Fs[kk][tr];
            float4 a1 = *(const float4*)&Fs[kk][tr + 4];
            float4 b0 = *(const float4*)&Vs[kk][tc];
            float4 b1 = *(const float4*)&Vs[kk][tc + 4];
            float ra[8] = {a0.x, a0.y, a0.z, a0.w, a1.x, a1.y, a1.z, a1.w};
            float rb[8] = {b0.x, b0.y, b0.z, b0.w, b1.x, b1.y, b1.z, b1.w};
#pragma unroll
            for (int i = 0; i < 8; i++)
#pragma unroll
                for (int j = 0; j < 8; j++)
                    acc[i][j] = fmaf(ra[i], rb[j], acc[i][j]);
        }
        __syncthreads();
    }
    float* outp = g_kvp + (size_t)(bh * NCH + ch) * (DH * DH);
#pragma unroll
    for (int i = 0; i < 8; i++)
#pragma unroll
        for (int j = 0; j < 8; j += 4) {
            float4 v;
            v.x = acc[i][j]; v.y = acc[i][j + 1]; v.z = acc[i][j + 2]; v.w = acc[i][j + 3];
            *(float4*)(outp + (tr + i) * DH + tc + j) = v;
        }
}

__global__ void kv_reduce_k() {
    int idx = blockIdx.x * 256 + threadIdx.x;
    int bh = idx >> 14;
    int e = idx & 16383;
    float s = 0.f;
#pragma unroll
    for (int c = 0; c < NCH; c++)
        s += g_kvp[(size_t)(bh * NCH + c) * (DH * DH) + e];
    g_kv[idx] = s;
}

__global__ void __launch_bounds__(128) ksum_part_k() {
    const int ch = blockIdx.x, bh = blockIdx.y;
    const int b = bh >> 3, h = bh & 7;
    const int i = threadIdx.x;
    float s = 0.f;
    const float* base = g_q + (size_t)(b * LL + ch * KSL) * DD + h * DH + i;
#pragma unroll 8
    for (int l = 0; l < KSL; l++)
        s += featf(base[(size_t)l * DD]);
    g_ksp[(bh * KSC + ch) * DH + i] = s;
}

__global__ void ksum_reduce_k() {
    int idx = blockIdx.x * 256 + threadIdx.x;
    int bh = idx >> 7;
    int i = idx & 127;
    float s = 0.f;
#pragma unroll
    for (int c = 0; c < KSC; c++)
        s += g_ksp[(bh * KSC + c) * DH + i];
    g_ks[idx] = s;
}

// Z: one warp per (n,h) pair; lanes split the 128-dim dot product.
__global__ void __launch_bounds__(256) z_k() {
    __shared__ float sk[BB * HH * DH];
    for (int i = threadIdx.x; i < BB * HH * DH; i += 256) sk[i] = g_ks[i];
    __syncthreads();
    const int wi = threadIdx.x >> 5, lane = threadIdx.x & 31;
    const int idx = blockIdx.x * 8 + wi;    // (n*H + h)
    const int n = idx >> 3, h = idx & 7;
    const int b = n >> 13;
    const float* qp = g_q + (size_t)n * DD + h * DH + lane * 4;
    const float* kp = sk + (b * HH + h) * DH + lane * 4;
    float4 v = *(const float4*)qp;
    float dot = featf(v.x) * kp[0] + featf(v.y) * kp[1] +
                featf(v.z) * kp[2] + featf(v.w) * kp[3];
#pragma unroll
    for (int o = 16; o > 0; o >>= 1) dot += __shfl_xor_sync(0xffffffffu, dot, o);
    if (lane == 0) g_z[idx] = 1.0f / (dot + ATTN_EPS);
}

// msg -> f16 single (consumed only by the Wm GEMM)
__global__ void __launch_bounds__(256) msg_k() {
    const int bh = blockIdx.y;
    const int b = bh >> 3, h = bh & 7;
    const int l0 = blockIdx.x * 128;
    __shared__ __align__(16) float As[BK16][128];
    __shared__ __align__(16) float Ks[BK16][DH];
    const int tid = threadIdx.x;
    const int rowA = tid >> 2;
    const int colA = (tid & 3) * 4;
    const int rowB = tid >> 5;
    const int colB = (tid & 31) * 4;
    const int tr = (tid >> 4) * 8, tc = (tid & 15) * 8;
    float acc[8][8] = {};
    const float* kvb = g_kv + (size_t)bh * (DH * DH);

    for (int k0 = 0; k0 < DH; k0 += BK16) {
#pragma unroll
        for (int i = 0; i < 2; i++) {
            int l = l0 + rowA + i * 64;
            float4 v = *(const float4*)(g_q + (size_t)(b * LL + l) * DD + h * DH + k0 + colA);
            As[colA + 0][rowA + i * 64] = featf(v.x);
            As[colA + 1][rowA + i * 64] = featf(v.y);
            As[colA + 2][rowA + i * 64] = featf(v.z);
            As[colA + 3][rowA + i * 64] = featf(v.w);
        }
#pragma unroll
        for (int i = 0; i < 2; i++) {
            float4 v = *(const float4*)(kvb + (size_t)(k0 + rowB + i * 8) * DH + colB);
            *(float4*)(&Ks[rowB + i * 8][colB]) = v;
        }
        __syncthreads();
#pragma unroll
        for (int kk = 0; kk < BK16; kk++) {
            float4 a0 = *(const float4*)&As[kk][tr];
            float4 a1 = *(const float4*)&As[kk][tr + 4];
            float4 b0 = *(const float4*)&Ks[kk][tc];
            float4 b1 = *(const float4*)&Ks[kk][tc + 4];
            float ra[8] = {a0.x, a0.y, a0.z, a0.w, a1.x, a1.y, a1.z, a1.w};
            float rb[8] = {b0.x, b0.y, b0.z, b0.w, b1.x, b1.y, b1.z, b1.w};
#pragma unroll
            for (int i = 0; i < 8; i++)
#pragma unroll
                for (int j = 0; j < 8; j++)
                    acc[i][j] = fmaf(ra[i], rb[j], acc[i][j]);
        }
        __syncthreads();
    }
#pragma unroll
    for (int i = 0; i < 8; i++) {
        int n = b * LL + l0 + tr + i;
        float zs = g_z[n * HH + h] * (float)LL;
        __half* hp = g_msg_f + (size_t)n * DD + h * DH + tc;
#pragma unroll
        for (int j = 0; j < 8; j += 2) {
            __half2 hh;
            hh.x = __float2half(acc[i][j] * zs);
            hh.y = __float2half(acc[i][j + 1] * zs);
            *(__half2*)(hp + j) = hh;
        }
    }
}

// ---------------------------------------------------------------------------
// LayerNorm + residual
// ---------------------------------------------------------------------------
__device__ __forceinline__ float warpReduceSum(float v) {
#pragma unroll
    for (int o = 16; o > 0; o >>= 1) v += __shfl_xor_sync(0xffffffffu, v, o);
    return v;
}

__global__ void __launch_bounds__(256) ln_k(const float* __restrict__ t,
                                            const float* __restrict__ base,
                                            const float* __restrict__ gam,
                                            const float* __restrict__ bet,
                                            float* __restrict__ out) {
    const int n = blockIdx.x;
    __shared__ float row[DD];
    __shared__ float rs[8], rs2[8];
    __shared__ float smu, srstd;
    const float* tp = t + (size_t)n * DD;
    float s = 0.f, s2 = 0.f;
    for (int d = threadIdx.x; d < DD; d += 256) {
        float v = tp[d];
        row[d] = v;
        s += v;
        s2 = fmaf(v, v, s2);
    }
    s = warpReduceSum(s);
    s2 = warpReduceSum(s2);
    int lane = threadIdx.x & 31, wid = threadIdx.x >> 5;
    if (lane == 0) { rs[wid] = s; rs2[wid] = s2; }
    __syncthreads();
    if (threadIdx.x < 32) {
        float a = (threadIdx.x < 8) ? rs[threadIdx.x] : 0.f;
        float b2 = (threadIdx.x < 8) ? rs2[threadIdx.x] : 0.f;
        a = warpReduceSum(a);
        b2 = warpReduceSum(b2);
        if (threadIdx.x == 0) {
            float mu = a * (1.0f / DD);
            float var = b2 * (1.0f / DD) - mu * mu;
            smu = mu;
            srstd = rsqrtf(var + LN_EPS);
        }
    }
    __syncthreads();
    float mu = smu, rstd = srstd;
    const float* bp = base + (size_t)n * DD;
    float* op = out + (size_t)n * DD;
    for (int d = threadIdx.x; d < DD; d += 256)
        op[d] = bp[d] + (row[d] - mu) * rstd * gam[d] + bet[d];
}

// ---------------------------------------------------------------------------
extern "C" void kernel_launch(void* const* d_in, const int* in_sizes, int n_in,
                              void* d_out, int out_size) {
    (void)in_sizes; (void)n_in; (void)out_size;
    const float* x  = (const float*)d_in[0];
    const float* Wq = (const float*)d_in[1];
    const float* Wm = (const float*)d_in[2];
    const float* W1 = (const float*)d_in[3];
    const float* W2 = (const float*)d_in[4];
    const float* g1 = (const float*)d_in[5];
    const float* b1 = (const float*)d_in[6];
    const float* g2 = (const float*)d_in[7];
    const float* b2 = (const float*)d_in[8];
    float* out = (float*)d_out;

    float *q, *tmp;
    __half *x_h, *x_l, *msg_f, *tmp_f, *h1_f;
    __half *wq_h, *wq_l, *wm_h, *w1_h, *w2_h;
    cudaGetSymbolAddress((void**)&q,     g_q);
    cudaGetSymbolAddress((void**)&tmp,   g_tmp);
    cudaGetSymbolAddress((void**)&x_h,   g_x_h);
    cudaGetSymbolAddress((void**)&x_l,   g_x_l);
    cudaGetSymbolAddress((void**)&msg_f, g_msg_f);
    cudaGetSymbolAddress((void**)&tmp_f, g_tmp_f);
    cudaGetSymbolAddress((void**)&h1_f,  g_h1_f);
    cudaGetSymbolAddress((void**)&wq_h,  g_wq_h);
    cudaGetSymbolAddress((void**)&wq_l,  g_wq_l);
    cudaGetSymbolAddress((void**)&wm_h,  g_wm_h);
    cudaGetSymbolAddress((void**)&w1_h,  g_w1_h);
    cudaGetSymbolAddress((void**)&w2_h,  g_w2_h);

    const int SM3 = 2 * 4 * GTILE;   // 3-pass: 81920 B
    const int SM1 = 2 * 2 * GTILE;   // 1-pass: 40960 B
    cudaFuncSetAttribute(hgemm_k<0, 3>, cudaFuncAttributeMaxDynamicSharedMemorySize, SM3);
    cudaFuncSetAttribute(hgemm_k<0, 1>, cudaFuncAttributeMaxDynamicSharedMemorySize, SM1);
    cudaFuncSetAttribute(hgemm_k<1, 1>, cudaFuncAttributeMaxDynamicSharedMemorySize, SM1);
    cudaFuncSetAttribute(hgemm_k<2, 1>, cudaFuncAttributeMaxDynamicSharedMemorySize, SM1);

    // 0. Convert inputs
    splitx_k<<<(NROW * DD + 255) / 256, 256>>>(x, x_h, x_l, NROW * DD);
    wtrans_k<<<dim3(DD / 32, DD / 32), dim3(32, 8)>>>(Wq, wq_h, wq_l, DD, DD);
    wtrans_k<<<dim3(DFF / 32, DD / 32), dim3(32, 8)>>>(W1, w1_h, nullptr, DD, DFF);
    wtrans_k<<<dim3(DD / 32, DD / 32), dim3(32, 8)>>>(Wm, wm_h, nullptr, DD, DD);
    wtrans_k<<<dim3(DD / 32, DFF / 32), dim3(32, 8)>>>(W2, w2_h, nullptr, DFF, DD);

    // 1. q = x @ Wq (3-pass hi/lo both sides — attention amplifies q error)
    hgemm_k<0, 3><<<dim3(DD / 128, NROW / 128), 128, SM3>>>(
        x_h, x_l, wq_h, wq_l, q, nullptr, DD, DD);
    // 2. attention reductions (fp32)
    kv_part_k<<<dim3(NCH, BB * HH), 256>>>();
    kv_reduce_k<<<BB * HH * DH * DH / 256, 256>>>();
    ksum_part_k<<<dim3(KSC, BB * HH), 128>>>();
    ksum_reduce_k<<<BB * HH * DH / 256, 256>>>();
    z_k<<<NROW * HH / 8, 256>>>();
    // 3. msg (f16 out)
    msg_k<<<dim3(LL / 128, BB * HH), 256>>>();
    // 4. tmp = msg @ Wm (1-pass; fp32 + f16)  -- this is the rebinded "msg"
    hgemm_k<1, 1><<<dim3(DD / 128, NROW / 128), 128, SM1>>>(
        msg_f, nullptr, wm_h, nullptr, tmp, tmp_f, DD, DD);
    // 5. out = x + LN(tmp)
    ln_k<<<NROW, 256>>>(tmp, x, g1, b1, out);
    // 6. h1 = relu(tmp @ W1) (1-pass; f16 only)
    hgemm_k<2, 1><<<dim3(DFF / 128, NROW / 128), 128, SM1>>>(
        tmp_f, nullptr, w1_h, nullptr, nullptr, h1_f, DFF, DD);
    // 7. tmp = h1 @ W2 (1-pass; fp32)
    hgemm_k<0, 1><<<dim3(DD / 128, NROW / 128), 128, SM1>>>(
        h1_f, nullptr, w2_h, nullptr, tmp, nullptr, DD, DFF);
    // 8. out += LN(tmp)
    ln_k<<<NROW, 256>>>(tmp, out, g2, b2, out);
}

// round 10
// speedup vs baseline: 1.7480x; 1.0198x over previous
#include <cuda_runtime.h>
#include <cuda_fp16.h>
#include <math.h>
#include <stdint.h>

// Problem constants
#define BB   2
#define LL   8192
#define DD   1024
#define HH   8
#define DH   128
#define NROW (BB*LL)     // 16384
#define DFF  (2*DD)      // 2048
#define LC   128
#define NCH  (LL/LC)     // 64
#define KSC  128         // ksum chunk count
#define KSL  (LL/KSC)    // 64 rows per ksum chunk
#define ATTN_EPS 1e-6f
#define LN_EPS   1e-5f

// ---------------------------------------------------------------------------
// Scratch (device globals: allocation-free per harness rules)
// ---------------------------------------------------------------------------
__device__ float g_q[NROW*DD];                  // x @ Wq (fp32, attention input)
__device__ float g_tmp[NROW*DD];                // msg@Wm fp32 (LN1 input), then mlp out
__device__ float g_kvp[BB*HH*NCH*DH*DH];        // KV partials per L-chunk
__device__ float g_kv[BB*HH*DH*DH];             // KV
__device__ float g_ksp[BB*HH*KSC*DH];           // Ksum partials
__device__ float g_ks[BB*HH*DH];                // Ksum
__device__ float g_z[NROW*HH];                  // 1/(Q.Ksum + eps)

// fp16 operands. Activations single f16.
__device__ __half g_x_h[NROW*DD];
__device__ __half g_msg_f[NROW*DD];
__device__ __half g_tmp_f[NROW*DD];
__device__ __half g_h1_f[NROW*DFF];
// transposed weights [N, K] K-major, fp16. Only Wq needs the lo part.
__device__ __half g_wq_h[DD*DD],  g_wq_l[DD*DD];
__device__ __half g_wm_h[DD*DD];
__device__ __half g_w1_h[DFF*DD];
__device__ __half g_w2_h[DD*DFF];

// ---------------------------------------------------------------------------
// Helpers
// ---------------------------------------------------------------------------
__device__ __forceinline__ uint32_t smem_u32(const void* p) {
    uint32_t a;
    asm("{ .reg .u64 t; cvta.to.shared.u64 t, %1; cvt.u32.u64 %0, t; }" : "=r"(a) : "l"(p));
    return a;
}

__device__ __forceinline__ void splith(float v, __half& h, __half& l) {
    h = __float2half(v);
    l = __float2half(v - __half2float(h));
}

__device__ __forceinline__ float featf(float v) {
    return v > 0.f ? v + 1.f : expf(v);
}

#define LDSM4(r0, r1, r2, r3, addr) \
    asm volatile("ldmatrix.sync.aligned.m8n8.x4.shared.b16 {%0,%1,%2,%3}, [%4];" \
                 : "=r"(r0), "=r"(r1), "=r"(r2), "=r"(r3) : "r"(addr))

#define CP16(dst, src) \
    asm volatile("cp.async.cg.shared.global [%0], [%1], 16;" :: "r"(dst), "l"(src))
#define CP_COMMIT() asm volatile("cp.async.commit_group;" ::: "memory")
#define CP_WAIT1()  asm volatile("cp.async.wait_group 1;" ::: "memory")
#define CP_WAIT0()  asm volatile("cp.async.wait_group 0;" ::: "memory")

__device__ __forceinline__ void mma16816(float* c, const uint32_t* a,
                                         uint32_t b0, uint32_t b1) {
    asm volatile("mma.sync.aligned.m16n8k16.row.col.f32.f16.f16.f32 "
                 "{%0,%1,%2,%3}, {%4,%5,%6,%7}, {%8,%9}, {%0,%1,%2,%3};"
                 : "+f"(c[0]), "+f"(c[1]), "+f"(c[2]), "+f"(c[3])
                 : "r"(a[0]), "r"(a[1]), "r"(a[2]), "r"(a[3]), "r"(b0), "r"(b1));
}

// ---------------------------------------------------------------------------
// HMMA GEMM, B stored [N,K] K-major, fp16 in / fp32 accumulate.
// PASSES=1: C = A @ Bh^T
// PASSES=2: C = A @ (Bh+Bl)^T           (a*bh + a*bl)
// PASSES=3: C = (Ah+Al) @ (Bh+Bl)^T     (ah*bh + al*bh + ah*bl)
// Block tile 128x128, K-chunk 32, 4 warps (2x2), warp tile 64x64, cp.async 2-stage.
// EPI: 0 = fp32 C; 1 = fp32 C + f16 Cf; 2 = relu then f16 Cf only.
// ---------------------------------------------------------------------------
#define SROW  80
#define GTILE (128 * SROW)      // one array (128 rows x 32 f16, padded)

template <int EPI, int PASSES>
__global__ void __launch_bounds__(128, 2)
hgemm_k(const __half* __restrict__ Ah, const __half* __restrict__ Al,
        const __half* __restrict__ Bh, const __half* __restrict__ Bl,
        float* __restrict__ C, __half* __restrict__ Cf, int Nn, int K) {
    constexpr int NSLOT = (PASSES == 1) ? 2 : (PASSES == 2 ? 3 : 4);  // Ah,Bh[,Bl[,Al]]
    constexpr int GSTG = NSLOT * GTILE;
    extern __shared__ __align__(16) char smem[];
    const uint32_t sb = smem_u32(smem);
    const int tid = threadIdx.x, warp = tid >> 5, lane = tid & 31;
    const int wm = warp >> 1, wn = warp & 1;           // 2 x 2 warp grid
    const int m0 = blockIdx.y * 128, n0 = blockIdx.x * 128;

    float acc[4][8][4] = {};   // [mtile][ntile][reg]

    const uint32_t aoff = (uint32_t)(wm * 64 + (lane & 15)) * SROW + ((lane >> 4) << 4);
    const int nloc = (lane & 7) + ((lane >> 4) << 3);
    const uint32_t boff = (uint32_t)(wn * 64 + nloc) * SROW + (((lane >> 3) & 1) << 4);

    const int lrow = tid >> 2, lseg = tid & 3;

    auto load_stage = [&](int s, int kc) {
        const uint32_t base = sb + (uint32_t)s * GSTG;
#pragma unroll
        for (int i = 0; i < 4; i++) {
            const int r = lrow + i * 32;
            const uint32_t so = (uint32_t)r * SROW + lseg * 16;
            const size_t ga = (size_t)(m0 + r) * K + kc + lseg * 8;
            const size_t gb = (size_t)(n0 + r) * K + kc + lseg * 8;
            CP16(base + 0 * GTILE + so, Ah + ga);
            CP16(base + 1 * GTILE + so, Bh + gb);
            if (PASSES >= 2) CP16(base + 2 * GTILE + so, Bl + gb);
            if (PASSES == 3) CP16(base + 3 * GTILE + so, Al + ga);
        }
    };

    const int nch = K / 32;
    load_stage(0, 0);
    CP_COMMIT();

    for (int c = 0; c < nch; c++) {
        if (c + 1 < nch) {
            load_stage((c + 1) & 1, (c + 1) * 32);
            CP_COMMIT();
            CP_WAIT1();
        } else {
            CP_WAIT0();
        }
        __syncthreads();
        const uint32_t base = sb + (uint32_t)(c & 1) * GSTG;
#pragma unroll
        for (int ks = 0; ks < 2; ks++) {
            const uint32_t kso = (uint32_t)ks * 32;    // 16 f16 = 32 bytes
            uint32_t ah[4][4], bh[4][4];
#pragma unroll
            for (int mt = 0; mt < 4; mt++)
                LDSM4(ah[mt][0], ah[mt][1], ah[mt][2], ah[mt][3],
                      base + 0 * GTILE + aoff + (uint32_t)mt * 16 * SROW + kso);
#pragma unroll
            for (int p = 0; p < 4; p++)
                LDSM4(bh[p][0], bh[p][1], bh[p][2], bh[p][3],
                      base + 1 * GTILE + boff + (uint32_t)p * 16 * SROW + kso);
            // pass 1: ah * bh
#pragma unroll
            for (int mt = 0; mt < 4; mt++)
#pragma unroll
                for (int p = 0; p < 4; p++) {
                    mma16816(acc[mt][p * 2 + 0], ah[mt], bh[p][0], bh[p][1]);
                    mma16816(acc[mt][p * 2 + 1], ah[mt], bh[p][2], bh[p][3]);
                }
            if (PASSES >= 2) {
                uint32_t bl[4][4];
#pragma unroll
                for (int p = 0; p < 4; p++)
                    LDSM4(bl[p][0], bl[p][1], bl[p][2], bl[p][3],
                          base + 2 * GTILE + boff + (uint32_t)p * 16 * SROW + kso);
                if (PASSES == 3) {
                    uint32_t al[4][4];
#pragma unroll
                    for (int mt = 0; mt < 4; mt++)
                        LDSM4(al[mt][0], al[mt][1], al[mt][2], al[mt][3],
                              base + 3 * GTILE + aoff + (uint32_t)mt * 16 * SROW + kso);
                    // pass: al * bh
#pragma unroll
                    for (int mt = 0; mt < 4; mt++)
#pragma unroll
                        for (int p = 0; p < 4; p++) {
                            mma16816(acc[mt][p * 2 + 0], al[mt], bh[p][0], bh[p][1]);
                            mma16816(acc[mt][p * 2 + 1], al[mt], bh[p][2], bh[p][3]);
                        }
                }
                // pass: ah * bl
#pragma unroll
                for (int mt = 0; mt < 4; mt++)
#pragma unroll
                    for (int p = 0; p < 4; p++) {
                        mma16816(acc[mt][p * 2 + 0], ah[mt], bl[p][0], bl[p][1]);
                        mma16816(acc[mt][p * 2 + 1], ah[mt], bl[p][2], bl[p][3]);
                    }
            }
        }
        __syncthreads();
    }

    // Epilogue: m16n8 acc mapping: c0,c1=(gid, t4*2,+1); c2,c3=(gid+8, ...)
    const int gid = lane >> 2, t4 = lane & 3;
#pragma unroll
    for (int mt = 0; mt < 4; mt++) {
#pragma unroll
        for (int nt = 0; nt < 8; nt++) {
            const float* c = acc[mt][nt];
            const int r0 = m0 + wm * 64 + mt * 16 + gid;
            const int cc = n0 + wn * 64 + nt * 8 + t4 * 2;
#pragma unroll
            for (int half_ = 0; half_ < 2; half_++) {
                const int r = r0 + half_ * 8;
                float v0 = c[half_ * 2 + 0], v1 = c[half_ * 2 + 1];
                if (EPI <= 1) {
                    float2 f; f.x = v0; f.y = v1;
                    *(float2*)(C + (size_t)r * Nn + cc) = f;
                }
                if (EPI >= 1) {
                    if (EPI == 2) { v0 = fmaxf(v0, 0.f); v1 = fmaxf(v1, 0.f); }
                    __half2 hh;
                    hh.x = __float2half(v0);
                    hh.y = __float2half(v1);
                    *(__half2*)(Cf + (size_t)r * Nn + cc) = hh;
                }
            }
        }
    }
}

// ---------------------------------------------------------------------------
// Conversion kernels
// ---------------------------------------------------------------------------
// x fp32 -> f16
__global__ void cvt_k(const float* __restrict__ in, __half* __restrict__ o, int n) {
    int i = blockIdx.x * 256 + threadIdx.x;
    if (i < n) o[i] = __float2half(in[i]);
}

// W [K,N] fp32 -> Wt hi (and optional lo) [N,K] f16, tiled transpose
__global__ void wtrans_k(const float* __restrict__ W, __half* __restrict__ Thi,
                         __half* __restrict__ Tlo, int K, int N) {
    __shared__ float t[32][33];
    const int k0 = blockIdx.y * 32, n0 = blockIdx.x * 32;
    const int tx = threadIdx.x, ty = threadIdx.y;   // 32 x 8
#pragma unroll
    for (int i = 0; i < 4; i++)
        t[ty + i * 8][tx] = W[(size_t)(k0 + ty + i * 8) * N + n0 + tx];
    __syncthreads();
#pragma unroll
    for (int i = 0; i < 4; i++) {
        float v = t[tx][ty + i * 8];
        __half h, l;
        splith(v, h, l);
        const size_t o = (size_t)(n0 + ty + i * 8) * K + k0 + tx;
        Thi[o] = h;
        if (Tlo) Tlo[o] = l;
    }
}

// ---------------------------------------------------------------------------
// Attention pieces (fp32 SIMT)
// ---------------------------------------------------------------------------
#define BK16 16

__global__ void __launch_bounds__(256) kv_part_k() {
    const int ch = blockIdx.x, bh = blockIdx.y;
    const int b = bh >> 3, h = bh & 7;
    __shared__ __align__(16) float Fs[BK16][DH];
    __shared__ __align__(16) float Vs[BK16][DH];
    const float invL = 1.0f / (float)LL;
    const int tid = threadIdx.x;
    const int rowL = tid >> 5;
    const int colL = (tid & 31) * 4;
    const int tr = (tid >> 4) * 8, tc = (tid & 15) * 8;
    float acc[8][8] = {};

    for (int l0 = ch * LC; l0 < ch * LC + LC; l0 += BK16) {
#pragma unroll
        for (int i = 0; i < 2; i++) {
            int l = l0 + rowL + i * 8;
            const float* p = g_q + (size_t)(b * LL + l) * DD + h * DH + colL;
            float4 v = *(const float4*)p;
            float4 f;
            f.x = featf(v.x); f.y = featf(v.y); f.z = featf(v.z); f.w = featf(v.w);
            *(float4*)&Fs[rowL + i * 8][colL] = f;
            float4 vv; vv.x = v.x * invL; vv.y = v.y * invL; vv.z = v.z * invL; vv.w = v.w * invL;
            *(float4*)&Vs[rowL + i * 8][colL] = vv;
        }
        __syncthreads();
#pragma unroll
        for (int kk = 0; kk < BK16; kk++) {
            float4 a0 = *(const float4*)&Fs[kk][tr];
            float4 a1 = *(const float4*)&Fs[kk][tr + 4];
            float4 b0 = *(const float4*)&Vs[kk][tc];
            float4 b1 = *(const float4*)&Vs[kk][tc + 4];
            float ra[8] = {a0.x, a0.y, a0.z, a0.w, a1.x, a1.y, a1.z, a1.w};
            float rb[8] = {b0.x, b0.y, b0.z, b0.w, b1.x, b1.y, b1.z, b1.w};
#pragma unroll
            for (int i = 0; i < 8; i++)
#pragma unroll
                for (int j = 0; j < 8; j++)
                    acc[i][j] = fmaf(ra[i], rb[j], acc[i][j]);
        }
        __syncthreads();
    }
    float* outp = g_kvp + (size_t)(bh * NCH + ch) * (DH * DH);
#pragma unroll
    for (int i = 0; i < 8; i++)
#pragma unroll
        for (int j = 0; j < 8; j += 4) {
            float4 v;
            v.x = acc[i][j]; v.y = acc[i][j + 1]; v.z = acc[i][j + 2]; v.w = acc[i][j + 3];
            *(float4*)(outp + (tr + i) * DH + tc + j) = v;
        }
}

__global__ void kv_reduce_k() {
    int idx = blockIdx.x * 256 + threadIdx.x;
    int bh = idx >> 14;
    int e = idx & 16383;
    float s = 0.f;
#pragma unroll 8
    for (int c = 0; c < NCH; c++)
        s += g_kvp[(size_t)(bh * NCH + c) * (DH * DH) + e];
    g_kv[idx] = s;
}

__global__ void __launch_bounds__(128) ksum_part_k() {
    const int ch = blockIdx.x, bh = blockIdx.y;
    const int b = bh >> 3, h = bh & 7;
    const int i = threadIdx.x;
    float s = 0.f;
    const float* base = g_q + (size_t)(b * LL + ch * KSL) * DD + h * DH + i;
#pragma unroll 8
    for (int l = 0; l < KSL; l++)
        s += featf(base[(size_t)l * DD]);
    g_ksp[(bh * KSC + ch) * DH + i] = s;
}

__global__ void ksum_reduce_k() {
    int idx = blockIdx.x * 256 + threadIdx.x;
    int bh = idx >> 7;
    int i = idx & 127;
    float s = 0.f;
#pragma unroll
    for (int c = 0; c < KSC; c++)
        s += g_ksp[(bh * KSC + c) * DH + i];
    g_ks[idx] = s;
}

// Z: one warp per (n,h) pair; lanes split the 128-dim dot product.
__global__ void __launch_bounds__(256) z_k() {
    __shared__ float sk[BB * HH * DH];
    for (int i = threadIdx.x; i < BB * HH * DH; i += 256) sk[i] = g_ks[i];
    __syncthreads();
    const int wi = threadIdx.x >> 5, lane = threadIdx.x & 31;
    const int idx = blockIdx.x * 8 + wi;    // (n*H + h)
    const int n = idx >> 3, h = idx & 7;
    const int b = n >> 13;
    const float* qp = g_q + (size_t)n * DD + h * DH + lane * 4;
    const float* kp = sk + (b * HH + h) * DH + lane * 4;
    float4 v = *(const float4*)qp;
    float dot = featf(v.x) * kp[0] + featf(v.y) * kp[1] +
                featf(v.z) * kp[2] + featf(v.w) * kp[3];
#pragma unroll
    for (int o = 16; o > 0; o >>= 1) dot += __shfl_xor_sync(0xffffffffu, dot, o);
    if (lane == 0) g_z[idx] = 1.0f / (dot + ATTN_EPS);
}

// msg -> f16 single (consumed only by the Wm GEMM)
__global__ void __launch_bounds__(256) msg_k() {
    const int bh = blockIdx.y;
    const int b = bh >> 3, h = bh & 7;
    const int l0 = blockIdx.x * 128;
    __shared__ __align__(16) float As[BK16][128];
    __shared__ __align__(16) float Ks[BK16][DH];
    const int tid = threadIdx.x;
    const int rowA = tid >> 2;
    const int colA = (tid & 3) * 4;
    const int rowB = tid >> 5;
    const int colB = (tid & 31) * 4;
    const int tr = (tid >> 4) * 8, tc = (tid & 15) * 8;
    float acc[8][8] = {};
    const float* kvb = g_kv + (size_t)bh * (DH * DH);

    for (int k0 = 0; k0 < DH; k0 += BK16) {
#pragma unroll
        for (int i = 0; i < 2; i++) {
            int l = l0 + rowA + i * 64;
            float4 v = *(const float4*)(g_q + (size_t)(b * LL + l) * DD + h * DH + k0 + colA);
            As[colA + 0][rowA + i * 64] = featf(v.x);
            As[colA + 1][rowA + i * 64] = featf(v.y);
            As[colA + 2][rowA + i * 64] = featf(v.z);
            As[colA + 3][rowA + i * 64] = featf(v.w);
        }
#pragma unroll
        for (int i = 0; i < 2; i++) {
            float4 v = *(const float4*)(kvb + (size_t)(k0 + rowB + i * 8) * DH + colB);
            *(float4*)(&Ks[rowB + i * 8][colB]) = v;
        }
        __syncthreads();
#pragma unroll
        for (int kk = 0; kk < BK16; kk++) {
            float4 a0 = *(const float4*)&As[kk][tr];
            float4 a1 = *(const float4*)&As[kk][tr + 4];
            float4 b0 = *(const float4*)&Ks[kk][tc];
            float4 b1 = *(const float4*)&Ks[kk][tc + 4];
            float ra[8] = {a0.x, a0.y, a0.z, a0.w, a1.x, a1.y, a1.z, a1.w};
            float rb[8] = {b0.x, b0.y, b0.z, b0.w, b1.x, b1.y, b1.z, b1.w};
#pragma unroll
            for (int i = 0; i < 8; i++)
#pragma unroll
                for (int j = 0; j < 8; j++)
                    acc[i][j] = fmaf(ra[i], rb[j], acc[i][j]);
        }
        __syncthreads();
    }
#pragma unroll
    for (int i = 0; i < 8; i++) {
        int n = b * LL + l0 + tr + i;
        float zs = g_z[n * HH + h] * (float)LL;
        __half* hp = g_msg_f + (size_t)n * DD + h * DH + tc;
#pragma unroll
        for (int j = 0; j < 8; j += 2) {
            __half2 hh;
            hh.x = __float2half(acc[i][j] * zs);
            hh.y = __float2half(acc[i][j + 1] * zs);
            *(__half2*)(hp + j) = hh;
        }
    }
}

// ---------------------------------------------------------------------------
// LayerNorm + residual
// ---------------------------------------------------------------------------
__device__ __forceinline__ float warpReduceSum(float v) {
#pragma unroll
    for (int o = 16; o > 0; o >>= 1) v += __shfl_xor_sync(0xffffffffu, v, o);
    return v;
}

__global__ void __launch_bounds__(256) ln_k(const float* __restrict__ t,
                                            const float* __restrict__ base,
                                            const float* __restrict__ gam,
                                            const float* __restrict__ bet,
                                            float* __restrict__ out) {
    const int n = blockIdx.x;
    __shared__ float row[DD];
    __shared__ float rs[8], rs2[8];
    __shared__ float smu, srstd;
    const float* tp = t + (size_t)n * DD;
    float s = 0.f, s2 = 0.f;
    for (int d = threadIdx.x; d < DD; d += 256) {
        float v = tp[d];
        row[d] = v;
        s += v;
        s2 = fmaf(v, v, s2);
    }
    s = warpReduceSum(s);
    s2 = warpReduceSum(s2);
    int lane = threadIdx.x & 31, wid = threadIdx.x >> 5;
    if (lane == 0) { rs[wid] = s; rs2[wid] = s2; }
    __syncthreads();
    if (threadIdx.x < 32) {
        float a = (threadIdx.x < 8) ? rs[threadIdx.x] : 0.f;
        float b2 = (threadIdx.x < 8) ? rs2[threadIdx.x] : 0.f;
        a = warpReduceSum(a);
        b2 = warpReduceSum(b2);
        if (threadIdx.x == 0) {
            float mu = a * (1.0f / DD);
            float var = b2 * (1.0f / DD) - mu * mu;
            smu = mu;
            srstd = rsqrtf(var + LN_EPS);
        }
    }
    __syncthreads();
    float mu = smu, rstd = srstd;
    const float* bp = base + (size_t)n * DD;
    float* op = out + (size_t)n * DD;
    for (int d = threadIdx.x; d < DD; d += 256)
        op[d] = bp[d] + (row[d] - mu) * rstd * gam[d] + bet[d];
}

// ---------------------------------------------------------------------------
extern "C" void kernel_launch(void* const* d_in, const int* in_sizes, int n_in,
                              void* d_out, int out_size) {
    (void)in_sizes; (void)n_in; (void)out_size;
    const float* x  = (const float*)d_in[0];
    const float* Wq = (const float*)d_in[1];
    const float* Wm = (const float*)d_in[2];
    const float* W1 = (const float*)d_in[3];
    const float* W2 = (const float*)d_in[4];
    const float* g1 = (const float*)d_in[5];
    const float* b1 = (const float*)d_in[6];
    const float* g2 = (const float*)d_in[7];
    const float* b2 = (const float*)d_in[8];
    float* out = (float*)d_out;

    float *q, *tmp;
    __half *x_h, *msg_f, *tmp_f, *h1_f;
    __half *wq_h, *wq_l, *wm_h, *w1_h, *w2_h;
    cudaGetSymbolAddress((void**)&q,     g_q);
    cudaGetSymbolAddress((void**)&tmp,   g_tmp);
    cudaGetSymbolAddress((void**)&x_h,   g_x_h);
    cudaGetSymbolAddress((void**)&msg_f, g_msg_f);
    cudaGetSymbolAddress((void**)&tmp_f, g_tmp_f);
    cudaGetSymbolAddress((void**)&h1_f,  g_h1_f);
    cudaGetSymbolAddress((void**)&wq_h,  g_wq_h);
    cudaGetSymbolAddress((void**)&wq_l,  g_wq_l);
    cudaGetSymbolAddress((void**)&wm_h,  g_wm_h);
    cudaGetSymbolAddress((void**)&w1_h,  g_w1_h);
    cudaGetSymbolAddress((void**)&w2_h,  g_w2_h);

    const int SM2 = 2 * 3 * GTILE;   // 2-pass: 61440 B
    const int SM1 = 2 * 2 * GTILE;   // 1-pass: 40960 B
    cudaFuncSetAttribute(hgemm_k<0, 2>, cudaFuncAttributeMaxDynamicSharedMemorySize, SM2);
    cudaFuncSetAttribute(hgemm_k<0, 1>, cudaFuncAttributeMaxDynamicSharedMemorySize, SM1);
    cudaFuncSetAttribute(hgemm_k<1, 1>, cudaFuncAttributeMaxDynamicSharedMemorySize, SM1);
    cudaFuncSetAttribute(hgemm_k<2, 1>, cudaFuncAttributeMaxDynamicSharedMemorySize, SM1);

    // 0. Convert inputs
    cvt_k<<<(NROW * DD + 255) / 256, 256>>>(x, x_h, NROW * DD);
    wtrans_k<<<dim3(DD / 32, DD / 32), dim3(32, 8)>>>(Wq, wq_h, wq_l, DD, DD);
    wtrans_k<<<dim3(DFF / 32, DD / 32), dim3(32, 8)>>>(W1, w1_h, nullptr, DD, DFF);
    wtrans_k<<<dim3(DD / 32, DD / 32), dim3(32, 8)>>>(Wm, wm_h, nullptr, DD, DD);
    wtrans_k<<<dim3(DD / 32, DFF / 32), dim3(32, 8)>>>(W2, w2_h, nullptr, DFF, DD);

    // 1. q = x @ Wq (2-pass: weights hi/lo, x single f16)
    hgemm_k<0, 2><<<dim3(DD / 128, NROW / 128), 128, SM2>>>(
        x_h, nullptr, wq_h, wq_l, q, nullptr, DD, DD);
    // 2. attention reductions (fp32)
    kv_part_k<<<dim3(NCH, BB * HH), 256>>>();
    kv_reduce_k<<<BB * HH * DH * DH / 256, 256>>>();
    ksum_part_k<<<dim3(KSC, BB * HH), 128>>>();
    ksum_reduce_k<<<BB * HH * DH / 256, 256>>>();
    z_k<<<NROW * HH / 8, 256>>>();
    // 3. msg (f16 out)
    msg_k<<<dim3(LL / 128, BB * HH), 256>>>();
    // 4. tmp = msg @ Wm (1-pass; fp32 + f16)  -- this is the rebinded "msg"
    hgemm_k<1, 1><<<dim3(DD / 128, NROW / 128), 128, SM1>>>(
        msg_f, nullptr, wm_h, nullptr, tmp, tmp_f, DD, DD);
    // 5. out = x + LN(tmp)
    ln_k<<<NROW, 256>>>(tmp, x, g1, b1, out);
    // 6. h1 = relu(tmp @ W1) (1-pass; f16 only)
    hgemm_k<2, 1><<<dim3(DFF / 128, NROW / 128), 128, SM1>>>(
        tmp_f, nullptr, w1_h, nullptr, nullptr, h1_f, DFF, DD);
    // 7. tmp = h1 @ W2 (1-pass; fp32)
    hgemm_k<0, 1><<<dim3(DD / 128, NROW / 128), 128, SM1>>>(
        h1_f, nullptr, w2_h, nullptr, tmp, nullptr, DD, DFF);
    // 8. out += LN(tmp)
    ln_k<<<NROW, 256>>>(tmp, out, g2, b2, out);
}

// round 12
// speedup vs baseline: 2.1208x; 1.2133x over previous
#include <cuda_runtime.h>
#include <cuda_fp16.h>
#include <math.h>
#include <stdint.h>

// Problem constants
#define BB   2
#define LL   8192
#define DD   1024
#define HH   8
#define DH   128
#define NROW (BB*LL)     // 16384
#define DFF  (2*DD)      // 2048
#define NKCH 16          // kv chunk count
#define KCHL (LL/NKCH)   // 512 l-rows per kv chunk
#define KSC  128         // ksum chunk count
#define KSL  (LL/KSC)    // 64 rows per ksum chunk
#define ATTN_EPS 1e-6f
#define LN_EPS   1e-5f

// ---------------------------------------------------------------------------
// Scratch (device globals: allocation-free per harness rules)
// ---------------------------------------------------------------------------
__device__ float g_tmp[NROW*DD];                // msg@Wm fp32 (LN1 input), then mlp out
__device__ float g_kvp[BB*HH*NKCH*DH*DH];       // KV partials per L-chunk (fp32)
__device__ float g_ksp[BB*HH*KSC*DH];           // Ksum partials
__device__ float g_ks[BB*HH*DH];                // Ksum
__device__ float g_z[NROW*HH];                  // 1/(Q.Ksum + eps)

// f16 operands
__device__ __half g_x_h[NROW*DD];
__device__ __half g_feat_f[NROW*DD];            // feat(q) = elu(q)+1, f16
__device__ __half g_v_f[NROW*DD];               // q (value, unscaled), f16
__device__ __half g_kvt[BB*HH*DH*DH];           // KV^T [bh][v][d] f16
__device__ __half g_msg_f[NROW*DD];
__device__ __half g_tmp_f[NROW*DD];
__device__ __half g_h1_f[NROW*DFF];
// transposed weights [N, K] K-major, fp16. Only Wq needs the lo part.
__device__ __half g_wq_h[DD*DD],  g_wq_l[DD*DD];
__device__ __half g_wm_h[DD*DD];
__device__ __half g_w1_h[DFF*DD];
__device__ __half g_w2_h[DD*DFF];

// ---------------------------------------------------------------------------
// Helpers
// ---------------------------------------------------------------------------
__device__ __forceinline__ uint32_t smem_u32(const void* p) {
    uint32_t a;
    asm("{ .reg .u64 t; cvta.to.shared.u64 t, %1; cvt.u32.u64 %0, t; }" : "=r"(a) : "l"(p));
    return a;
}

__device__ __forceinline__ void splith(float v, __half& h, __half& l) {
    h = __float2half(v);
    l = __float2half(v - __half2float(h));
}

__device__ __forceinline__ float featf(float v) {
    return v > 0.f ? v + 1.f : expf(v);
}

#define LDSM4(r0, r1, r2, r3, addr) \
    asm volatile("ldmatrix.sync.aligned.m8n8.x4.shared.b16 {%0,%1,%2,%3}, [%4];" \
                 : "=r"(r0), "=r"(r1), "=r"(r2), "=r"(r3) : "r"(addr))
#define LDSM4T(r0, r1, r2, r3, addr) \
    asm volatile("ldmatrix.sync.aligned.m8n8.x4.trans.shared.b16 {%0,%1,%2,%3}, [%4];" \
                 : "=r"(r0), "=r"(r1), "=r"(r2), "=r"(r3) : "r"(addr))

#define CP16(dst, src) \
    asm volatile("cp.async.cg.shared.global [%0], [%1], 16;" :: "r"(dst), "l"(src))
#define CP_COMMIT() asm volatile("cp.async.commit_group;" ::: "memory")
#define CP_WAIT1()  asm volatile("cp.async.wait_group 1;" ::: "memory")
#define CP_WAIT0()  asm volatile("cp.async.wait_group 0;" ::: "memory")

__device__ __forceinline__ void mma16816(float* c, const uint32_t* a,
                                         uint32_t b0, uint32_t b1) {
    asm volatile("mma.sync.aligned.m16n8k16.row.col.f32.f16.f16.f32 "
                 "{%0,%1,%2,%3}, {%4,%5,%6,%7}, {%8,%9}, {%0,%1,%2,%3};"
                 : "+f"(c[0]), "+f"(c[1]), "+f"(c[2]), "+f"(c[3])
                 : "r"(a[0]), "r"(a[1]), "r"(a[2]), "r"(a[3]), "r"(b0), "r"(b1));
}

// ---------------------------------------------------------------------------
// HMMA GEMM, B stored [N,K] K-major, fp16 in / fp32 accumulate.
// PASSES=1: C = A @ Bh^T
// PASSES=2: C = A @ (Bh+Bl)^T
// Block tile 128x128, K-chunk 32, 4 warps (2x2), warp tile 64x64, cp.async 2-stage.
// EPI: 0 = fp32 C; 1 = fp32 C + f16 Cf; 2 = relu then f16 Cf only;
//      3 = f16 feat(C) -> Cf and f16 C -> Cf2 (Wq epilogue).
// ---------------------------------------------------------------------------
#define SROW  80
#define GTILE (128 * SROW)

template <int EPI, int PASSES>
__global__ void __launch_bounds__(128, 2)
hgemm_k(const __half* __restrict__ Ah,
        const __half* __restrict__ Bh, const __half* __restrict__ Bl,
        float* __restrict__ C, __half* __restrict__ Cf, __half* __restrict__ Cf2,
        int Nn, int K) {
    constexpr int NSLOT = (PASSES == 1) ? 2 : 3;  // Ah,Bh[,Bl]
    constexpr int GSTG = NSLOT * GTILE;
    extern __shared__ __align__(16) char smem[];
    const uint32_t sb = smem_u32(smem);
    const int tid = threadIdx.x, warp = tid >> 5, lane = tid & 31;
    const int wm = warp >> 1, wn = warp & 1;
    const int m0 = blockIdx.y * 128, n0 = blockIdx.x * 128;

    float acc[4][8][4] = {};

    const uint32_t aoff = (uint32_t)(wm * 64 + (lane & 15)) * SROW + ((lane >> 4) << 4);
    const int nloc = (lane & 7) + ((lane >> 4) << 3);
    const uint32_t boff = (uint32_t)(wn * 64 + nloc) * SROW + (((lane >> 3) & 1) << 4);

    const int lrow = tid >> 2, lseg = tid & 3;

    auto load_stage = [&](int s, int kc) {
        const uint32_t base = sb + (uint32_t)s * GSTG;
#pragma unroll
        for (int i = 0; i < 4; i++) {
            const int r = lrow + i * 32;
            const uint32_t so = (uint32_t)r * SROW + lseg * 16;
            const size_t ga = (size_t)(m0 + r) * K + kc + lseg * 8;
            const size_t gb = (size_t)(n0 + r) * K + kc + lseg * 8;
            CP16(base + 0 * GTILE + so, Ah + ga);
            CP16(base + 1 * GTILE + so, Bh + gb);
            if (PASSES == 2) CP16(base + 2 * GTILE + so, Bl + gb);
        }
    };

    const int nch = K / 32;
    load_stage(0, 0);
    CP_COMMIT();

    for (int c = 0; c < nch; c++) {
        if (c + 1 < nch) {
            load_stage((c + 1) & 1, (c + 1) * 32);
            CP_COMMIT();
            CP_WAIT1();
        } else {
            CP_WAIT0();
        }
        __syncthreads();
        const uint32_t base = sb + (uint32_t)(c & 1) * GSTG;
#pragma unroll
        for (int ks = 0; ks < 2; ks++) {
            const uint32_t kso = (uint32_t)ks * 32;
            uint32_t ah[4][4], bh[4][4];
#pragma unroll
            for (int mt = 0; mt < 4; mt++)
                LDSM4(ah[mt][0], ah[mt][1], ah[mt][2], ah[mt][3],
                      base + 0 * GTILE + aoff + (uint32_t)mt * 16 * SROW + kso);
#pragma unroll
            for (int p = 0; p < 4; p++)
                LDSM4(bh[p][0], bh[p][1], bh[p][2], bh[p][3],
                      base + 1 * GTILE + boff + (uint32_t)p * 16 * SROW + kso);
#pragma unroll
            for (int mt = 0; mt < 4; mt++)
#pragma unroll
                for (int p = 0; p < 4; p++) {
                    mma16816(acc[mt][p * 2 + 0], ah[mt], bh[p][0], bh[p][1]);
                    mma16816(acc[mt][p * 2 + 1], ah[mt], bh[p][2], bh[p][3]);
                }
            if (PASSES == 2) {
                uint32_t bl[4][4];
#pragma unroll
                for (int p = 0; p < 4; p++)
                    LDSM4(bl[p][0], bl[p][1], bl[p][2], bl[p][3],
                          base + 2 * GTILE + boff + (uint32_t)p * 16 * SROW + kso);
#pragma unroll
                for (int mt = 0; mt < 4; mt++)
#pragma unroll
                    for (int p = 0; p < 4; p++) {
                        mma16816(acc[mt][p * 2 + 0], ah[mt], bl[p][0], bl[p][1]);
                        mma16816(acc[mt][p * 2 + 1], ah[mt], bl[p][2], bl[p][3]);
                    }
            }
        }
        __syncthreads();
    }

    const int gid = lane >> 2, t4 = lane & 3;
#pragma unroll
    for (int mt = 0; mt < 4; mt++) {
#pragma unroll
        for (int nt = 0; nt < 8; nt++) {
            const float* c = acc[mt][nt];
            const int r0 = m0 + wm * 64 + mt * 16 + gid;
            const int cc = n0 + wn * 64 + nt * 8 + t4 * 2;
#pragma unroll
            for (int half_ = 0; half_ < 2; half_++) {
                const int r = r0 + half_ * 8;
                float v0 = c[half_ * 2 + 0], v1 = c[half_ * 2 + 1];
                if (EPI <= 1) {
                    float2 f; f.x = v0; f.y = v1;
                    *(float2*)(C + (size_t)r * Nn + cc) = f;
                }
                if (EPI == 1 || EPI == 2) {
                    if (EPI == 2) { v0 = fmaxf(v0, 0.f); v1 = fmaxf(v1, 0.f); }
                    __half2 hh;
                    hh.x = __float2half(v0);
                    hh.y = __float2half(v1);
                    *(__half2*)(Cf + (size_t)r * Nn + cc) = hh;
                }
                if (EPI == 3) {
                    __half2 fh, vh;
                    fh.x = __float2half(featf(v0));
                    fh.y = __float2half(featf(v1));
                    vh.x = __float2half(v0);
                    vh.y = __float2half(v1);
                    *(__half2*)(Cf  + (size_t)r * Nn + cc) = fh;
                    *(__half2*)(Cf2 + (size_t)r * Nn + cc) = vh;
                }
            }
        }
    }
}

// ---------------------------------------------------------------------------
// KV MMA: per (chunk, bh): KVp[d,v] = sum_{l in chunk} F[l,d] * V[l,v]
// A = F^T, B = V, both via ldmatrix.trans from [l, .]-major smem tiles.
// Block 128 thr (2x2 warps, 64x64 warp tiles), K-chunk 32 l, cp.async 2-stage.
// ---------------------------------------------------------------------------
#define TROW 272                 // 128 f16 + 8 pad = 272 bytes/row
#define TTILE (32 * TROW)        // 8704 B

__global__ void __launch_bounds__(128, 2) kv_mma_k() {
    __shared__ __align__(16) char smem[4 * TTILE];   // 2 stages x (F, V)
    const uint32_t sb = smem_u32(smem);
    const int ch = blockIdx.x, bh = blockIdx.y;
    const int b = bh >> 3, h = bh & 7;
    const int tid = threadIdx.x, warp = tid >> 5, lane = tid & 31;
    const int wm = warp >> 1, wn = warp & 1;
    float acc[4][8][4] = {};

    // trans-ldmatrix per-lane offsets (rows = l within tile)
    const uint32_t aoff = (uint32_t)((lane >> 4) * 8 + (lane & 7)) * TROW
                        + (uint32_t)(wm * 64 + ((lane >> 3) & 1) * 8) * 2;
    const uint32_t boff = (uint32_t)(((lane >> 3) & 1) * 8 + (lane & 7)) * TROW
                        + (uint32_t)(wn * 64 + (lane >> 4) * 8) * 2;

    auto load_stage = [&](int st, int l0) {
        const uint32_t base = sb + (uint32_t)st * 2 * TTILE;
#pragma unroll
        for (int i = 0; i < 4; i++) {
            const int lin = i * 128 + tid;
            const int row = lin >> 4, seg = lin & 15;
            const uint32_t so = (uint32_t)row * TROW + seg * 16;
            const size_t g = (size_t)(b * LL + l0 + row) * DD + h * DH + seg * 8;
            CP16(base + so, g_feat_f + g);
            CP16(base + TTILE + so, g_v_f + g);
        }
    };

    const int lbase = ch * KCHL;
    load_stage(0, lbase);
    CP_COMMIT();

    for (int c = 0; c < KCHL / 32; c++) {
        if (c + 1 < KCHL / 32) {
            load_stage((c + 1) & 1, lbase + (c + 1) * 32);
            CP_COMMIT();
            CP_WAIT1();
        } else {
            CP_WAIT0();
        }
        __syncthreads();
        const uint32_t base = sb + (uint32_t)(c & 1) * 2 * TTILE;
#pragma unroll
        for (int ks = 0; ks < 2; ks++) {
            const uint32_t kro = (uint32_t)ks * 16 * TROW;
            uint32_t a[4][4], bb[4][4];
#pragma unroll
            for (int mt = 0; mt < 4; mt++)
                LDSM4T(a[mt][0], a[mt][1], a[mt][2], a[mt][3],
                       base + kro + aoff + (uint32_t)mt * 32);
#pragma unroll
            for (int p = 0; p < 4; p++)
                LDSM4T(bb[p][0], bb[p][1], bb[p][2], bb[p][3],
                       base + TTILE + kro + boff + (uint32_t)p * 32);
#pragma unroll
            for (int mt = 0; mt < 4; mt++)
#pragma unroll
                for (int p = 0; p < 4; p++) {
                    mma16816(acc[mt][p * 2 + 0], a[mt], bb[p][0], bb[p][1]);
                    mma16816(acc[mt][p * 2 + 1], a[mt], bb[p][2], bb[p][3]);
                }
        }
        __syncthreads();
    }

    const int gid = lane >> 2, t4 = lane & 3;
    float* outp = g_kvp + ((size_t)bh * NKCH + ch) * (DH * DH);
#pragma unroll
    for (int mt = 0; mt < 4; mt++)
#pragma unroll
        for (int nt = 0; nt < 8; nt++) {
            const float* c = acc[mt][nt];
            const int d0 = wm * 64 + mt * 16 + gid;
            const int vv = wn * 64 + nt * 8 + t4 * 2;
#pragma unroll
            for (int half_ = 0; half_ < 2; half_++) {
                float2 f;
                f.x = c[half_ * 2 + 0];
                f.y = c[half_ * 2 + 1];
                *(float2*)(outp + (d0 + half_ * 8) * DH + vv) = f;
            }
        }
}

// Reduce KV partials -> KV^T f16 [bh][v][d]
__global__ void kv_reduce_k() {
    int o = blockIdx.x * 256 + threadIdx.x;    // BB*HH*16384
    int bh = o >> 14;
    int e = o & 16383;
    int v = e >> 7, d = e & 127;
    float s = 0.f;
    const float* p = g_kvp + (size_t)bh * NKCH * (DH * DH) + d * DH + v;
#pragma unroll
    for (int c = 0; c < NKCH; c++)
        s += p[(size_t)c * (DH * DH)];
    g_kvt[o] = __float2half(s);
}

// ---------------------------------------------------------------------------
// msg MMA: per (lblock, bh): msg[l, v] = (sum_d F[l,d] * KVT[v,d]) * Z[l,h]
// Standard (non-trans) loads; K = 128 single-shot staging.
// ---------------------------------------------------------------------------
#define MTILE (128 * TROW)       // 34816 B per array

__global__ void __launch_bounds__(128, 2) msg_mma_k() {
    extern __shared__ __align__(16) char smem[];
    const uint32_t sb = smem_u32(smem);
    const int lb = blockIdx.x, bh = blockIdx.y;
    const int b = bh >> 3, h = bh & 7;
    const int l0 = lb * 128;
    const int tid = threadIdx.x, warp = tid >> 5, lane = tid & 31;
    const int wm = warp >> 1, wn = warp & 1;
    float acc[4][8][4] = {};

    const uint32_t aoff = (uint32_t)(wm * 64 + (lane & 15)) * TROW + ((lane >> 4) << 4);
    const int nloc = (lane & 7) + ((lane >> 4) << 3);
    const uint32_t boff = (uint32_t)(wn * 64 + nloc) * TROW + (((lane >> 3) & 1) << 4);

    // stage A (F rows) and B (KVT rows), 128 x 256B each
#pragma unroll
    for (int i = 0; i < 16; i++) {
        const int lin = i * 128 + tid;
        const int row = lin >> 4, seg = lin & 15;
        const uint32_t so = (uint32_t)row * TROW + seg * 16;
        CP16(sb + so, g_feat_f + (size_t)(b * LL + l0 + row) * DD + h * DH + seg * 8);
        CP16(sb + MTILE + so, g_kvt + (size_t)bh * (DH * DH) + row * DH + seg * 8);
    }
    CP_COMMIT();
    CP_WAIT0();
    __syncthreads();

#pragma unroll
    for (int ks = 0; ks < 8; ks++) {
        const uint32_t kso = (uint32_t)ks * 32;
        uint32_t a[4][4], bb[4][4];
#pragma unroll
        for (int mt = 0; mt < 4; mt++)
            LDSM4(a[mt][0], a[mt][1], a[mt][2], a[mt][3],
                  sb + aoff + (uint32_t)mt * 16 * TROW + kso);
#pragma unroll
        for (int p = 0; p < 4; p++)
            LDSM4(bb[p][0], bb[p][1], bb[p][2], bb[p][3],
                  sb + MTILE + boff + (uint32_t)p * 16 * TROW + kso);
#pragma unroll
        for (int mt = 0; mt < 4; mt++)
#pragma unroll
            for (int p = 0; p < 4; p++) {
                mma16816(acc[mt][p * 2 + 0], a[mt], bb[p][0], bb[p][1]);
                mma16816(acc[mt][p * 2 + 1], a[mt], bb[p][2], bb[p][3]);
            }
    }

    const int gid = lane >> 2, t4 = lane & 3;
#pragma unroll
    for (int mt = 0; mt < 4; mt++)
#pragma unroll
        for (int nt = 0; nt < 8; nt++) {
            const float* c = acc[mt][nt];
            const int lr = wm * 64 + mt * 16 + gid;
            const int cc = wn * 64 + nt * 8 + t4 * 2;
#pragma unroll
            for (int half_ = 0; half_ < 2; half_++) {
                const int n = b * LL + l0 + lr + half_ * 8;
                const float z = g_z[n * HH + h];
                __half2 hh;
                hh.x = __float2half(c[half_ * 2 + 0] * z);
                hh.y = __float2half(c[half_ * 2 + 1] * z);
                *(__half2*)(g_msg_f + (size_t)n * DD + h * DH + cc) = hh;
            }
        }
}

// ---------------------------------------------------------------------------
// Conversion kernels
// ---------------------------------------------------------------------------
__global__ void cvt_k(const float* __restrict__ in, __half* __restrict__ o, int n) {
    int i = blockIdx.x * 256 + threadIdx.x;
    if (i < n) o[i] = __float2half(in[i]);
}

__global__ void wtrans_k(const float* __restrict__ W, __half* __restrict__ Thi,
                         __half* __restrict__ Tlo, int K, int N) {
    __shared__ float t[32][33];
    const int k0 = blockIdx.y * 32, n0 = blockIdx.x * 32;
    const int tx = threadIdx.x, ty = threadIdx.y;
#pragma unroll
    for (int i = 0; i < 4; i++)
        t[ty + i * 8][tx] = W[(size_t)(k0 + ty + i * 8) * N + n0 + tx];
    __syncthreads();
#pragma unroll
    for (int i = 0; i < 4; i++) {
        float v = t[tx][ty + i * 8];
        __half h, l;
        splith(v, h, l);
        const size_t o = (size_t)(n0 + ty + i * 8) * K + k0 + tx;
        Thi[o] = h;
        if (Tlo) Tlo[o] = l;
    }
}

// ---------------------------------------------------------------------------
// Ksum / Z (read f16 feat)
// ---------------------------------------------------------------------------
__global__ void __launch_bounds__(128) ksum_part_k() {
    const int ch = blockIdx.x, bh = blockIdx.y;
    const int b = bh >> 3, h = bh & 7;
    const int i = threadIdx.x;
    float s = 0.f;
    const __half* base = g_feat_f + (size_t)(b * LL + ch * KSL) * DD + h * DH + i;
#pragma unroll 8
    for (int l = 0; l < KSL; l++)
        s += __half2float(base[(size_t)l * DD]);
    g_ksp[(bh * KSC + ch) * DH + i] = s;
}

__global__ void ksum_reduce_k() {
    int idx = blockIdx.x * 256 + threadIdx.x;
    int bh = idx >> 7;
    int i = idx & 127;
    float s = 0.f;
#pragma unroll
    for (int c = 0; c < KSC; c++)
        s += g_ksp[(bh * KSC + c) * DH + i];
    g_ks[idx] = s;
}

__global__ void __launch_bounds__(256) z_k() {
    __shared__ float sk[BB * HH * DH];
    for (int i = threadIdx.x; i < BB * HH * DH; i += 256) sk[i] = g_ks[i];
    __syncthreads();
    const int wi = threadIdx.x >> 5, lane = threadIdx.x & 31;
    const int idx = blockIdx.x * 8 + wi;
    const int n = idx >> 3, h = idx & 7;
    const int b = n >> 13;
    const __half* qp = g_feat_f + (size_t)n * DD + h * DH + lane * 4;
    const float* kp = sk + (b * HH + h) * DH + lane * 4;
    __half2 f0 = *(const __half2*)qp;
    __half2 f1 = *(const __half2*)(qp + 2);
    float dot = __half2float(f0.x) * kp[0] + __half2float(f0.y) * kp[1] +
                __half2float(f1.x) * kp[2] + __half2float(f1.y) * kp[3];
#pragma unroll
    for (int o = 16; o > 0; o >>= 1) dot += __shfl_xor_sync(0xffffffffu, dot, o);
    if (lane == 0) g_z[idx] = 1.0f / (dot + ATTN_EPS);
}

// ---------------------------------------------------------------------------
// LayerNorm + residual
// ---------------------------------------------------------------------------
__device__ __forceinline__ float warpReduceSum(float v) {
#pragma unroll
    for (int o = 16; o > 0; o >>= 1) v += __shfl_xor_sync(0xffffffffu, v, o);
    return v;
}

__global__ void __launch_bounds__(256) ln_k(const float* __restrict__ t,
                                            const float* __restrict__ base,
                                            const float* __restrict__ gam,
                                            const float* __restrict__ bet,
                                            float* __restrict__ out) {
    const int n = blockIdx.x;
    __shared__ float row[DD];
    __shared__ float rs[8], rs2[8];
    __shared__ float smu, srstd;
    const float* tp = t + (size_t)n * DD;
    float s = 0.f, s2 = 0.f;
    for (int d = threadIdx.x; d < DD; d += 256) {
        float v = tp[d];
        row[d] = v;
        s += v;
        s2 = fmaf(v, v, s2);
    }
    s = warpReduceSum(s);
    s2 = warpReduceSum(s2);
    int lane = threadIdx.x & 31, wid = threadIdx.x >> 5;
    if (lane == 0) { rs[wid] = s; rs2[wid] = s2; }
    __syncthreads();
    if (threadIdx.x < 32) {
        float a = (threadIdx.x < 8) ? rs[threadIdx.x] : 0.f;
        float b2 = (threadIdx.x < 8) ? rs2[threadIdx.x] : 0.f;
        a = warpReduceSum(a);
        b2 = warpReduceSum(b2);
        if (threadIdx.x == 0) {
            float mu = a * (1.0f / DD);
            float var = b2 * (1.0f / DD) - mu * mu;
            smu = mu;
            srstd = rsqrtf(var + LN_EPS);
        }
    }
    __syncthreads();
    float mu = smu, rstd = srstd;
    const float* bp = base + (size_t)n * DD;
    float* op = out + (size_t)n * DD;
    for (int d = threadIdx.x; d < DD; d += 256)
        op[d] = bp[d] + (row[d] - mu) * rstd * gam[d] + bet[d];
}

// ---------------------------------------------------------------------------
extern "C" void kernel_launch(void* const* d_in, const int* in_sizes, int n_in,
                              void* d_out, int out_size) {
    (void)in_sizes; (void)n_in; (void)out_size;
    const float* x  = (const float*)d_in[0];
    const float* Wq = (const float*)d_in[1];
    const float* Wm = (const float*)d_in[2];
    const float* W1 = (const float*)d_in[3];
    const float* W2 = (const float*)d_in[4];
    const float* g1 = (const float*)d_in[5];
    const float* b1 = (const float*)d_in[6];
    const float* g2 = (const float*)d_in[7];
    const float* b2 = (const float*)d_in[8];
    float* out = (float*)d_out;

    float* tmp;
    __half *x_h, *feat_f, *v_f, *msg_f, *tmp_f, *h1_f;
    __half *wq_h, *wq_l, *wm_h, *w1_h, *w2_h;
    cudaGetSymbolAddress((void**)&tmp,    g_tmp);
    cudaGetSymbolAddress((void**)&x_h,    g_x_h);
    cudaGetSymbolAddress((void**)&feat_f, g_feat_f);
    cudaGetSymbolAddress((void**)&v_f,    g_v_f);
    cudaGetSymbolAddress((void**)&msg_f,  g_msg_f);
    cudaGetSymbolAddress((void**)&tmp_f,  g_tmp_f);
    cudaGetSymbolAddress((void**)&h1_f,   g_h1_f);
    cudaGetSymbolAddress((void**)&wq_h,   g_wq_h);
    cudaGetSymbolAddress((void**)&wq_l,   g_wq_l);
    cudaGetSymbolAddress((void**)&wm_h,   g_wm_h);
    cudaGetSymbolAddress((void**)&w1_h,   g_w1_h);
    cudaGetSymbolAddress((void**)&w2_h,   g_w2_h);

    const int SM2 = 2 * 3 * GTILE;   // 61440 B
    const int SM1 = 2 * 2 * GTILE;   // 40960 B
    const int SMM = 2 * MTILE;       // 69632 B (msg)
    cudaFuncSetAttribute(hgemm_k<3, 2>, cudaFuncAttributeMaxDynamicSharedMemorySize, SM2);
    cudaFuncSetAttribute(hgemm_k<0, 1>, cudaFuncAttributeMaxDynamicSharedMemorySize, SM1);
    cudaFuncSetAttribute(hgemm_k<1, 1>, cudaFuncAttributeMaxDynamicSharedMemorySize, SM1);
    cudaFuncSetAttribute(hgemm_k<2, 1>, cudaFuncAttributeMaxDynamicSharedMemorySize, SM1);
    cudaFuncSetAttribute(msg_mma_k, cudaFuncAttributeMaxDynamicSharedMemorySize, SMM);

    // 0. Convert inputs
    cvt_k<<<(NROW * DD + 255) / 256, 256>>>(x, x_h, NROW * DD);
    wtrans_k<<<dim3(DD / 32, DD / 32), dim3(32, 8)>>>(Wq, wq_h, wq_l, DD, DD);
    wtrans_k<<<dim3(DFF / 32, DD / 32), dim3(32, 8)>>>(W1, w1_h, nullptr, DD, DFF);
    wtrans_k<<<dim3(DD / 32, DD / 32), dim3(32, 8)>>>(Wm, wm_h, nullptr, DD, DD);
    wtrans_k<<<dim3(DD / 32, DFF / 32), dim3(32, 8)>>>(W2, w2_h, nullptr, DFF, DD);

    // 1. q = x @ Wq, epilogue emits feat(q) f16 + q f16 (no fp32 q)
    hgemm_k<3, 2><<<dim3(DD / 128, NROW / 128), 128, SM2>>>(
        x_h, wq_h, wq_l, nullptr, feat_f, v_f, DD, DD);
    // 2. attention: KV (tensor-core), Ksum, Z
    kv_mma_k<<<dim3(NKCH, BB * HH), 128>>>();
    kv_reduce_k<<<BB * HH * DH * DH / 256, 256>>>();
    ksum_part_k<<<dim3(KSC, BB * HH), 128>>>();
    ksum_reduce_k<<<BB * HH * DH / 256, 256>>>();
    z_k<<<NROW * HH / 8, 256>>>();
    // 3. msg (tensor-core, Z-scaled f16 out)
    msg_mma_k<<<dim3(LL / 128, BB * HH), 128, SMM>>>();
    // 4. tmp = msg @ Wm (fp32 + f16) -- the rebinded "msg"
    hgemm_k<1, 1><<<dim3(DD / 128, NROW / 128), 128, SM1>>>(
        msg_f, wm_h, nullptr, tmp, tmp_f, nullptr, DD, DD);
    // 5. out = x + LN(tmp)
    ln_k<<<NROW, 256>>>(tmp, x, g1, b1, out);
    // 6. h1 = relu(tmp @ W1) (f16 only)
    hgemm_k<2, 1><<<dim3(DFF / 128, NROW / 128), 128, SM1>>>(
        tmp_f, w1_h, nullptr, nullptr, h1_f, nullptr, DFF, DD);
    // 7. tmp = h1 @ W2 (fp32)
    hgemm_k<0, 1><<<dim3(DD / 128, NROW / 128), 128, SM1>>>(
        h1_f, w2_h, nullptr, tmp, nullptr, nullptr, DD, DFF);
    // 8. out += LN(tmp)
    ln_k<<<NROW, 256>>>(tmp, out, g2, b2, out);
}

// round 13
// speedup vs baseline: 2.3088x; 1.0886x over previous
#include <cuda_runtime.h>
#include <cuda_fp16.h>
#include <math.h>
#include <stdint.h>

// Problem constants
#define BB   2
#define LL   8192
#define DD   1024
#define HH   8
#define DH   128
#define NROW (BB*LL)     // 16384
#define DFF  (2*DD)      // 2048
#define NKCH 16          // kv chunk count
#define KCHL (LL/NKCH)   // 512 l-rows per kv chunk
#define KSC  128         // ksum chunk count
#define KSL  (LL/KSC)    // 64 rows per ksum chunk
#define ATTN_EPS 1e-6f
#define LN_EPS   1e-5f

// ---------------------------------------------------------------------------
// Scratch (device globals: allocation-free per harness rules)
// ---------------------------------------------------------------------------
__device__ float g_tmp[NROW*DD];                // msg@Wm fp32 (LN1 input), then mlp out
__device__ float g_kvp[BB*HH*NKCH*DH*DH];       // KV partials per L-chunk (fp32)
__device__ float g_ksp[BB*HH*KSC*DH];           // Ksum partials
__device__ float g_ks[BB*HH*DH];                // Ksum
__device__ float g_z[NROW*HH];                  // 1/(Q.Ksum + eps)

// f16 operands
__device__ __half g_x_h[NROW*DD];
__device__ __half g_feat_f[NROW*DD];            // feat(q) = elu(q)+1, f16
__device__ __half g_v_f[NROW*DD];               // q (value, unscaled), f16
__device__ __half g_kvt[BB*HH*DH*DH];           // KV^T [bh][v][d] f16
__device__ __half g_msg_f[NROW*DD];
__device__ __half g_tmp_f[NROW*DD];
__device__ __half g_h1_f[NROW*DFF];
// transposed weights [N, K] K-major, fp16, single precision level
__device__ __half g_wq_h[DD*DD];
__device__ __half g_wm_h[DD*DD];
__device__ __half g_w1_h[DFF*DD];
__device__ __half g_w2_h[DD*DFF];

// ---------------------------------------------------------------------------
// Helpers
// ---------------------------------------------------------------------------
__device__ __forceinline__ uint32_t smem_u32(const void* p) {
    uint32_t a;
    asm("{ .reg .u64 t; cvta.to.shared.u64 t, %1; cvt.u32.u64 %0, t; }" : "=r"(a) : "l"(p));
    return a;
}

__device__ __forceinline__ float featf(float v) {
    return v > 0.f ? v + 1.f : expf(v);
}

#define LDSM4(r0, r1, r2, r3, addr) \
    asm volatile("ldmatrix.sync.aligned.m8n8.x4.shared.b16 {%0,%1,%2,%3}, [%4];" \
                 : "=r"(r0), "=r"(r1), "=r"(r2), "=r"(r3) : "r"(addr))
#define LDSM4T(r0, r1, r2, r3, addr) \
    asm volatile("ldmatrix.sync.aligned.m8n8.x4.trans.shared.b16 {%0,%1,%2,%3}, [%4];" \
                 : "=r"(r0), "=r"(r1), "=r"(r2), "=r"(r3) : "r"(addr))

#define CP16(dst, src) \
    asm volatile("cp.async.cg.shared.global [%0], [%1], 16;" :: "r"(dst), "l"(src))
#define CP_COMMIT() asm volatile("cp.async.commit_group;" ::: "memory")
#define CP_WAIT1()  asm volatile("cp.async.wait_group 1;" ::: "memory")
#define CP_WAIT0()  asm volatile("cp.async.wait_group 0;" ::: "memory")

__device__ __forceinline__ void mma16816(float* c, const uint32_t* a,
                                         uint32_t b0, uint32_t b1) {
    asm volatile("mma.sync.aligned.m16n8k16.row.col.f32.f16.f16.f32 "
                 "{%0,%1,%2,%3}, {%4,%5,%6,%7}, {%8,%9}, {%0,%1,%2,%3};"
                 : "+f"(c[0]), "+f"(c[1]), "+f"(c[2]), "+f"(c[3])
                 : "r"(a[0]), "r"(a[1]), "r"(a[2]), "r"(a[3]), "r"(b0), "r"(b1));
}

// ---------------------------------------------------------------------------
// HMMA GEMM: C = A @ B^T, B stored [N,K] K-major, fp16 in / fp32 accumulate.
// Block tile 128x128, K-chunk 32, 4 warps (2x2), warp tile 64x64, cp.async 2-stage.
// EPI: 0 = fp32 C; 1 = fp32 C + f16 Cf; 2 = relu then f16 Cf only;
//      3 = f16 feat(C) -> Cf and f16 C -> Cf2 (Wq epilogue).
// ---------------------------------------------------------------------------
#define SROW  80
#define GTILE (128 * SROW)
#define GSTG  (2 * GTILE)        // Ah, Bh
#define GSMEM (2 * GSTG)         // 40960 B, two stages

template <int EPI>
__global__ void __launch_bounds__(128, 2)
hgemm_k(const __half* __restrict__ Ah, const __half* __restrict__ Bh,
        float* __restrict__ C, __half* __restrict__ Cf, __half* __restrict__ Cf2,
        int Nn, int K) {
    extern __shared__ __align__(16) char smem[];
    const uint32_t sb = smem_u32(smem);
    const int tid = threadIdx.x, warp = tid >> 5, lane = tid & 31;
    const int wm = warp >> 1, wn = warp & 1;
    const int m0 = blockIdx.y * 128, n0 = blockIdx.x * 128;

    float acc[4][8][4] = {};

    const uint32_t aoff = (uint32_t)(wm * 64 + (lane & 15)) * SROW + ((lane >> 4) << 4);
    const int nloc = (lane & 7) + ((lane >> 4) << 3);
    const uint32_t boff = (uint32_t)(wn * 64 + nloc) * SROW + (((lane >> 3) & 1) << 4);

    const int lrow = tid >> 2, lseg = tid & 3;

    auto load_stage = [&](int s, int kc) {
        const uint32_t base = sb + (uint32_t)s * GSTG;
#pragma unroll
        for (int i = 0; i < 4; i++) {
            const int r = lrow + i * 32;
            const uint32_t so = (uint32_t)r * SROW + lseg * 16;
            CP16(base + so, Ah + (size_t)(m0 + r) * K + kc + lseg * 8);
            CP16(base + GTILE + so, Bh + (size_t)(n0 + r) * K + kc + lseg * 8);
        }
    };

    const int nch = K / 32;
    load_stage(0, 0);
    CP_COMMIT();

    for (int c = 0; c < nch; c++) {
        if (c + 1 < nch) {
            load_stage((c + 1) & 1, (c + 1) * 32);
            CP_COMMIT();
            CP_WAIT1();
        } else {
            CP_WAIT0();
        }
        __syncthreads();
        const uint32_t base = sb + (uint32_t)(c & 1) * GSTG;
#pragma unroll
        for (int ks = 0; ks < 2; ks++) {
            const uint32_t kso = (uint32_t)ks * 32;
            uint32_t ah[4][4], bh[4][4];
#pragma unroll
            for (int mt = 0; mt < 4; mt++)
                LDSM4(ah[mt][0], ah[mt][1], ah[mt][2], ah[mt][3],
                      base + aoff + (uint32_t)mt * 16 * SROW + kso);
#pragma unroll
            for (int p = 0; p < 4; p++)
                LDSM4(bh[p][0], bh[p][1], bh[p][2], bh[p][3],
                      base + GTILE + boff + (uint32_t)p * 16 * SROW + kso);
#pragma unroll
            for (int mt = 0; mt < 4; mt++)
#pragma unroll
                for (int p = 0; p < 4; p++) {
                    mma16816(acc[mt][p * 2 + 0], ah[mt], bh[p][0], bh[p][1]);
                    mma16816(acc[mt][p * 2 + 1], ah[mt], bh[p][2], bh[p][3]);
                }
        }
        __syncthreads();
    }

    const int gid = lane >> 2, t4 = lane & 3;
#pragma unroll
    for (int mt = 0; mt < 4; mt++) {
#pragma unroll
        for (int nt = 0; nt < 8; nt++) {
            const float* c = acc[mt][nt];
            const int r0 = m0 + wm * 64 + mt * 16 + gid;
            const int cc = n0 + wn * 64 + nt * 8 + t4 * 2;
#pragma unroll
            for (int half_ = 0; half_ < 2; half_++) {
                const int r = r0 + half_ * 8;
                float v0 = c[half_ * 2 + 0], v1 = c[half_ * 2 + 1];
                if (EPI <= 1) {
                    float2 f; f.x = v0; f.y = v1;
                    *(float2*)(C + (size_t)r * Nn + cc) = f;
                }
                if (EPI == 1 || EPI == 2) {
                    if (EPI == 2) { v0 = fmaxf(v0, 0.f); v1 = fmaxf(v1, 0.f); }
                    __half2 hh;
                    hh.x = __float2half(v0);
                    hh.y = __float2half(v1);
                    *(__half2*)(Cf + (size_t)r * Nn + cc) = hh;
                }
                if (EPI == 3) {
                    __half2 fh, vh;
                    fh.x = __float2half(featf(v0));
                    fh.y = __float2half(featf(v1));
                    vh.x = __float2half(v0);
                    vh.y = __float2half(v1);
                    *(__half2*)(Cf  + (size_t)r * Nn + cc) = fh;
                    *(__half2*)(Cf2 + (size_t)r * Nn + cc) = vh;
                }
            }
        }
    }
}

// ---------------------------------------------------------------------------
// KV MMA: per (chunk, bh): KVp[d,v] = sum_{l in chunk} F[l,d] * V[l,v]
// A = F^T, B = V, both via ldmatrix.trans from [l, .]-major smem tiles.
// ---------------------------------------------------------------------------
#define TROW 272                 // 128 f16 + 8 pad = 272 bytes/row
#define TTILE (32 * TROW)        // 8704 B

__global__ void __launch_bounds__(128, 2) kv_mma_k() {
    __shared__ __align__(16) char smem[4 * TTILE];   // 2 stages x (F, V)
    const uint32_t sb = smem_u32(smem);
    const int ch = blockIdx.x, bh = blockIdx.y;
    const int b = bh >> 3, h = bh & 7;
    const int tid = threadIdx.x, warp = tid >> 5, lane = tid & 31;
    const int wm = warp >> 1, wn = warp & 1;
    float acc[4][8][4] = {};

    const uint32_t aoff = (uint32_t)((lane >> 4) * 8 + (lane & 7)) * TROW
                        + (uint32_t)(wm * 64 + ((lane >> 3) & 1) * 8) * 2;
    const uint32_t boff = (uint32_t)(((lane >> 3) & 1) * 8 + (lane & 7)) * TROW
                        + (uint32_t)(wn * 64 + (lane >> 4) * 8) * 2;

    auto load_stage = [&](int st, int l0) {
        const uint32_t base = sb + (uint32_t)st * 2 * TTILE;
#pragma unroll
        for (int i = 0; i < 4; i++) {
            const int lin = i * 128 + tid;
            const int row = lin >> 4, seg = lin & 15;
            const uint32_t so = (uint32_t)row * TROW + seg * 16;
            const size_t g = (size_t)(b * LL + l0 + row) * DD + h * DH + seg * 8;
            CP16(base + so, g_feat_f + g);
            CP16(base + TTILE + so, g_v_f + g);
        }
    };

    const int lbase = ch * KCHL;
    load_stage(0, lbase);
    CP_COMMIT();

    for (int c = 0; c < KCHL / 32; c++) {
        if (c + 1 < KCHL / 32) {
            load_stage((c + 1) & 1, lbase + (c + 1) * 32);
            CP_COMMIT();
            CP_WAIT1();
        } else {
            CP_WAIT0();
        }
        __syncthreads();
        const uint32_t base = sb + (uint32_t)(c & 1) * 2 * TTILE;
#pragma unroll
        for (int ks = 0; ks < 2; ks++) {
            const uint32_t kro = (uint32_t)ks * 16 * TROW;
            uint32_t a[4][4], bb[4][4];
#pragma unroll
            for (int mt = 0; mt < 4; mt++)
                LDSM4T(a[mt][0], a[mt][1], a[mt][2], a[mt][3],
                       base + kro + aoff + (uint32_t)mt * 32);
#pragma unroll
            for (int p = 0; p < 4; p++)
                LDSM4T(bb[p][0], bb[p][1], bb[p][2], bb[p][3],
                       base + TTILE + kro + boff + (uint32_t)p * 32);
#pragma unroll
            for (int mt = 0; mt < 4; mt++)
#pragma unroll
                for (int p = 0; p < 4; p++) {
                    mma16816(acc[mt][p * 2 + 0], a[mt], bb[p][0], bb[p][1]);
                    mma16816(acc[mt][p * 2 + 1], a[mt], bb[p][2], bb[p][3]);
                }
        }
        __syncthreads();
    }

    const int gid = lane >> 2, t4 = lane & 3;
    float* outp = g_kvp + ((size_t)bh * NKCH + ch) * (DH * DH);
#pragma unroll
    for (int mt = 0; mt < 4; mt++)
#pragma unroll
        for (int nt = 0; nt < 8; nt++) {
            const float* c = acc[mt][nt];
            const int d0 = wm * 64 + mt * 16 + gid;
            const int vv = wn * 64 + nt * 8 + t4 * 2;
#pragma unroll
            for (int half_ = 0; half_ < 2; half_++) {
                float2 f;
                f.x = c[half_ * 2 + 0];
                f.y = c[half_ * 2 + 1];
                *(float2*)(outp + (d0 + half_ * 8) * DH + vv) = f;
            }
        }
}

// Reduce KV partials -> KV^T f16 [bh][v][d]
__global__ void kv_reduce_k() {
    int o = blockIdx.x * 256 + threadIdx.x;    // BB*HH*16384
    int bh = o >> 14;
    int e = o & 16383;
    int v = e >> 7, d = e & 127;
    float s = 0.f;
    const float* p = g_kvp + (size_t)bh * NKCH * (DH * DH) + d * DH + v;
#pragma unroll
    for (int c = 0; c < NKCH; c++)
        s += p[(size_t)c * (DH * DH)];
    g_kvt[o] = __float2half(s);
}

// ---------------------------------------------------------------------------
// msg MMA: per (lblock, bh): msg[l, v] = (sum_d F[l,d] * KVT[v,d]) * Z[l,h]
// ---------------------------------------------------------------------------
#define MTILE (128 * TROW)       // 34816 B per array

__global__ void __launch_bounds__(128, 2) msg_mma_k() {
    extern __shared__ __align__(16) char smem[];
    const uint32_t sb = smem_u32(smem);
    const int lb = blockIdx.x, bh = blockIdx.y;
    const int b = bh >> 3, h = bh & 7;
    const int l0 = lb * 128;
    const int tid = threadIdx.x, warp = tid >> 5, lane = tid & 31;
    const int wm = warp >> 1, wn = warp & 1;
    float acc[4][8][4] = {};

    const uint32_t aoff = (uint32_t)(wm * 64 + (lane & 15)) * TROW + ((lane >> 4) << 4);
    const int nloc = (lane & 7) + ((lane >> 4) << 3);
    const uint32_t boff = (uint32_t)(wn * 64 + nloc) * TROW + (((lane >> 3) & 1) << 4);

#pragma unroll
    for (int i = 0; i < 16; i++) {
        const int lin = i * 128 + tid;
        const int row = lin >> 4, seg = lin & 15;
        const uint32_t so = (uint32_t)row * TROW + seg * 16;
        CP16(sb + so, g_feat_f + (size_t)(b * LL + l0 + row) * DD + h * DH + seg * 8);
        CP16(sb + MTILE + so, g_kvt + (size_t)bh * (DH * DH) + row * DH + seg * 8);
    }
    CP_COMMIT();
    CP_WAIT0();
    __syncthreads();

#pragma unroll
    for (int ks = 0; ks < 8; ks++) {
        const uint32_t kso = (uint32_t)ks * 32;
        uint32_t a[4][4], bb[4][4];
#pragma unroll
        for (int mt = 0; mt < 4; mt++)
            LDSM4(a[mt][0], a[mt][1], a[mt][2], a[mt][3],
                  sb + aoff + (uint32_t)mt * 16 * TROW + kso);
#pragma unroll
        for (int p = 0; p < 4; p++)
            LDSM4(bb[p][0], bb[p][1], bb[p][2], bb[p][3],
                  sb + MTILE + boff + (uint32_t)p * 16 * TROW + kso);
#pragma unroll
        for (int mt = 0; mt < 4; mt++)
#pragma unroll
            for (int p = 0; p < 4; p++) {
                mma16816(acc[mt][p * 2 + 0], a[mt], bb[p][0], bb[p][1]);
                mma16816(acc[mt][p * 2 + 1], a[mt], bb[p][2], bb[p][3]);
            }
    }

    const int gid = lane >> 2, t4 = lane & 3;
#pragma unroll
    for (int mt = 0; mt < 4; mt++)
#pragma unroll
        for (int nt = 0; nt < 8; nt++) {
            const float* c = acc[mt][nt];
            const int lr = wm * 64 + mt * 16 + gid;
            const int cc = wn * 64 + nt * 8 + t4 * 2;
#pragma unroll
            for (int half_ = 0; half_ < 2; half_++) {
                const int n = b * LL + l0 + lr + half_ * 8;
                const float z = g_z[n * HH + h];
                __half2 hh;
                hh.x = __float2half(c[half_ * 2 + 0] * z);
                hh.y = __float2half(c[half_ * 2 + 1] * z);
                *(__half2*)(g_msg_f + (size_t)n * DD + h * DH + cc) = hh;
            }
        }
}

// ---------------------------------------------------------------------------
// Conversion kernels
// ---------------------------------------------------------------------------
__global__ void cvt_k(const float* __restrict__ in, __half* __restrict__ o, int n) {
    int i = blockIdx.x * 256 + threadIdx.x;
    if (i < n) o[i] = __float2half(in[i]);
}

__global__ void wtrans_k(const float* __restrict__ W, __half* __restrict__ T,
                         int K, int N) {
    __shared__ float t[32][33];
    const int k0 = blockIdx.y * 32, n0 = blockIdx.x * 32;
    const int tx = threadIdx.x, ty = threadIdx.y;
#pragma unroll
    for (int i = 0; i < 4; i++)
        t[ty + i * 8][tx] = W[(size_t)(k0 + ty + i * 8) * N + n0 + tx];
    __syncthreads();
#pragma unroll
    for (int i = 0; i < 4; i++)
        T[(size_t)(n0 + ty + i * 8) * K + k0 + tx] = __float2half(t[tx][ty + i * 8]);
}

// ---------------------------------------------------------------------------
// Ksum / Z (read f16 feat)
// ---------------------------------------------------------------------------
__global__ void __launch_bounds__(128) ksum_part_k() {
    const int ch = blockIdx.x, bh = blockIdx.y;
    const int b = bh >> 3, h = bh & 7;
    const int i = threadIdx.x;
    float s = 0.f;
    const __half* base = g_feat_f + (size_t)(b * LL + ch * KSL) * DD + h * DH + i;
#pragma unroll 8
    for (int l = 0; l < KSL; l++)
        s += __half2float(base[(size_t)l * DD]);
    g_ksp[(bh * KSC + ch) * DH + i] = s;
}

__global__ void ksum_reduce_k() {
    int idx = blockIdx.x * 256 + threadIdx.x;
    int bh = idx >> 7;
    int i = idx & 127;
    float s = 0.f;
#pragma unroll
    for (int c = 0; c < KSC; c++)
        s += g_ksp[(bh * KSC + c) * DH + i];
    g_ks[idx] = s;
}

__global__ void __launch_bounds__(256) z_k() {
    __shared__ float sk[BB * HH * DH];
    for (int i = threadIdx.x; i < BB * HH * DH; i += 256) sk[i] = g_ks[i];
    __syncthreads();
    const int wi = threadIdx.x >> 5, lane = threadIdx.x & 31;
    const int idx = blockIdx.x * 8 + wi;
    const int n = idx >> 3, h = idx & 7;
    const int b = n >> 13;
    const __half* qp = g_feat_f + (size_t)n * DD + h * DH + lane * 4;
    const float* kp = sk + (b * HH + h) * DH + lane * 4;
    __half2 f0 = *(const __half2*)qp;
    __half2 f1 = *(const __half2*)(qp + 2);
    float dot = __half2float(f0.x) * kp[0] + __half2float(f0.y) * kp[1] +
                __half2float(f1.x) * kp[2] + __half2float(f1.y) * kp[3];
#pragma unroll
    for (int o = 16; o > 0; o >>= 1) dot += __shfl_xor_sync(0xffffffffu, dot, o);
    if (lane == 0) g_z[idx] = 1.0f / (dot + ATTN_EPS);
}

// ---------------------------------------------------------------------------
// LayerNorm + residual
// ---------------------------------------------------------------------------
__device__ __forceinline__ float warpReduceSum(float v) {
#pragma unroll
    for (int o = 16; o > 0; o >>= 1) v += __shfl_xor_sync(0xffffffffu, v, o);
    return v;
}

__global__ void __launch_bounds__(256) ln_k(const float* __restrict__ t,
                                            const float* __restrict__ base,
                                            const float* __restrict__ gam,
                                            const float* __restrict__ bet,
                                            float* __restrict__ out) {
    const int n = blockIdx.x;
    __shared__ float row[DD];
    __shared__ float rs[8], rs2[8];
    __shared__ float smu, srstd;
    const float* tp = t + (size_t)n * DD;
    float s = 0.f, s2 = 0.f;
    for (int d = threadIdx.x; d < DD; d += 256) {
        float v = tp[d];
        row[d] = v;
        s += v;
        s2 = fmaf(v, v, s2);
    }
    s = warpReduceSum(s);
    s2 = warpReduceSum(s2);
    int lane = threadIdx.x & 31, wid = threadIdx.x >> 5;
    if (lane == 0) { rs[wid] = s; rs2[wid] = s2; }
    __syncthreads();
    if (threadIdx.x < 32) {
        float a = (threadIdx.x < 8) ? rs[threadIdx.x] : 0.f;
        float b2 = (threadIdx.x < 8) ? rs2[threadIdx.x] : 0.f;
        a = warpReduceSum(a);
        b2 = warpReduceSum(b2);
        if (threadIdx.x == 0) {
            float mu = a * (1.0f / DD);
            float var = b2 * (1.0f / DD) - mu * mu;
            smu = mu;
            srstd = rsqrtf(var + LN_EPS);
        }
    }
    __syncthreads();
    float mu = smu, rstd = srstd;
    const float* bp = base + (size_t)n * DD;
    float* op = out + (size_t)n * DD;
    for (int d = threadIdx.x; d < DD; d += 256)
        op[d] = bp[d] + (row[d] - mu) * rstd * gam[d] + bet[d];
}

// ---------------------------------------------------------------------------
extern "C" void kernel_launch(void* const* d_in, const int* in_sizes, int n_in,
                              void* d_out, int out_size) {
    (void)in_sizes; (void)n_in; (void)out_size;
    const float* x  = (const float*)d_in[0];
    const float* Wq = (const float*)d_in[1];
    const float* Wm = (const float*)d_in[2];
    const float* W1 = (const float*)d_in[3];
    const float* W2 = (const float*)d_in[4];
    const float* g1 = (const float*)d_in[5];
    const float* b1 = (const float*)d_in[6];
    const float* g2 = (const float*)d_in[7];
    const float* b2 = (const float*)d_in[8];
    float* out = (float*)d_out;

    float* tmp;
    __half *x_h, *feat_f, *v_f, *msg_f, *tmp_f, *h1_f;
    __half *wq_h, *wm_h, *w1_h, *w2_h;
    cudaGetSymbolAddress((void**)&tmp,    g_tmp);
    cudaGetSymbolAddress((void**)&x_h,    g_x_h);
    cudaGetSymbolAddress((void**)&feat_f, g_feat_f);
    cudaGetSymbolAddress((void**)&v_f,    g_v_f);
    cudaGetSymbolAddress((void**)&msg_f,  g_msg_f);
    cudaGetSymbolAddress((void**)&tmp_f,  g_tmp_f);
    cudaGetSymbolAddress((void**)&h1_f,   g_h1_f);
    cudaGetSymbolAddress((void**)&wq_h,   g_wq_h);
    cudaGetSymbolAddress((void**)&wm_h,   g_wm_h);
    cudaGetSymbolAddress((void**)&w1_h,   g_w1_h);
    cudaGetSymbolAddress((void**)&w2_h,   g_w2_h);

    const int SMM = 2 * MTILE;       // 69632 B (msg)
    cudaFuncSetAttribute(hgemm_k<0>, cudaFuncAttributeMaxDynamicSharedMemorySize, GSMEM);
    cudaFuncSetAttribute(hgemm_k<1>, cudaFuncAttributeMaxDynamicSharedMemorySize, GSMEM);
    cudaFuncSetAttribute(hgemm_k<2>, cudaFuncAttributeMaxDynamicSharedMemorySize, GSMEM);
    cudaFuncSetAttribute(hgemm_k<3>, cudaFuncAttributeMaxDynamicSharedMemorySize, GSMEM);
    cudaFuncSetAttribute(msg_mma_k, cudaFuncAttributeMaxDynamicSharedMemorySize, SMM);

    // 0. Convert inputs
    cvt_k<<<(NROW * DD + 255) / 256, 256>>>(x, x_h, NROW * DD);
    wtrans_k<<<dim3(DD / 32, DD / 32), dim3(32, 8)>>>(Wq, wq_h, DD, DD);
    wtrans_k<<<dim3(DFF / 32, DD / 32), dim3(32, 8)>>>(W1, w1_h, DD, DFF);
    wtrans_k<<<dim3(DD / 32, DD / 32), dim3(32, 8)>>>(Wm, wm_h, DD, DD);
    wtrans_k<<<dim3(DD / 32, DFF / 32), dim3(32, 8)>>>(W2, w2_h, DFF, DD);

    // 1. q = x @ Wq (1-pass), epilogue emits feat(q) f16 + q f16
    hgemm_k<3><<<dim3(DD / 128, NROW / 128), 128, GSMEM>>>(
        x_h, wq_h, nullptr, feat_f, v_f, DD, DD);
    // 2. attention: KV (tensor-core), Ksum, Z
    kv_mma_k<<<dim3(NKCH, BB * HH), 128>>>();
    kv_reduce_k<<<BB * HH * DH * DH / 256, 256>>>();
    ksum_part_k<<<dim3(KSC, BB * HH), 128>>>();
    ksum_reduce_k<<<BB * HH * DH / 256, 256>>>();
    z_k<<<NROW * HH / 8, 256>>>();
    // 3. msg (tensor-core, Z-scaled f16 out)
    msg_mma_k<<<dim3(LL / 128, BB * HH), 128, SMM>>>();
    // 4. tmp = msg @ Wm (fp32 + f16) -- the rebinded "msg"
    hgemm_k<1><<<dim3(DD / 128, NROW / 128), 128, GSMEM>>>(
        msg_f, wm_h, tmp, tmp_f, nullptr, DD, DD);
    // 5. out = x + LN(tmp)
    ln_k<<<NROW, 256>>>(tmp, x, g1, b1, out);
    // 6. h1 = relu(tmp @ W1) (f16 only)
    hgemm_k<2><<<dim3(DFF / 128, NROW / 128), 128, GSMEM>>>(
        tmp_f, w1_h, nullptr, h1_f, nullptr, DFF, DD);
    // 7. tmp = h1 @ W2 (fp32)
    hgemm_k<0><<<dim3(DD / 128, NROW / 128), 128, GSMEM>>>(
        h1_f, w2_h, tmp, nullptr, nullptr, DD, DFF);
    // 8. out += LN(tmp)
    ln_k<<<NROW, 256>>>(tmp, out, g2, b2, out);
}

// round 14
// speedup vs baseline: 2.4466x; 1.0597x over previous
#include <cuda_runtime.h>
#include <cuda_fp16.h>
#include <math.h>
#include <stdint.h>

// Problem constants
#define BB   2
#define LL   8192
#define DD   1024
#define HH   8
#define DH   128
#define NROW (BB*LL)     // 16384
#define DFF  (2*DD)      // 2048
#define NKCH 16          // kv chunk count
#define KCHL (LL/NKCH)   // 512 l-rows per kv chunk
#define KSC  128         // ksum chunk count
#define KSL  (LL/KSC)    // 64 rows per ksum chunk
#define ATTN_EPS 1e-6f
#define LN_EPS   1e-5f

// ---------------------------------------------------------------------------
// Scratch (device globals: allocation-free per harness rules)
// ---------------------------------------------------------------------------
__device__ float g_kvp[BB*HH*NKCH*DH*DH];       // KV partials per L-chunk (fp32)
__device__ float g_ksp[BB*HH*KSC*DH];           // Ksum partials
__device__ float g_ks[BB*HH*DH];                // Ksum
__device__ float g_z[NROW*HH];                  // 1/(Q.Ksum + eps)

// f16 operands
__device__ __half g_x_h[NROW*DD];
__device__ __half g_feat_f[NROW*DD];            // feat(q) = elu(q)+1, f16
__device__ __half g_v_f[NROW*DD];               // q (value, unscaled), f16
__device__ __half g_kvt[BB*HH*DH*DH];           // KV^T [bh][v][d] f16
__device__ __half g_msg_f[NROW*DD];             // attention msg, then reused: mlp out
__device__ __half g_tmp_f[NROW*DD];             // msg@Wm f16 (LN1 input + W1 input)
__device__ __half g_h1_f[NROW*DFF];
// transposed weights [N, K] K-major, f16
__device__ __half g_wq_h[DD*DD];
__device__ __half g_wm_h[DD*DD];
__device__ __half g_w1_h[DFF*DD];
__device__ __half g_w2_h[DD*DFF];

// ---------------------------------------------------------------------------
// Helpers
// ---------------------------------------------------------------------------
__device__ __forceinline__ uint32_t smem_u32(const void* p) {
    uint32_t a;
    asm("{ .reg .u64 t; cvta.to.shared.u64 t, %1; cvt.u32.u64 %0, t; }" : "=r"(a) : "l"(p));
    return a;
}

__device__ __forceinline__ float featf(float v) {
    return v > 0.f ? v + 1.f : expf(v);
}

#define LDSM4(r0, r1, r2, r3, addr) \
    asm volatile("ldmatrix.sync.aligned.m8n8.x4.shared.b16 {%0,%1,%2,%3}, [%4];" \
                 : "=r"(r0), "=r"(r1), "=r"(r2), "=r"(r3) : "r"(addr))
#define LDSM4T(r0, r1, r2, r3, addr) \
    asm volatile("ldmatrix.sync.aligned.m8n8.x4.trans.shared.b16 {%0,%1,%2,%3}, [%4];" \
                 : "=r"(r0), "=r"(r1), "=r"(r2), "=r"(r3) : "r"(addr))

#define CP16(dst, src) \
    asm volatile("cp.async.cg.shared.global [%0], [%1], 16;" :: "r"(dst), "l"(src))
#define CP_COMMIT() asm volatile("cp.async.commit_group;" ::: "memory")
#define CP_WAIT1()  asm volatile("cp.async.wait_group 1;" ::: "memory")
#define CP_WAIT0()  asm volatile("cp.async.wait_group 0;" ::: "memory")

__device__ __forceinline__ void mma16816(float* c, const uint32_t* a,
                                         uint32_t b0, uint32_t b1) {
    asm volatile("mma.sync.aligned.m16n8k16.row.col.f32.f16.f16.f32 "
                 "{%0,%1,%2,%3}, {%4,%5,%6,%7}, {%8,%9}, {%0,%1,%2,%3};"
                 : "+f"(c[0]), "+f"(c[1]), "+f"(c[2]), "+f"(c[3])
                 : "r"(a[0]), "r"(a[1]), "r"(a[2]), "r"(a[3]), "r"(b0), "r"(b1));
}

// ---------------------------------------------------------------------------
// HMMA GEMM: C = A @ B^T, B stored [N,K] K-major, f16 in / fp32 acc / f16 out.
// Block tile 128x128, K-chunk 64, 4 warps (2x2), warp tile 64x64, cp.async 2-stage.
// EPI: 1 = f16 Cf; 2 = relu then f16 Cf; 3 = f16 feat(C)->Cf and f16 C->Cf2.
// Rows 144B (64 f16 + 16B pad): ldmatrix conflict-free (9x16B stride).
// ---------------------------------------------------------------------------
#define SROW  144
#define GTILE (128 * SROW)       // 18432 B
#define GSTG  (2 * GTILE)        // A, B = 36864 B
#define GSMEM (2 * GSTG)         // 73728 B, two stages

template <int EPI>
__global__ void __launch_bounds__(128, 2)
hgemm_k(const __half* __restrict__ Ah, const __half* __restrict__ Bh,
        __half* __restrict__ Cf, __half* __restrict__ Cf2, int Nn, int K) {
    extern __shared__ __align__(16) char smem[];
    const uint32_t sb = smem_u32(smem);
    const int tid = threadIdx.x, warp = tid >> 5, lane = tid & 31;
    const int wm = warp >> 1, wn = warp & 1;
    const int m0 = blockIdx.y * 128, n0 = blockIdx.x * 128;

    float acc[4][8][4] = {};

    const uint32_t aoff = (uint32_t)(wm * 64 + (lane & 15)) * SROW + ((lane >> 4) << 4);
    const int nloc = (lane & 7) + ((lane >> 4) << 3);
    const uint32_t boff = (uint32_t)(wn * 64 + nloc) * SROW + (((lane >> 3) & 1) << 4);

    auto load_stage = [&](int s, int kc) {
        const uint32_t base = sb + (uint32_t)s * GSTG;
#pragma unroll
        for (int i = 0; i < 8; i++) {
            const int lin = i * 128 + tid;
            const int r = lin >> 3, seg = lin & 7;
            const uint32_t so = (uint32_t)r * SROW + seg * 16;
            CP16(base + so, Ah + (size_t)(m0 + r) * K + kc + seg * 8);
            CP16(base + GTILE + so, Bh + (size_t)(n0 + r) * K + kc + seg * 8);
        }
    };

    const int nch = K / 64;
    load_stage(0, 0);
    CP_COMMIT();

    for (int c = 0; c < nch; c++) {
        if (c + 1 < nch) {
            load_stage((c + 1) & 1, (c + 1) * 64);
            CP_COMMIT();
            CP_WAIT1();
        } else {
            CP_WAIT0();
        }
        __syncthreads();
        const uint32_t base = sb + (uint32_t)(c & 1) * GSTG;
#pragma unroll
        for (int ks = 0; ks < 4; ks++) {
            const uint32_t kso = (uint32_t)ks * 32;
            uint32_t ah[4][4], bh[4][4];
#pragma unroll
            for (int mt = 0; mt < 4; mt++)
                LDSM4(ah[mt][0], ah[mt][1], ah[mt][2], ah[mt][3],
                      base + aoff + (uint32_t)mt * 16 * SROW + kso);
#pragma unroll
            for (int p = 0; p < 4; p++)
                LDSM4(bh[p][0], bh[p][1], bh[p][2], bh[p][3],
                      base + GTILE + boff + (uint32_t)p * 16 * SROW + kso);
#pragma unroll
            for (int mt = 0; mt < 4; mt++)
#pragma unroll
                for (int p = 0; p < 4; p++) {
                    mma16816(acc[mt][p * 2 + 0], ah[mt], bh[p][0], bh[p][1]);
                    mma16816(acc[mt][p * 2 + 1], ah[mt], bh[p][2], bh[p][3]);
                }
        }
        __syncthreads();
    }

    const int gid = lane >> 2, t4 = lane & 3;
#pragma unroll
    for (int mt = 0; mt < 4; mt++) {
#pragma unroll
        for (int nt = 0; nt < 8; nt++) {
            const float* c = acc[mt][nt];
            const int r0 = m0 + wm * 64 + mt * 16 + gid;
            const int cc = n0 + wn * 64 + nt * 8 + t4 * 2;
#pragma unroll
            for (int half_ = 0; half_ < 2; half_++) {
                const int r = r0 + half_ * 8;
                float v0 = c[half_ * 2 + 0], v1 = c[half_ * 2 + 1];
                if (EPI == 1 || EPI == 2) {
                    if (EPI == 2) { v0 = fmaxf(v0, 0.f); v1 = fmaxf(v1, 0.f); }
                    __half2 hh;
                    hh.x = __float2half(v0);
                    hh.y = __float2half(v1);
                    *(__half2*)(Cf + (size_t)r * Nn + cc) = hh;
                }
                if (EPI == 3) {
                    __half2 fh, vh;
                    fh.x = __float2half(featf(v0));
                    fh.y = __float2half(featf(v1));
                    vh.x = __float2half(v0);
                    vh.y = __float2half(v1);
                    *(__half2*)(Cf  + (size_t)r * Nn + cc) = fh;
                    *(__half2*)(Cf2 + (size_t)r * Nn + cc) = vh;
                }
            }
        }
    }
}

// ---------------------------------------------------------------------------
// KV MMA: per (chunk, bh): KVp[d,v] = sum_{l in chunk} F[l,d] * V[l,v]
// A = F^T, B = V, both via ldmatrix.trans from [l, .]-major smem tiles.
// ---------------------------------------------------------------------------
#define TROW 272                 // 128 f16 + 8 pad = 272 bytes/row
#define TTILE (32 * TROW)        // 8704 B

__global__ void __launch_bounds__(128, 2) kv_mma_k() {
    __shared__ __align__(16) char smem[4 * TTILE];   // 2 stages x (F, V)
    const uint32_t sb = smem_u32(smem);
    const int ch = blockIdx.x, bh = blockIdx.y;
    const int b = bh >> 3, h = bh & 7;
    const int tid = threadIdx.x, warp = tid >> 5, lane = tid & 31;
    const int wm = warp >> 1, wn = warp & 1;
    float acc[4][8][4] = {};

    const uint32_t aoff = (uint32_t)((lane >> 4) * 8 + (lane & 7)) * TROW
                        + (uint32_t)(wm * 64 + ((lane >> 3) & 1) * 8) * 2;
    const uint32_t boff = (uint32_t)(((lane >> 3) & 1) * 8 + (lane & 7)) * TROW
                        + (uint32_t)(wn * 64 + (lane >> 4) * 8) * 2;

    auto load_stage = [&](int st, int l0) {
        const uint32_t base = sb + (uint32_t)st * 2 * TTILE;
#pragma unroll
        for (int i = 0; i < 4; i++) {
            const int lin = i * 128 + tid;
            const int row = lin >> 4, seg = lin & 15;
            const uint32_t so = (uint32_t)row * TROW + seg * 16;
            const size_t g = (size_t)(b * LL + l0 + row) * DD + h * DH + seg * 8;
            CP16(base + so, g_feat_f + g);
            CP16(base + TTILE + so, g_v_f + g);
        }
    };

    const int lbase = ch * KCHL;
    load_stage(0, lbase);
    CP_COMMIT();

    for (int c = 0; c < KCHL / 32; c++) {
        if (c + 1 < KCHL / 32) {
            load_stage((c + 1) & 1, lbase + (c + 1) * 32);
            CP_COMMIT();
            CP_WAIT1();
        } else {
            CP_WAIT0();
        }
        __syncthreads();
        const uint32_t base = sb + (uint32_t)(c & 1) * 2 * TTILE;
#pragma unroll
        for (int ks = 0; ks < 2; ks++) {
            const uint32_t kro = (uint32_t)ks * 16 * TROW;
            uint32_t a[4][4], bb[4][4];
#pragma unroll
            for (int mt = 0; mt < 4; mt++)
                LDSM4T(a[mt][0], a[mt][1], a[mt][2], a[mt][3],
                       base + kro + aoff + (uint32_t)mt * 32);
#pragma unroll
            for (int p = 0; p < 4; p++)
                LDSM4T(bb[p][0], bb[p][1], bb[p][2], bb[p][3],
                       base + TTILE + kro + boff + (uint32_t)p * 32);
#pragma unroll
            for (int mt = 0; mt < 4; mt++)
#pragma unroll
                for (int p = 0; p < 4; p++) {
                    mma16816(acc[mt][p * 2 + 0], a[mt], bb[p][0], bb[p][1]);
                    mma16816(acc[mt][p * 2 + 1], a[mt], bb[p][2], bb[p][3]);
                }
        }
        __syncthreads();
    }

    const int gid = lane >> 2, t4 = lane & 3;
    float* outp = g_kvp + ((size_t)bh * NKCH + ch) * (DH * DH);
#pragma unroll
    for (int mt = 0; mt < 4; mt++)
#pragma unroll
        for (int nt = 0; nt < 8; nt++) {
            const float* c = acc[mt][nt];
            const int d0 = wm * 64 + mt * 16 + gid;
            const int vv = wn * 64 + nt * 8 + t4 * 2;
#pragma unroll
            for (int half_ = 0; half_ < 2; half_++) {
                float2 f;
                f.x = c[half_ * 2 + 0];
                f.y = c[half_ * 2 + 1];
                *(float2*)(outp + (d0 + half_ * 8) * DH + vv) = f;
            }
        }
}

// Reduce KV partials -> KV^T f16 [bh][v][d]
__global__ void kv_reduce_k() {
    int o = blockIdx.x * 256 + threadIdx.x;    // BB*HH*16384
    int bh = o >> 14;
    int e = o & 16383;
    int v = e >> 7, d = e & 127;
    float s = 0.f;
    const float* p = g_kvp + (size_t)bh * NKCH * (DH * DH) + d * DH + v;
#pragma unroll
    for (int c = 0; c < NKCH; c++)
        s += p[(size_t)c * (DH * DH)];
    g_kvt[o] = __float2half(s);
}

// ---------------------------------------------------------------------------
// msg MMA: per (lblock, bh): msg[l, v] = (sum_d F[l,d] * KVT[v,d]) * Z[l,h]
// ---------------------------------------------------------------------------
#define MTILE (128 * TROW)       // 34816 B per array

__global__ void __launch_bounds__(128, 2) msg_mma_k() {
    extern __shared__ __align__(16) char smem[];
    const uint32_t sb = smem_u32(smem);
    const int lb = blockIdx.x, bh = blockIdx.y;
    const int b = bh >> 3, h = bh & 7;
    const int l0 = lb * 128;
    const int tid = threadIdx.x, warp = tid >> 5, lane = tid & 31;
    const int wm = warp >> 1, wn = warp & 1;
    float acc[4][8][4] = {};

    const uint32_t aoff = (uint32_t)(wm * 64 + (lane & 15)) * TROW + ((lane >> 4) << 4);
    const int nloc = (lane & 7) + ((lane >> 4) << 3);
    const uint32_t boff = (uint32_t)(wn * 64 + nloc) * TROW + (((lane >> 3) & 1) << 4);

#pragma unroll
    for (int i = 0; i < 16; i++) {
        const int lin = i * 128 + tid;
        const int row = lin >> 4, seg = lin & 15;
        const uint32_t so = (uint32_t)row * TROW + seg * 16;
        CP16(sb + so, g_feat_f + (size_t)(b * LL + l0 + row) * DD + h * DH + seg * 8);
        CP16(sb + MTILE + so, g_kvt + (size_t)bh * (DH * DH) + row * DH + seg * 8);
    }
    CP_COMMIT();
    CP_WAIT0();
    __syncthreads();

#pragma unroll
    for (int ks = 0; ks < 8; ks++) {
        const uint32_t kso = (uint32_t)ks * 32;
        uint32_t a[4][4], bb[4][4];
#pragma unroll
        for (int mt = 0; mt < 4; mt++)
            LDSM4(a[mt][0], a[mt][1], a[mt][2], a[mt][3],
                  sb + aoff + (uint32_t)mt * 16 * TROW + kso);
#pragma unroll
        for (int p = 0; p < 4; p++)
            LDSM4(bb[p][0], bb[p][1], bb[p][2], bb[p][3],
                  sb + MTILE + boff + (uint32_t)p * 16 * TROW + kso);
#pragma unroll
        for (int mt = 0; mt < 4; mt++)
#pragma unroll
            for (int p = 0; p < 4; p++) {
                mma16816(acc[mt][p * 2 + 0], a[mt], bb[p][0], bb[p][1]);
                mma16816(acc[mt][p * 2 + 1], a[mt], bb[p][2], bb[p][3]);
            }
    }

    const int gid = lane >> 2, t4 = lane & 3;
#pragma unroll
    for (int mt = 0; mt < 4; mt++)
#pragma unroll
        for (int nt = 0; nt < 8; nt++) {
            const float* c = acc[mt][nt];
            const int lr = wm * 64 + mt * 16 + gid;
            const int cc = wn * 64 + nt * 8 + t4 * 2;
#pragma unroll
            for (int half_ = 0; half_ < 2; half_++) {
                const int n = b * LL + l0 + lr + half_ * 8;
                const float z = g_z[n * HH + h];
                __half2 hh;
                hh.x = __float2half(c[half_ * 2 + 0] * z);
                hh.y = __float2half(c[half_ * 2 + 1] * z);
                *(__half2*)(g_msg_f + (size_t)n * DD + h * DH + cc) = hh;
            }
        }
}

// ---------------------------------------------------------------------------
// Conversion kernels
// ---------------------------------------------------------------------------
__global__ void cvt_k(const float* __restrict__ in, __half* __restrict__ o, int n) {
    int i = blockIdx.x * 256 + threadIdx.x;
    if (i < n) o[i] = __float2half(in[i]);
}

__global__ void wtrans_k(const float* __restrict__ W, __half* __restrict__ T,
                         int K, int N) {
    __shared__ float t[32][33];
    const int k0 = blockIdx.y * 32, n0 = blockIdx.x * 32;
    const int tx = threadIdx.x, ty = threadIdx.y;
#pragma unroll
    for (int i = 0; i < 4; i++)
        t[ty + i * 8][tx] = W[(size_t)(k0 + ty + i * 8) * N + n0 + tx];
    __syncthreads();
#pragma unroll
    for (int i = 0; i < 4; i++)
        T[(size_t)(n0 + ty + i * 8) * K + k0 + tx] = __float2half(t[tx][ty + i * 8]);
}

// ---------------------------------------------------------------------------
// Ksum / Z (read f16 feat)
// ---------------------------------------------------------------------------
__global__ void __launch_bounds__(128) ksum_part_k() {
    const int ch = blockIdx.x, bh = blockIdx.y;
    const int b = bh >> 3, h = bh & 7;
    const int i = threadIdx.x;
    float s = 0.f;
    const __half* base = g_feat_f + (size_t)(b * LL + ch * KSL) * DD + h * DH + i;
#pragma unroll 8
    for (int l = 0; l < KSL; l++)
        s += __half2float(base[(size_t)l * DD]);
    g_ksp[(bh * KSC + ch) * DH + i] = s;
}

__global__ void ksum_reduce_k() {
    int idx = blockIdx.x * 256 + threadIdx.x;
    int bh = idx >> 7;
    int i = idx & 127;
    float s = 0.f;
#pragma unroll
    for (int c = 0; c < KSC; c++)
        s += g_ksp[(bh * KSC + c) * DH + i];
    g_ks[idx] = s;
}

__global__ void __launch_bounds__(256) z_k() {
    __shared__ float sk[BB * HH * DH];
    for (int i = threadIdx.x; i < BB * HH * DH; i += 256) sk[i] = g_ks[i];
    __syncthreads();
    const int wi = threadIdx.x >> 5, lane = threadIdx.x & 31;
    const int idx = blockIdx.x * 8 + wi;
    const int n = idx >> 3, h = idx & 7;
    const int b = n >> 13;
    const __half* qp = g_feat_f + (size_t)n * DD + h * DH + lane * 4;
    const float* kp = sk + (b * HH + h) * DH + lane * 4;
    __half2 f0 = *(const __half2*)qp;
    __half2 f1 = *(const __half2*)(qp + 2);
    float dot = __half2float(f0.x) * kp[0] + __half2float(f0.y) * kp[1] +
                __half2float(f1.x) * kp[2] + __half2float(f1.y) * kp[3];
#pragma unroll
    for (int o = 16; o > 0; o >>= 1) dot += __shfl_xor_sync(0xffffffffu, dot, o);
    if (lane == 0) g_z[idx] = 1.0f / (dot + ATTN_EPS);
}

// ---------------------------------------------------------------------------
// LayerNorm + residual: out[n,:] = base[n,:] + LN(t_f16[n,:])*g + bias
// ---------------------------------------------------------------------------
__device__ __forceinline__ float warpReduceSum(float v) {
#pragma unroll
    for (int o = 16; o > 0; o >>= 1) v += __shfl_xor_sync(0xffffffffu, v, o);
    return v;
}

__global__ void __launch_bounds__(256) ln_k(const __half* __restrict__ t,
                                            const float* __restrict__ base,
                                            const float* __restrict__ gam,
                                            const float* __restrict__ bet,
                                            float* __restrict__ out) {
    const int n = blockIdx.x;
    __shared__ float row[DD];
    __shared__ float rs[8], rs2[8];
    __shared__ float smu, srstd;
    const __half* tp = t + (size_t)n * DD;
    float s = 0.f, s2 = 0.f;
    for (int d = threadIdx.x * 2; d < DD; d += 512) {
        __half2 hv = *(const __half2*)(tp + d);
        float v0 = __half2float(hv.x), v1 = __half2float(hv.y);
        row[d] = v0;
        row[d + 1] = v1;
        s += v0 + v1;
        s2 = fmaf(v0, v0, fmaf(v1, v1, s2));
    }
    s = warpReduceSum(s);
    s2 = warpReduceSum(s2);
    int lane = threadIdx.x & 31, wid = threadIdx.x >> 5;
    if (lane == 0) { rs[wid] = s; rs2[wid] = s2; }
    __syncthreads();
    if (threadIdx.x < 32) {
        float a = (threadIdx.x < 8) ? rs[threadIdx.x] : 0.f;
        float b2 = (threadIdx.x < 8) ? rs2[threadIdx.x] : 0.f;
        a = warpReduceSum(a);
        b2 = warpReduceSum(b2);
        if (threadIdx.x == 0) {
            float mu = a * (1.0f / DD);
            float var = b2 * (1.0f / DD) - mu * mu;
            smu = mu;
            srstd = rsqrtf(var + LN_EPS);
        }
    }
    __syncthreads();
    float mu = smu, rstd = srstd;
    const float* bp = base + (size_t)n * DD;
    float* op = out + (size_t)n * DD;
    for (int d = threadIdx.x; d < DD; d += 256)
        op[d] = bp[d] + (row[d] - mu) * rstd * gam[d] + bet[d];
}

// ---------------------------------------------------------------------------
extern "C" void kernel_launch(void* const* d_in, const int* in_sizes, int n_in,
                              void* d_out, int out_size) {
    (void)in_sizes; (void)n_in; (void)out_size;
    const float* x  = (const float*)d_in[0];
    const float* Wq = (const float*)d_in[1];
    const float* Wm = (const float*)d_in[2];
    const float* W1 = (const float*)d_in[3];
    const float* W2 = (const float*)d_in[4];
    const float* g1 = (const float*)d_in[5];
    const float* b1 = (const float*)d_in[6];
    const float* g2 = (const float*)d_in[7];
    const float* b2 = (const float*)d_in[8];
    float* out = (float*)d_out;

    __half *x_h, *feat_f, *v_f, *msg_f, *tmp_f, *h1_f;
    __half *wq_h, *wm_h, *w1_h, *w2_h;
    cudaGetSymbolAddress((void**)&x_h,    g_x_h);
    cudaGetSymbolAddress((void**)&feat_f, g_feat_f);
    cudaGetSymbolAddress((void**)&v_f,    g_v_f);
    cudaGetSymbolAddress((void**)&msg_f,  g_msg_f);
    cudaGetSymbolAddress((void**)&tmp_f,  g_tmp_f);
    cudaGetSymbolAddress((void**)&h1_f,   g_h1_f);
    cudaGetSymbolAddress((void**)&wq_h,   g_wq_h);
    cudaGetSymbolAddress((void**)&wm_h,   g_wm_h);
    cudaGetSymbolAddress((void**)&w1_h,   g_w1_h);
    cudaGetSymbolAddress((void**)&w2_h,   g_w2_h);

    const int SMM = 2 * MTILE;       // 69632 B (msg)
    cudaFuncSetAttribute(hgemm_k<1>, cudaFuncAttributeMaxDynamicSharedMemorySize, GSMEM);
    cudaFuncSetAttribute(hgemm_k<2>, cudaFuncAttributeMaxDynamicSharedMemorySize, GSMEM);
    cudaFuncSetAttribute(hgemm_k<3>, cudaFuncAttributeMaxDynamicSharedMemorySize, GSMEM);
    cudaFuncSetAttribute(msg_mma_k, cudaFuncAttributeMaxDynamicSharedMemorySize, SMM);

    // 0. Convert inputs
    cvt_k<<<(NROW * DD + 255) / 256, 256>>>(x, x_h, NROW * DD);
    wtrans_k<<<dim3(DD / 32, DD / 32), dim3(32, 8)>>>(Wq, wq_h, DD, DD);
    wtrans_k<<<dim3(DFF / 32, DD / 32), dim3(32, 8)>>>(W1, w1_h, DD, DFF);
    wtrans_k<<<dim3(DD / 32, DD / 32), dim3(32, 8)>>>(Wm, wm_h, DD, DD);
    wtrans_k<<<dim3(DD / 32, DFF / 32), dim3(32, 8)>>>(W2, w2_h, DFF, DD);

    // 1. q = x @ Wq, epilogue emits feat(q) f16 + q f16
    hgemm_k<3><<<dim3(DD / 128, NROW / 128), 128, GSMEM>>>(
        x_h, wq_h, feat_f, v_f, DD, DD);
    // 2. attention: KV (tensor-core), Ksum, Z
    kv_mma_k<<<dim3(NKCH, BB * HH), 128>>>();
    kv_reduce_k<<<BB * HH * DH * DH / 256, 256>>>();
    ksum_part_k<<<dim3(KSC, BB * HH), 128>>>();
    ksum_reduce_k<<<BB * HH * DH / 256, 256>>>();
    z_k<<<NROW * HH / 8, 256>>>();
    // 3. msg (tensor-core, Z-scaled f16 out)
    msg_mma_k<<<dim3(LL / 128, BB * HH), 128, SMM>>>();
    // 4. tmp_f = msg @ Wm (f16) -- the rebinded "msg"
    hgemm_k<1><<<dim3(DD / 128, NROW / 128), 128, GSMEM>>>(
        msg_f, wm_h, tmp_f, nullptr, DD, DD);
    // 5. out = x + LN(tmp_f)
    ln_k<<<NROW, 256>>>(tmp_f, x, g1, b1, out);
    // 6. h1 = relu(tmp_f @ W1) (f16)
    hgemm_k<2><<<dim3(DFF / 128, NROW / 128), 128, GSMEM>>>(
        tmp_f, w1_h, h1_f, nullptr, DFF, DD);
    // 7. mlp = h1 @ W2 (f16, reuse msg_f buffer)
    hgemm_k<1><<<dim3(DD / 128, NROW / 128), 128, GSMEM>>>(
        h1_f, w2_h, msg_f, nullptr, DD, DFF);
    // 8. out += LN(mlp)
    ln_k<<<NROW, 256>>>(msg_f, out, g2, b2, out);
}

// round 15
// speedup vs baseline: 2.5380x; 1.0374x over previous
#include <cuda_runtime.h>
#include <cuda_fp16.h>
#include <math.h>
#include <stdint.h>

// Problem constants
#define BB   2
#define LL   8192
#define DD   1024
#define HH   8
#define DH   128
#define NROW (BB*LL)     // 16384
#define DFF  (2*DD)      // 2048
#define NKCH 16          // kv chunk count
#define KCHL (LL/NKCH)   // 512 l-rows per kv chunk
#define ATTN_EPS 1e-6f
#define LN_EPS   1e-5f

// ---------------------------------------------------------------------------
// Scratch (device globals: allocation-free per harness rules)
// ---------------------------------------------------------------------------
__device__ float g_kvp[BB*HH*NKCH*DH*DH];       // KV partials per L-chunk (fp32)
__device__ float g_ksp[BB*HH*NKCH*DH];          // Ksum partials (from kv_mma)
__device__ float g_ks[BB*HH*DH];                // Ksum

// f16 operands
__device__ __half g_x_h[NROW*DD];
__device__ __half g_feat_f[NROW*DD];            // feat(q) = elu(q)+1, f16
__device__ __half g_v_f[NROW*DD];               // q (value, unscaled), f16
__device__ __half g_kvt[BB*HH*DH*DH];           // KV^T [bh][v][d] f16
__device__ __half g_msg_f[NROW*DD];             // attention msg, then reused: mlp out
__device__ __half g_tmp_f[NROW*DD];             // msg@Wm f16 (LN1 input + W1 input)
__device__ __half g_h1_f[NROW*DFF];
// transposed weights [N, K] K-major, f16
__device__ __half g_wq_h[DD*DD];
__device__ __half g_wm_h[DD*DD];
__device__ __half g_w1_h[DFF*DD];
__device__ __half g_w2_h[DD*DFF];

// ---------------------------------------------------------------------------
// Helpers
// ---------------------------------------------------------------------------
__device__ __forceinline__ uint32_t smem_u32(const void* p) {
    uint32_t a;
    asm("{ .reg .u64 t; cvta.to.shared.u64 t, %1; cvt.u32.u64 %0, t; }" : "=r"(a) : "l"(p));
    return a;
}

__device__ __forceinline__ float featf(float v) {
    return v > 0.f ? v + 1.f : expf(v);
}

#define LDSM4(r0, r1, r2, r3, addr) \
    asm volatile("ldmatrix.sync.aligned.m8n8.x4.shared.b16 {%0,%1,%2,%3}, [%4];" \
                 : "=r"(r0), "=r"(r1), "=r"(r2), "=r"(r3) : "r"(addr))
#define LDSM4T(r0, r1, r2, r3, addr) \
    asm volatile("ldmatrix.sync.aligned.m8n8.x4.trans.shared.b16 {%0,%1,%2,%3}, [%4];" \
                 : "=r"(r0), "=r"(r1), "=r"(r2), "=r"(r3) : "r"(addr))

#define CP16(dst, src) \
    asm volatile("cp.async.cg.shared.global [%0], [%1], 16;" :: "r"(dst), "l"(src))
#define CP_COMMIT() asm volatile("cp.async.commit_group;" ::: "memory")
#define CP_WAIT1()  asm volatile("cp.async.wait_group 1;" ::: "memory")
#define CP_WAIT0()  asm volatile("cp.async.wait_group 0;" ::: "memory")

__device__ __forceinline__ void mma16816(float* c, const uint32_t* a,
                                         uint32_t b0, uint32_t b1) {
    asm volatile("mma.sync.aligned.m16n8k16.row.col.f32.f16.f16.f32 "
                 "{%0,%1,%2,%3}, {%4,%5,%6,%7}, {%8,%9}, {%0,%1,%2,%3};"
                 : "+f"(c[0]), "+f"(c[1]), "+f"(c[2]), "+f"(c[3])
                 : "r"(a[0]), "r"(a[1]), "r"(a[2]), "r"(a[3]), "r"(b0), "r"(b1));
}

// ---------------------------------------------------------------------------
// HMMA GEMM: C = A @ B^T, B stored [N,K] K-major, f16 in / fp32 acc / f16 out.
// Block tile 128x128, K-chunk 64, 4 warps (2x2), warp tile 64x64, cp.async 2-stage.
// EPI: 1 = f16 Cf; 2 = relu then f16 Cf; 3 = f16 feat(C)->Cf and f16 C->Cf2.
// ---------------------------------------------------------------------------
#define SROW  144
#define GTILE (128 * SROW)       // 18432 B
#define GSTG  (2 * GTILE)        // A, B = 36864 B
#define GSMEM (2 * GSTG)         // 73728 B, two stages

template <int EPI>
__global__ void __launch_bounds__(128, 2)
hgemm_k(const __half* __restrict__ Ah, const __half* __restrict__ Bh,
        __half* __restrict__ Cf, __half* __restrict__ Cf2, int Nn, int K) {
    extern __shared__ __align__(16) char smem[];
    const uint32_t sb = smem_u32(smem);
    const int tid = threadIdx.x, warp = tid >> 5, lane = tid & 31;
    const int wm = warp >> 1, wn = warp & 1;
    const int m0 = blockIdx.y * 128, n0 = blockIdx.x * 128;

    float acc[4][8][4] = {};

    const uint32_t aoff = (uint32_t)(wm * 64 + (lane & 15)) * SROW + ((lane >> 4) << 4);
    const int nloc = (lane & 7) + ((lane >> 4) << 3);
    const uint32_t boff = (uint32_t)(wn * 64 + nloc) * SROW + (((lane >> 3) & 1) << 4);

    auto load_stage = [&](int s, int kc) {
        const uint32_t base = sb + (uint32_t)s * GSTG;
#pragma unroll
        for (int i = 0; i < 8; i++) {
            const int lin = i * 128 + tid;
            const int r = lin >> 3, seg = lin & 7;
            const uint32_t so = (uint32_t)r * SROW + seg * 16;
            CP16(base + so, Ah + (size_t)(m0 + r) * K + kc + seg * 8);
            CP16(base + GTILE + so, Bh + (size_t)(n0 + r) * K + kc + seg * 8);
        }
    };

    const int nch = K / 64;
    load_stage(0, 0);
    CP_COMMIT();

    for (int c = 0; c < nch; c++) {
        if (c + 1 < nch) {
            load_stage((c + 1) & 1, (c + 1) * 64);
            CP_COMMIT();
            CP_WAIT1();
        } else {
            CP_WAIT0();
        }
        __syncthreads();
        const uint32_t base = sb + (uint32_t)(c & 1) * GSTG;
#pragma unroll
        for (int ks = 0; ks < 4; ks++) {
            const uint32_t kso = (uint32_t)ks * 32;
            uint32_t ah[4][4], bh[4][4];
#pragma unroll
            for (int mt = 0; mt < 4; mt++)
                LDSM4(ah[mt][0], ah[mt][1], ah[mt][2], ah[mt][3],
                      base + aoff + (uint32_t)mt * 16 * SROW + kso);
#pragma unroll
            for (int p = 0; p < 4; p++)
                LDSM4(bh[p][0], bh[p][1], bh[p][2], bh[p][3],
                      base + GTILE + boff + (uint32_t)p * 16 * SROW + kso);
#pragma unroll
            for (int mt = 0; mt < 4; mt++)
#pragma unroll
                for (int p = 0; p < 4; p++) {
                    mma16816(acc[mt][p * 2 + 0], ah[mt], bh[p][0], bh[p][1]);
                    mma16816(acc[mt][p * 2 + 1], ah[mt], bh[p][2], bh[p][3]);
                }
        }
        __syncthreads();
    }

    const int gid = lane >> 2, t4 = lane & 3;
#pragma unroll
    for (int mt = 0; mt < 4; mt++) {
#pragma unroll
        for (int nt = 0; nt < 8; nt++) {
            const float* c = acc[mt][nt];
            const int r0 = m0 + wm * 64 + mt * 16 + gid;
            const int cc = n0 + wn * 64 + nt * 8 + t4 * 2;
#pragma unroll
            for (int half_ = 0; half_ < 2; half_++) {
                const int r = r0 + half_ * 8;
                float v0 = c[half_ * 2 + 0], v1 = c[half_ * 2 + 1];
                if (EPI == 1 || EPI == 2) {
                    if (EPI == 2) { v0 = fmaxf(v0, 0.f); v1 = fmaxf(v1, 0.f); }
                    __half2 hh;
                    hh.x = __float2half(v0);
                    hh.y = __float2half(v1);
                    *(__half2*)(Cf + (size_t)r * Nn + cc) = hh;
                }
                if (EPI == 3) {
                    __half2 fh, vh;
                    fh.x = __float2half(featf(v0));
                    fh.y = __float2half(featf(v1));
                    vh.x = __float2half(v0);
                    vh.y = __float2half(v1);
                    *(__half2*)(Cf  + (size_t)r * Nn + cc) = fh;
                    *(__half2*)(Cf2 + (size_t)r * Nn + cc) = vh;
                }
            }
        }
    }
}

// ---------------------------------------------------------------------------
// KV MMA + fused Ksum partial:
// per (chunk, bh): KVp[d,v] = sum_{l in chunk} F[l,d] * V[l,v]
//                  KSp[d]   = sum_{l in chunk} F[l,d]   (thread d sums smem col d)
// ---------------------------------------------------------------------------
#define TROW 272                 // 128 f16 + 8 pad = 272 bytes/row
#define TTILE (32 * TROW)        // 8704 B

__global__ void __launch_bounds__(128, 2) kv_mma_k() {
    __shared__ __align__(16) char smem[4 * TTILE];   // 2 stages x (F, V)
    const uint32_t sb = smem_u32(smem);
    const int ch = blockIdx.x, bh = blockIdx.y;
    const int b = bh >> 3, h = bh & 7;
    const int tid = threadIdx.x, warp = tid >> 5, lane = tid & 31;
    const int wm = warp >> 1, wn = warp & 1;
    float acc[4][8][4] = {};
    float ks_acc = 0.f;          // column tid of F, summed over all l in chunk

    const uint32_t aoff = (uint32_t)((lane >> 4) * 8 + (lane & 7)) * TROW
                        + (uint32_t)(wm * 64 + ((lane >> 3) & 1) * 8) * 2;
    const uint32_t boff = (uint32_t)(((lane >> 3) & 1) * 8 + (lane & 7)) * TROW
                        + (uint32_t)(wn * 64 + (lane >> 4) * 8) * 2;

    auto load_stage = [&](int st, int l0) {
        const uint32_t base = sb + (uint32_t)st * 2 * TTILE;
#pragma unroll
        for (int i = 0; i < 4; i++) {
            const int lin = i * 128 + tid;
            const int row = lin >> 4, seg = lin & 15;
            const uint32_t so = (uint32_t)row * TROW + seg * 16;
            const size_t g = (size_t)(b * LL + l0 + row) * DD + h * DH + seg * 8;
            CP16(base + so, g_feat_f + g);
            CP16(base + TTILE + so, g_v_f + g);
        }
    };

    const int lbase = ch * KCHL;
    load_stage(0, lbase);
    CP_COMMIT();

    for (int c = 0; c < KCHL / 32; c++) {
        if (c + 1 < KCHL / 32) {
            load_stage((c + 1) & 1, lbase + (c + 1) * 32);
            CP_COMMIT();
            CP_WAIT1();
        } else {
            CP_WAIT0();
        }
        __syncthreads();
        const uint32_t base = sb + (uint32_t)(c & 1) * 2 * TTILE;
#pragma unroll
        for (int ks = 0; ks < 2; ks++) {
            const uint32_t kro = (uint32_t)ks * 16 * TROW;
            uint32_t a[4][4], bb[4][4];
#pragma unroll
            for (int mt = 0; mt < 4; mt++)
                LDSM4T(a[mt][0], a[mt][1], a[mt][2], a[mt][3],
                       base + kro + aoff + (uint32_t)mt * 32);
#pragma unroll
            for (int p = 0; p < 4; p++)
                LDSM4T(bb[p][0], bb[p][1], bb[p][2], bb[p][3],
                       base + TTILE + kro + boff + (uint32_t)p * 32);
#pragma unroll
            for (int mt = 0; mt < 4; mt++)
#pragma unroll
                for (int p = 0; p < 4; p++) {
                    mma16816(acc[mt][p * 2 + 0], a[mt], bb[p][0], bb[p][1]);
                    mma16816(acc[mt][p * 2 + 1], a[mt], bb[p][2], bb[p][3]);
                }
        }
        // fused Ksum partial: thread tid sums F smem column tid (32 rows)
        {
            const char* fbase = smem + (size_t)(c & 1) * 2 * TTILE + tid * 2;
#pragma unroll 8
            for (int r = 0; r < 32; r++)
                ks_acc += __half2float(*(const __half*)(fbase + r * TROW));
        }
        __syncthreads();
    }

    g_ksp[(bh * NKCH + ch) * DH + tid] = ks_acc;

    const int gid = lane >> 2, t4 = lane & 3;
    float* outp = g_kvp + ((size_t)bh * NKCH + ch) * (DH * DH);
#pragma unroll
    for (int mt = 0; mt < 4; mt++)
#pragma unroll
        for (int nt = 0; nt < 8; nt++) {
            const float* c = acc[mt][nt];
            const int d0 = wm * 64 + mt * 16 + gid;
            const int vv = wn * 64 + nt * 8 + t4 * 2;
#pragma unroll
            for (int half_ = 0; half_ < 2; half_++) {
                float2 f;
                f.x = c[half_ * 2 + 0];
                f.y = c[half_ * 2 + 1];
                *(float2*)(outp + (d0 + half_ * 8) * DH + vv) = f;
            }
        }
}

// Reduce KV partials -> KV^T f16 [bh][v][d]
__global__ void kv_reduce_k() {
    int o = blockIdx.x * 256 + threadIdx.x;    // BB*HH*16384
    int bh = o >> 14;
    int e = o & 16383;
    int v = e >> 7, d = e & 127;
    float s = 0.f;
    const float* p = g_kvp + (size_t)bh * NKCH * (DH * DH) + d * DH + v;
#pragma unroll
    for (int c = 0; c < NKCH; c++)
        s += p[(size_t)c * (DH * DH)];
    g_kvt[o] = __float2half(s);
}

// Reduce ksum partials (16 per bh)
__global__ void ksum_reduce_k() {
    int idx = blockIdx.x * 256 + threadIdx.x;   // BB*HH*DH = 2048
    int bh = idx >> 7;
    int i = idx & 127;
    float s = 0.f;
#pragma unroll
    for (int c = 0; c < NKCH; c++)
        s += g_ksp[(bh * NKCH + c) * DH + i];
    g_ks[idx] = s;
}

// ---------------------------------------------------------------------------
// msg MMA + fused Z: per (lblock, bh):
//   z[r] = 1/(F[r,:]·Ksum + eps)  computed from staged smem F
//   msg[l, v] = (sum_d F[l,d] * KVT[v,d]) * z
// ---------------------------------------------------------------------------
#define MTILE (128 * TROW)       // 34816 B per array

__global__ void __launch_bounds__(128, 2) msg_mma_k() {
    extern __shared__ __align__(16) char smem[];
    __shared__ float sks[DH];
    __shared__ float sz[128];
    const uint32_t sb = smem_u32(smem);
    const int lb = blockIdx.x, bh = blockIdx.y;
    const int b = bh >> 3, h = bh & 7;
    const int l0 = lb * 128;
    const int tid = threadIdx.x, warp = tid >> 5, lane = tid & 31;
    const int wm = warp >> 1, wn = warp & 1;
    float acc[4][8][4] = {};

    const uint32_t aoff = (uint32_t)(wm * 64 + (lane & 15)) * TROW + ((lane >> 4) << 4);
    const int nloc = (lane & 7) + ((lane >> 4) << 3);
    const uint32_t boff = (uint32_t)(wn * 64 + nloc) * TROW + (((lane >> 3) & 1) << 4);

#pragma unroll
    for (int i = 0; i < 16; i++) {
        const int lin = i * 128 + tid;
        const int row = lin >> 4, seg = lin & 15;
        const uint32_t so = (uint32_t)row * TROW + seg * 16;
        CP16(sb + so, g_feat_f + (size_t)(b * LL + l0 + row) * DD + h * DH + seg * 8);
        CP16(sb + MTILE + so, g_kvt + (size_t)bh * (DH * DH) + row * DH + seg * 8);
    }
    sks[tid] = g_ks[bh * DH + tid];
    CP_COMMIT();
    CP_WAIT0();
    __syncthreads();

    // fused Z: thread tid dots F row tid with Ksum
    {
        const char* frow = smem + (size_t)tid * TROW;
        float dot = 0.f;
#pragma unroll
        for (int j = 0; j < DH; j += 2) {
            __half2 hv = *(const __half2*)(frow + j * 2);
            dot += __half2float(hv.x) * sks[j] + __half2float(hv.y) * sks[j + 1];
        }
        sz[tid] = 1.0f / (dot + ATTN_EPS);
    }

#pragma unroll
    for (int ks = 0; ks < 8; ks++) {
        const uint32_t kso = (uint32_t)ks * 32;
        uint32_t a[4][4], bb[4][4];
#pragma unroll
        for (int mt = 0; mt < 4; mt++)
            LDSM4(a[mt][0], a[mt][1], a[mt][2], a[mt][3],
                  sb + aoff + (uint32_t)mt * 16 * TROW + kso);
#pragma unroll
        for (int p = 0; p < 4; p++)
            LDSM4(bb[p][0], bb[p][1], bb[p][2], bb[p][3],
                  sb + MTILE + boff + (uint32_t)p * 16 * TROW + kso);
#pragma unroll
        for (int mt = 0; mt < 4; mt++)
#pragma unroll
            for (int p = 0; p < 4; p++) {
                mma16816(acc[mt][p * 2 + 0], a[mt], bb[p][0], bb[p][1]);
                mma16816(acc[mt][p * 2 + 1], a[mt], bb[p][2], bb[p][3]);
            }
    }
    __syncthreads();   // sz complete before epilogue reads

    const int gid = lane >> 2, t4 = lane & 3;
#pragma unroll
    for (int mt = 0; mt < 4; mt++)
#pragma unroll
        for (int nt = 0; nt < 8; nt++) {
            const float* c = acc[mt][nt];
            const int lr = wm * 64 + mt * 16 + gid;
            const int cc = wn * 64 + nt * 8 + t4 * 2;
#pragma unroll
            for (int half_ = 0; half_ < 2; half_++) {
                const int lloc = lr + half_ * 8;
                const int n = b * LL + l0 + lloc;
                const float z = sz[lloc];
                __half2 hh;
                hh.x = __float2half(c[half_ * 2 + 0] * z);
                hh.y = __float2half(c[half_ * 2 + 1] * z);
                *(__half2*)(g_msg_f + (size_t)n * DD + h * DH + cc) = hh;
            }
        }
}

// ---------------------------------------------------------------------------
// Conversion kernels
// ---------------------------------------------------------------------------
__global__ void cvt_k(const float* __restrict__ in, __half* __restrict__ o, int n) {
    int i = blockIdx.x * 256 + threadIdx.x;
    if (i < n) o[i] = __float2half(in[i]);
}

__global__ void wtrans_k(const float* __restrict__ W, __half* __restrict__ T,
                         int K, int N) {
    __shared__ float t[32][33];
    const int k0 = blockIdx.y * 32, n0 = blockIdx.x * 32;
    const int tx = threadIdx.x, ty = threadIdx.y;
#pragma unroll
    for (int i = 0; i < 4; i++)
        t[ty + i * 8][tx] = W[(size_t)(k0 + ty + i * 8) * N + n0 + tx];
    __syncthreads();
#pragma unroll
    for (int i = 0; i < 4; i++)
        T[(size_t)(n0 + ty + i * 8) * K + k0 + tx] = __float2half(t[tx][ty + i * 8]);
}

// ---------------------------------------------------------------------------
// LayerNorm + residual: out[n,:] = base[n,:] + LN(t_f16[n,:])*g + bias
// ---------------------------------------------------------------------------
__device__ __forceinline__ float warpReduceSum(float v) {
#pragma unroll
    for (int o = 16; o > 0; o >>= 1) v += __shfl_xor_sync(0xffffffffu, v, o);
    return v;
}

__global__ void __launch_bounds__(256) ln_k(const __half* __restrict__ t,
                                            const float* __restrict__ base,
                                            const float* __restrict__ gam,
                                            const float* __restrict__ bet,
                                            float* __restrict__ out) {
    const int n = blockIdx.x;
    __shared__ float row[DD];
    __shared__ float rs[8], rs2[8];
    __shared__ float smu, srstd;
    const __half* tp = t + (size_t)n * DD;
    float s = 0.f, s2 = 0.f;
    for (int d = threadIdx.x * 2; d < DD; d += 512) {
        __half2 hv = *(const __half2*)(tp + d);
        float v0 = __half2float(hv.x), v1 = __half2float(hv.y);
        row[d] = v0;
        row[d + 1] = v1;
        s += v0 + v1;
        s2 = fmaf(v0, v0, fmaf(v1, v1, s2));
    }
    s = warpReduceSum(s);
    s2 = warpReduceSum(s2);
    int lane = threadIdx.x & 31, wid = threadIdx.x >> 5;
    if (lane == 0) { rs[wid] = s; rs2[wid] = s2; }
    __syncthreads();
    if (threadIdx.x < 32) {
        float a = (threadIdx.x < 8) ? rs[threadIdx.x] : 0.f;
        float b2 = (threadIdx.x < 8) ? rs2[threadIdx.x] : 0.f;
        a = warpReduceSum(a);
        b2 = warpReduceSum(b2);
        if (threadIdx.x == 0) {
            float mu = a * (1.0f / DD);
            float var = b2 * (1.0f / DD) - mu * mu;
            smu = mu;
            srstd = rsqrtf(var + LN_EPS);
        }
    }
    __syncthreads();
    float mu = smu, rstd = srstd;
    const float* bp = base + (size_t)n * DD;
    float* op = out + (size_t)n * DD;
    for (int d = threadIdx.x; d < DD; d += 256)
        op[d] = bp[d] + (row[d] - mu) * rstd * gam[d] + bet[d];
}

// ---------------------------------------------------------------------------
extern "C" void kernel_launch(void* const* d_in, const int* in_sizes, int n_in,
                              void* d_out, int out_size) {
    (void)in_sizes; (void)n_in; (void)out_size;
    const float* x  = (const float*)d_in[0];
    const float* Wq = (const float*)d_in[1];
    const float* Wm = (const float*)d_in[2];
    const float* W1 = (const float*)d_in[3];
    const float* W2 = (const float*)d_in[4];
    const float* g1 = (const float*)d_in[5];
    const float* b1 = (const float*)d_in[6];
    const float* g2 = (const float*)d_in[7];
    const float* b2 = (const float*)d_in[8];
    float* out = (float*)d_out;

    __half *x_h, *feat_f, *v_f, *msg_f, *tmp_f, *h1_f;
    __half *wq_h, *wm_h, *w1_h, *w2_h;
    cudaGetSymbolAddress((void**)&x_h,    g_x_h);
    cudaGetSymbolAddress((void**)&feat_f, g_feat_f);
    cudaGetSymbolAddress((void**)&v_f,    g_v_f);
    cudaGetSymbolAddress((void**)&msg_f,  g_msg_f);
    cudaGetSymbolAddress((void**)&tmp_f,  g_tmp_f);
    cudaGetSymbolAddress((void**)&h1_f,   g_h1_f);
    cudaGetSymbolAddress((void**)&wq_h,   g_wq_h);
    cudaGetSymbolAddress((void**)&wm_h,   g_wm_h);
    cudaGetSymbolAddress((void**)&w1_h,   g_w1_h);
    cudaGetSymbolAddress((void**)&w2_h,   g_w2_h);

    const int SMM = 2 * MTILE;       // 69632 B (msg, dynamic; +static sks/sz)
    cudaFuncSetAttribute(hgemm_k<1>, cudaFuncAttributeMaxDynamicSharedMemorySize, GSMEM);
    cudaFuncSetAttribute(hgemm_k<2>, cudaFuncAttributeMaxDynamicSharedMemorySize, GSMEM);
    cudaFuncSetAttribute(hgemm_k<3>, cudaFuncAttributeMaxDynamicSharedMemorySize, GSMEM);
    cudaFuncSetAttribute(msg_mma_k, cudaFuncAttributeMaxDynamicSharedMemorySize, SMM);

    // 0. Convert inputs
    cvt_k<<<(NROW * DD + 255) / 256, 256>>>(x, x_h, NROW * DD);
    wtrans_k<<<dim3(DD / 32, DD / 32), dim3(32, 8)>>>(Wq, wq_h, DD, DD);
    wtrans_k<<<dim3(DFF / 32, DD / 32), dim3(32, 8)>>>(W1, w1_h, DD, DFF);
    wtrans_k<<<dim3(DD / 32, DD / 32), dim3(32, 8)>>>(Wm, wm_h, DD, DD);
    wtrans_k<<<dim3(DD / 32, DFF / 32), dim3(32, 8)>>>(W2, w2_h, DFF, DD);

    // 1. q = x @ Wq, epilogue emits feat(q) f16 + q f16
    hgemm_k<3><<<dim3(DD / 128, NROW / 128), 128, GSMEM>>>(
        x_h, wq_h, feat_f, v_f, DD, DD);
    // 2. attention: KV MMA (fused ksum partials), reductions
    kv_mma_k<<<dim3(NKCH, BB * HH), 128>>>();
    kv_reduce_k<<<BB * HH * DH * DH / 256, 256>>>();
    ksum_reduce_k<<<BB * HH * DH / 256, 256>>>();
    // 3. msg (tensor-core, fused Z, f16 out)
    msg_mma_k<<<dim3(LL / 128, BB * HH), 128, SMM>>>();
    // 4. tmp_f = msg @ Wm (f16) -- the rebinded "msg"
    hgemm_k<1><<<dim3(DD / 128, NROW / 128), 128, GSMEM>>>(
        msg_f, wm_h, tmp_f, nullptr, DD, DD);
    // 5. out = x + LN(tmp_f)
    ln_k<<<NROW, 256>>>(tmp_f, x, g1, b1, out);
    // 6. h1 = relu(tmp_f @ W1) (f16)
    hgemm_k<2><<<dim3(DFF / 128, NROW / 128), 128, GSMEM>>>(
        tmp_f, w1_h, h1_f, nullptr, DFF, DD);
    // 7. mlp = h1 @ W2 (f16, reuse msg_f buffer)
    hgemm_k<1><<<dim3(DD / 128, NROW / 128), 128, GSMEM>>>(
        h1_f, w2_h, msg_f, nullptr, DD, DFF);
    // 8. out += LN(mlp)
    ln_k<<<NROW, 256>>>(msg_f, out, g2, b2, out);
}

// round 16
// speedup vs baseline: 2.5394x; 1.0005x over previous
#include <cuda_runtime.h>
#include <cuda_fp16.h>
#include <math.h>
#include <stdint.h>

// Problem constants
#define BB   2
#define LL   8192
#define DD   1024
#define HH   8
#define DH   128
#define NROW (BB*LL)     // 16384
#define DFF  (2*DD)      // 2048
#define NKCH 16          // kv chunk count
#define KCHL (LL/NKCH)   // 512 l-rows per kv chunk
#define ATTN_EPS 1e-6f
#define LN_EPS   1e-5f

// ---------------------------------------------------------------------------
// Scratch (device globals: allocation-free per harness rules)
// ---------------------------------------------------------------------------
__device__ float g_kvp[BB*HH*NKCH*DH*DH];       // KV partials per L-chunk (fp32)
__device__ float g_ksp[BB*HH*NKCH*DH];          // Ksum partials (from kv_mma)
__device__ float g_ks[BB*HH*DH];                // Ksum

// f16 operands
__device__ __half g_x_h[NROW*DD];
__device__ __half g_feat_f[NROW*DD];            // feat(q) = elu(q)+1, f16
__device__ __half g_v_f[NROW*DD];               // q (value, unscaled), f16
__device__ __half g_kvt[BB*HH*DH*DH];           // KV^T [bh][v][d] f16
__device__ __half g_msg_f[NROW*DD];             // attention msg, then reused: mlp out
__device__ __half g_tmp_f[NROW*DD];             // msg@Wm f16 (LN1 input + W1 input)
__device__ __half g_h1_f[NROW*DFF];
// transposed weights [N, K] K-major, f16
__device__ __half g_wq_h[DD*DD];
__device__ __half g_wm_h[DD*DD];
__device__ __half g_w1_h[DFF*DD];
__device__ __half g_w2_h[DD*DFF];

// ---------------------------------------------------------------------------
// Helpers
// ---------------------------------------------------------------------------
__device__ __forceinline__ uint32_t smem_u32(const void* p) {
    uint32_t a;
    asm("{ .reg .u64 t; cvta.to.shared.u64 t, %1; cvt.u32.u64 %0, t; }" : "=r"(a) : "l"(p));
    return a;
}

__device__ __forceinline__ float featf(float v) {
    return v > 0.f ? v + 1.f : expf(v);
}

#define LDSM4(r0, r1, r2, r3, addr) \
    asm volatile("ldmatrix.sync.aligned.m8n8.x4.shared.b16 {%0,%1,%2,%3}, [%4];" \
                 : "=r"(r0), "=r"(r1), "=r"(r2), "=r"(r3) : "r"(addr))
#define LDSM4T(r0, r1, r2, r3, addr) \
    asm volatile("ldmatrix.sync.aligned.m8n8.x4.trans.shared.b16 {%0,%1,%2,%3}, [%4];" \
                 : "=r"(r0), "=r"(r1), "=r"(r2), "=r"(r3) : "r"(addr))

#define CP16(dst, src) \
    asm volatile("cp.async.cg.shared.global [%0], [%1], 16;" :: "r"(dst), "l"(src))
#define CP_COMMIT() asm volatile("cp.async.commit_group;" ::: "memory")
#define CP_WAIT2()  asm volatile("cp.async.wait_group 2;" ::: "memory")
#define CP_WAIT1()  asm volatile("cp.async.wait_group 1;" ::: "memory")
#define CP_WAIT0()  asm volatile("cp.async.wait_group 0;" ::: "memory")

__device__ __forceinline__ void mma16816(float* c, const uint32_t* a,
                                         uint32_t b0, uint32_t b1) {
    asm volatile("mma.sync.aligned.m16n8k16.row.col.f32.f16.f16.f32 "
                 "{%0,%1,%2,%3}, {%4,%5,%6,%7}, {%8,%9}, {%0,%1,%2,%3};"
                 : "+f"(c[0]), "+f"(c[1]), "+f"(c[2]), "+f"(c[3])
                 : "r"(a[0]), "r"(a[1]), "r"(a[2]), "r"(a[3]), "r"(b0), "r"(b1));
}

// ---------------------------------------------------------------------------
// HMMA GEMM: C = A @ B^T, B stored [N,K] K-major, f16 in / fp32 acc / f16 out.
// Block tile 128x128, K-chunk 64, 4 warps (2x2), warp tile 64x64, cp.async 3-stage.
// EPI: 1 = f16 Cf; 2 = relu then f16 Cf; 3 = f16 feat(C)->Cf and f16 C->Cf2.
// ---------------------------------------------------------------------------
#define SROW  144
#define GTILE (128 * SROW)       // 18432 B
#define GSTG  (2 * GTILE)        // A, B = 36864 B
#define GSMEM (3 * GSTG)         // 110592 B, three stages

template <int EPI>
__global__ void __launch_bounds__(128, 2)
hgemm_k(const __half* __restrict__ Ah, const __half* __restrict__ Bh,
        __half* __restrict__ Cf, __half* __restrict__ Cf2, int Nn, int K) {
    extern __shared__ __align__(16) char smem[];
    const uint32_t sb = smem_u32(smem);
    const int tid = threadIdx.x, warp = tid >> 5, lane = tid & 31;
    const int wm = warp >> 1, wn = warp & 1;
    const int m0 = blockIdx.y * 128, n0 = blockIdx.x * 128;

    float acc[4][8][4] = {};

    const uint32_t aoff = (uint32_t)(wm * 64 + (lane & 15)) * SROW + ((lane >> 4) << 4);
    const int nloc = (lane & 7) + ((lane >> 4) << 3);
    const uint32_t boff = (uint32_t)(wn * 64 + nloc) * SROW + (((lane >> 3) & 1) << 4);

    auto load_stage = [&](int s, int kc) {
        const uint32_t base = sb + (uint32_t)s * GSTG;
#pragma unroll
        for (int i = 0; i < 8; i++) {
            const int lin = i * 128 + tid;
            const int r = lin >> 3, seg = lin & 7;
            const uint32_t so = (uint32_t)r * SROW + seg * 16;
            CP16(base + so, Ah + (size_t)(m0 + r) * K + kc + seg * 8);
            CP16(base + GTILE + so, Bh + (size_t)(n0 + r) * K + kc + seg * 8);
        }
    };

    const int nch = K / 64;
    load_stage(0, 0);
    CP_COMMIT();
    if (nch > 1) {
        load_stage(1, 64);
        CP_COMMIT();
    }

    int st = 0, nst = (nch > 2) ? 2 : 0;  // stage of chunk c; next free stage
    for (int c = 0; c < nch; c++) {
        if (c + 2 < nch) {
            load_stage(nst, (c + 2) * 64);
            CP_COMMIT();
            CP_WAIT2();
        } else if (c + 1 < nch) {
            CP_WAIT1();
        } else {
            CP_WAIT0();
        }
        __syncthreads();
        const uint32_t base = sb + (uint32_t)st * GSTG;
#pragma unroll
        for (int ks = 0; ks < 4; ks++) {
            const uint32_t kso = (uint32_t)ks * 32;
            uint32_t ah[4][4], bh[4][4];
#pragma unroll
            for (int mt = 0; mt < 4; mt++)
                LDSM4(ah[mt][0], ah[mt][1], ah[mt][2], ah[mt][3],
                      base + aoff + (uint32_t)mt * 16 * SROW + kso);
#pragma unroll
            for (int p = 0; p < 4; p++)
                LDSM4(bh[p][0], bh[p][1], bh[p][2], bh[p][3],
                      base + GTILE + boff + (uint32_t)p * 16 * SROW + kso);
#pragma unroll
            for (int mt = 0; mt < 4; mt++)
#pragma unroll
                for (int p = 0; p < 4; p++) {
                    mma16816(acc[mt][p * 2 + 0], ah[mt], bh[p][0], bh[p][1]);
                    mma16816(acc[mt][p * 2 + 1], ah[mt], bh[p][2], bh[p][3]);
                }
        }
        __syncthreads();
        st = (st == 2) ? 0 : st + 1;
        nst = (nst == 2) ? 0 : nst + 1;
    }

    const int gid = lane >> 2, t4 = lane & 3;
#pragma unroll
    for (int mt = 0; mt < 4; mt++) {
#pragma unroll
        for (int nt = 0; nt < 8; nt++) {
            const float* c = acc[mt][nt];
            const int r0 = m0 + wm * 64 + mt * 16 + gid;
            const int cc = n0 + wn * 64 + nt * 8 + t4 * 2;
#pragma unroll
            for (int half_ = 0; half_ < 2; half_++) {
                const int r = r0 + half_ * 8;
                float v0 = c[half_ * 2 + 0], v1 = c[half_ * 2 + 1];
                if (EPI == 1 || EPI == 2) {
                    if (EPI == 2) { v0 = fmaxf(v0, 0.f); v1 = fmaxf(v1, 0.f); }
                    __half2 hh;
                    hh.x = __float2half(v0);
                    hh.y = __float2half(v1);
                    *(__half2*)(Cf + (size_t)r * Nn + cc) = hh;
                }
                if (EPI == 3) {
                    __half2 fh, vh;
                    fh.x = __float2half(featf(v0));
                    fh.y = __float2half(featf(v1));
                    vh.x = __float2half(v0);
                    vh.y = __float2half(v1);
                    *(__half2*)(Cf  + (size_t)r * Nn + cc) = fh;
                    *(__half2*)(Cf2 + (size_t)r * Nn + cc) = vh;
                }
            }
        }
    }
}

// ---------------------------------------------------------------------------
// KV MMA + fused Ksum partial:
// per (chunk, bh): KVp[d,v] = sum_{l in chunk} F[l,d] * V[l,v]
//                  KSp[d]   = sum_{l in chunk} F[l,d]   (thread d sums smem col d)
// ---------------------------------------------------------------------------
#define TROW 272                 // 128 f16 + 8 pad = 272 bytes/row
#define TTILE (32 * TROW)        // 8704 B

__global__ void __launch_bounds__(128, 2) kv_mma_k() {
    __shared__ __align__(16) char smem[4 * TTILE];   // 2 stages x (F, V)
    const uint32_t sb = smem_u32(smem);
    const int ch = blockIdx.x, bh = blockIdx.y;
    const int b = bh >> 3, h = bh & 7;
    const int tid = threadIdx.x, warp = tid >> 5, lane = tid & 31;
    const int wm = warp >> 1, wn = warp & 1;
    float acc[4][8][4] = {};
    float ks_acc = 0.f;

    const uint32_t aoff = (uint32_t)((lane >> 4) * 8 + (lane & 7)) * TROW
                        + (uint32_t)(wm * 64 + ((lane >> 3) & 1) * 8) * 2;
    const uint32_t boff = (uint32_t)(((lane >> 3) & 1) * 8 + (lane & 7)) * TROW
                        + (uint32_t)(wn * 64 + (lane >> 4) * 8) * 2;

    auto load_stage = [&](int st, int l0) {
        const uint32_t base = sb + (uint32_t)st * 2 * TTILE;
#pragma unroll
        for (int i = 0; i < 4; i++) {
            const int lin = i * 128 + tid;
            const int row = lin >> 4, seg = lin & 15;
            const uint32_t so = (uint32_t)row * TROW + seg * 16;
            const size_t g = (size_t)(b * LL + l0 + row) * DD + h * DH + seg * 8;
            CP16(base + so, g_feat_f + g);
            CP16(base + TTILE + so, g_v_f + g);
        }
    };

    const int lbase = ch * KCHL;
    load_stage(0, lbase);
    CP_COMMIT();

    for (int c = 0; c < KCHL / 32; c++) {
        if (c + 1 < KCHL / 32) {
            load_stage((c + 1) & 1, lbase + (c + 1) * 32);
            CP_COMMIT();
            CP_WAIT1();
        } else {
            CP_WAIT0();
        }
        __syncthreads();
        const uint32_t base = sb + (uint32_t)(c & 1) * 2 * TTILE;
#pragma unroll
        for (int ks = 0; ks < 2; ks++) {
            const uint32_t kro = (uint32_t)ks * 16 * TROW;
            uint32_t a[4][4], bb[4][4];
#pragma unroll
            for (int mt = 0; mt < 4; mt++)
                LDSM4T(a[mt][0], a[mt][1], a[mt][2], a[mt][3],
                       base + kro + aoff + (uint32_t)mt * 32);
#pragma unroll
            for (int p = 0; p < 4; p++)
                LDSM4T(bb[p][0], bb[p][1], bb[p][2], bb[p][3],
                       base + TTILE + kro + boff + (uint32_t)p * 32);
#pragma unroll
            for (int mt = 0; mt < 4; mt++)
#pragma unroll
                for (int p = 0; p < 4; p++) {
                    mma16816(acc[mt][p * 2 + 0], a[mt], bb[p][0], bb[p][1]);
                    mma16816(acc[mt][p * 2 + 1], a[mt], bb[p][2], bb[p][3]);
                }
        }
        // fused Ksum partial: thread tid sums F smem column tid (32 rows)
        {
            const char* fbase = smem + (size_t)(c & 1) * 2 * TTILE + tid * 2;
#pragma unroll 8
            for (int r = 0; r < 32; r++)
                ks_acc += __half2float(*(const __half*)(fbase + r * TROW));
        }
        __syncthreads();
    }

    g_ksp[(bh * NKCH + ch) * DH + tid] = ks_acc;

    const int gid = lane >> 2, t4 = lane & 3;
    float* outp = g_kvp + ((size_t)bh * NKCH + ch) * (DH * DH);
#pragma unroll
    for (int mt = 0; mt < 4; mt++)
#pragma unroll
        for (int nt = 0; nt < 8; nt++) {
            const float* c = acc[mt][nt];
            const int d0 = wm * 64 + mt * 16 + gid;
            const int vv = wn * 64 + nt * 8 + t4 * 2;
#pragma unroll
            for (int half_ = 0; half_ < 2; half_++) {
                float2 f;
                f.x = c[half_ * 2 + 0];
                f.y = c[half_ * 2 + 1];
                *(float2*)(outp + (d0 + half_ * 8) * DH + vv) = f;
            }
        }
}

// Combined reduce: blocks [0,1024) -> KV partials -> KV^T f16;
//                  block 1024      -> ksum partials -> Ksum
__global__ void attn_reduce_k() {
    if (blockIdx.x < 1024) {
        int o = blockIdx.x * 256 + threadIdx.x;    // BB*HH*16384
        int bh = o >> 14;
        int e = o & 16383;
        int v = e >> 7, d = e & 127;
        float s = 0.f;
        const float* p = g_kvp + (size_t)bh * NKCH * (DH * DH) + d * DH + v;
#pragma unroll
        for (int c = 0; c < NKCH; c++)
            s += p[(size_t)c * (DH * DH)];
        g_kvt[o] = __float2half(s);
    } else {
        // 2048 ksum outputs over blocks [1024, 1032)
        int idx = (blockIdx.x - 1024) * 256 + threadIdx.x;
        int bh = idx >> 7;
        int i = idx & 127;
        float s = 0.f;
#pragma unroll
        for (int c = 0; c < NKCH; c++)
            s += g_ksp[(bh * NKCH + c) * DH + i];
        g_ks[idx] = s;
    }
}

// ---------------------------------------------------------------------------
// msg MMA + fused Z: per (lblock, bh):
//   z[r] = 1/(F[r,:]·Ksum + eps)  computed from staged smem F
//   msg[l, v] = (sum_d F[l,d] * KVT[v,d]) * z
// ---------------------------------------------------------------------------
#define MTILE (128 * TROW)       // 34816 B per array

__global__ void __launch_bounds__(128, 2) msg_mma_k() {
    extern __shared__ __align__(16) char smem[];
    __shared__ float sks[DH];
    __shared__ float sz[128];
    const uint32_t sb = smem_u32(smem);
    const int lb = blockIdx.x, bh = blockIdx.y;
    const int b = bh >> 3, h = bh & 7;
    const int l0 = lb * 128;
    const int tid = threadIdx.x, warp = tid >> 5, lane = tid & 31;
    const int wm = warp >> 1, wn = warp & 1;
    float acc[4][8][4] = {};

    const uint32_t aoff = (uint32_t)(wm * 64 + (lane & 15)) * TROW + ((lane >> 4) << 4);
    const int nloc = (lane & 7) + ((lane >> 4) << 3);
    const uint32_t boff = (uint32_t)(wn * 64 + nloc) * TROW + (((lane >> 3) & 1) << 4);

#pragma unroll
    for (int i = 0; i < 16; i++) {
        const int lin = i * 128 + tid;
        const int row = lin >> 4, seg = lin & 15;
        const uint32_t so = (uint32_t)row * TROW + seg * 16;
        CP16(sb + so, g_feat_f + (size_t)(b * LL + l0 + row) * DD + h * DH + seg * 8);
        CP16(sb + MTILE + so, g_kvt + (size_t)bh * (DH * DH) + row * DH + seg * 8);
    }
    sks[tid] = g_ks[bh * DH + tid];
    CP_COMMIT();
    CP_WAIT0();
    __syncthreads();

    // fused Z: thread tid dots F row tid with Ksum
    {
        const char* frow = smem + (size_t)tid * TROW;
        float dot = 0.f;
#pragma unroll
        for (int j = 0; j < DH; j += 2) {
            __half2 hv = *(const __half2*)(frow + j * 2);
            dot += __half2float(hv.x) * sks[j] + __half2float(hv.y) * sks[j + 1];
        }
        sz[tid] = 1.0f / (dot + ATTN_EPS);
    }

#pragma unroll
    for (int ks = 0; ks < 8; ks++) {
        const uint32_t kso = (uint32_t)ks * 32;
        uint32_t a[4][4], bb[4][4];
#pragma unroll
        for (int mt = 0; mt < 4; mt++)
            LDSM4(a[mt][0], a[mt][1], a[mt][2], a[mt][3],
                  sb + aoff + (uint32_t)mt * 16 * TROW + kso);
#pragma unroll
        for (int p = 0; p < 4; p++)
            LDSM4(bb[p][0], bb[p][1], bb[p][2], bb[p][3],
                  sb + MTILE + boff + (uint32_t)p * 16 * TROW + kso);
#pragma unroll
        for (int mt = 0; mt < 4; mt++)
#pragma unroll
            for (int p = 0; p < 4; p++) {
                mma16816(acc[mt][p * 2 + 0], a[mt], bb[p][0], bb[p][1]);
                mma16816(acc[mt][p * 2 + 1], a[mt], bb[p][2], bb[p][3]);
            }
    }
    __syncthreads();   // sz complete before epilogue reads

    const int gid = lane >> 2, t4 = lane & 3;
#pragma unroll
    for (int mt = 0; mt < 4; mt++)
#pragma unroll
        for (int nt = 0; nt < 8; nt++) {
            const float* c = acc[mt][nt];
            const int lr = wm * 64 + mt * 16 + gid;
            const int cc = wn * 64 + nt * 8 + t4 * 2;
#pragma unroll
            for (int half_ = 0; half_ < 2; half_++) {
                const int lloc = lr + half_ * 8;
                const int n = b * LL + l0 + lloc;
                const float z = sz[lloc];
                __half2 hh;
                hh.x = __float2half(c[half_ * 2 + 0] * z);
                hh.y = __float2half(c[half_ * 2 + 1] * z);
                *(__half2*)(g_msg_f + (size_t)n * DD + h * DH + cc) = hh;
            }
        }
}

// ---------------------------------------------------------------------------
// Conversion kernels
// ---------------------------------------------------------------------------
__global__ void cvt_k(const float* __restrict__ in, __half* __restrict__ o, int n) {
    int i = blockIdx.x * 256 + threadIdx.x;
    if (i < n) o[i] = __float2half(in[i]);
}

// All 4 weight transposes in one launch. Block ranges:
// [0,1024) Wq; [1024,3072) W1; [3072,4096) Wm; [4096,6144) W2.
__global__ void wtrans_all_k(const float* __restrict__ Wq, const float* __restrict__ Wm,
                             const float* __restrict__ W1, const float* __restrict__ W2,
                             __half* __restrict__ Tq, __half* __restrict__ Tm,
                             __half* __restrict__ T1, __half* __restrict__ T2) {
    __shared__ float t[32][33];
    int bid = blockIdx.x;
    const float* W;
    __half* T;
    int K, N, bx, by;
    if (bid < 1024) {            // Wq: K=1024, N=1024, grid 32x32
        W = Wq; T = Tq; K = DD; N = DD;
        bx = bid & 31; by = bid >> 5;
    } else if (bid < 3072) {     // W1: K=1024, N=2048, grid 64x32
        bid -= 1024;
        W = W1; T = T1; K = DD; N = DFF;
        bx = bid & 63; by = bid >> 6;
    } else if (bid < 4096) {     // Wm
        bid -= 3072;
        W = Wm; T = Tm; K = DD; N = DD;
        bx = bid & 31; by = bid >> 5;
    } else {                     // W2: K=2048, N=1024, grid 32x64
        bid -= 4096;
        W = W2; T = T2; K = DFF; N = DD;
        bx = bid & 31; by = bid >> 5;
    }
    const int k0 = by * 32, n0 = bx * 32;
    const int tx = threadIdx.x, ty = threadIdx.y;
#pragma unroll
    for (int i = 0; i < 4; i++)
        t[ty + i * 8][tx] = W[(size_t)(k0 + ty + i * 8) * N + n0 + tx];
    __syncthreads();
#pragma unroll
    for (int i = 0; i < 4; i++)
        T[(size_t)(n0 + ty + i * 8) * K + k0 + tx] = __float2half(t[tx][ty + i * 8]);
}

// ---------------------------------------------------------------------------
// LayerNorm + residual: out[n,:] = base[n,:] + LN(t_f16[n,:])*g + bias
// ---------------------------------------------------------------------------
__device__ __forceinline__ float warpReduceSum(float v) {
#pragma unroll
    for (int o = 16; o > 0; o >>= 1) v += __shfl_xor_sync(0xffffffffu, v, o);
    return v;
}

__global__ void __launch_bounds__(256) ln_k(const __half* __restrict__ t,
                                            const float* __restrict__ base,
                                            const float* __restrict__ gam,
                                            const float* __restrict__ bet,
                                            float* __restrict__ out) {
    const int n = blockIdx.x;
    __shared__ float row[DD];
    __shared__ float rs[8], rs2[8];
    __shared__ float smu, srstd;
    const __half* tp = t + (size_t)n * DD;
    float s = 0.f, s2 = 0.f;
    for (int d = threadIdx.x * 2; d < DD; d += 512) {
        __half2 hv = *(const __half2*)(tp + d);
        float v0 = __half2float(hv.x), v1 = __half2float(hv.y);
        row[d] = v0;
        row[d + 1] = v1;
        s += v0 + v1;
        s2 = fmaf(v0, v0, fmaf(v1, v1, s2));
    }
    s = warpReduceSum(s);
    s2 = warpReduceSum(s2);
    int lane = threadIdx.x & 31, wid = threadIdx.x >> 5;
    if (lane == 0) { rs[wid] = s; rs2[wid] = s2; }
    __syncthreads();
    if (threadIdx.x < 32) {
        float a = (threadIdx.x < 8) ? rs[threadIdx.x] : 0.f;
        float b2 = (threadIdx.x < 8) ? rs2[threadIdx.x] : 0.f;
        a = warpReduceSum(a);
        b2 = warpReduceSum(b2);
        if (threadIdx.x == 0) {
            float mu = a * (1.0f / DD);
            float var = b2 * (1.0f / DD) - mu * mu;
            smu = mu;
            srstd = rsqrtf(var + LN_EPS);
        }
    }
    __syncthreads();
    float mu = smu, rstd = srstd;
    const float* bp = base + (size_t)n * DD;
    float* op = out + (size_t)n * DD;
    for (int d = threadIdx.x; d < DD; d += 256)
        op[d] = bp[d] + (row[d] - mu) * rstd * gam[d] + bet[d];
}

// ---------------------------------------------------------------------------
extern "C" void kernel_launch(void* const* d_in, const int* in_sizes, int n_in,
                              void* d_out, int out_size) {
    (void)in_sizes; (void)n_in; (void)out_size;
    const float* x  = (const float*)d_in[0];
    const float* Wq = (const float*)d_in[1];
    const float* Wm = (const float*)d_in[2];
    const float* W1 = (const float*)d_in[3];
    const float* W2 = (const float*)d_in[4];
    const float* g1 = (const float*)d_in[5];
    const float* b1 = (const float*)d_in[6];
    const float* g2 = (const float*)d_in[7];
    const float* b2 = (const float*)d_in[8];
    float* out = (float*)d_out;

    __half *x_h, *feat_f, *v_f, *msg_f, *tmp_f, *h1_f;
    __half *wq_h, *wm_h, *w1_h, *w2_h;
    cudaGetSymbolAddress((void**)&x_h,    g_x_h);
    cudaGetSymbolAddress((void**)&feat_f, g_feat_f);
    cudaGetSymbolAddress((void**)&v_f,    g_v_f);
    cudaGetSymbolAddress((void**)&msg_f,  g_msg_f);
    cudaGetSymbolAddress((void**)&tmp_f,  g_tmp_f);
    cudaGetSymbolAddress((void**)&h1_f,   g_h1_f);
    cudaGetSymbolAddress((void**)&wq_h,   g_wq_h);
    cudaGetSymbolAddress((void**)&wm_h,   g_wm_h);
    cudaGetSymbolAddress((void**)&w1_h,   g_w1_h);
    cudaGetSymbolAddress((void**)&w2_h,   g_w2_h);

    const int SMM = 2 * MTILE;       // 69632 B (msg, dynamic; +static sks/sz)
    cudaFuncSetAttribute(hgemm_k<1>, cudaFuncAttributeMaxDynamicSharedMemorySize, GSMEM);
    cudaFuncSetAttribute(hgemm_k<2>, cudaFuncAttributeMaxDynamicSharedMemorySize, GSMEM);
    cudaFuncSetAttribute(hgemm_k<3>, cudaFuncAttributeMaxDynamicSharedMemorySize, GSMEM);
    cudaFuncSetAttribute(msg_mma_k, cudaFuncAttributeMaxDynamicSharedMemorySize, SMM);

    // 0. Convert inputs (one launch for all weight transposes)
    cvt_k<<<(NROW * DD + 255) / 256, 256>>>(x, x_h, NROW * DD);
    wtrans_all_k<<<6144, dim3(32, 8)>>>(Wq, Wm, W1, W2, wq_h, wm_h, w1_h, w2_h);

    // 1. q = x @ Wq, epilogue emits feat(q) f16 + q f16
    hgemm_k<3><<<dim3(DD / 128, NROW / 128), 128, GSMEM>>>(
        x_h, wq_h, feat_f, v_f, DD, DD);
    // 2. attention: KV MMA (fused ksum partials), combined reduce
    kv_mma_k<<<dim3(NKCH, BB * HH), 128>>>();
    attn_reduce_k<<<1032, 256>>>();
    // 3. msg (tensor-core, fused Z, f16 out)
    msg_mma_k<<<dim3(LL / 128, BB * HH), 128, SMM>>>();
    // 4. tmp_f = msg @ Wm (f16) -- the rebinded "msg"
    hgemm_k<1><<<dim3(DD / 128, NROW / 128), 128, GSMEM>>>(
        msg_f, wm_h, tmp_f, nullptr, DD, DD);
    // 5. out = x + LN(tmp_f)
    ln_k<<<NROW, 256>>>(tmp_f, x, g1, b1, out);
    // 6. h1 = relu(tmp_f @ W1) (f16)
    hgemm_k<2><<<dim3(DFF / 128, NROW / 128), 128, GSMEM>>>(
        tmp_f, w1_h, h1_f, nullptr, DFF, DD);
    // 7. mlp = h1 @ W2 (f16, reuse msg_f buffer)
    hgemm_k<1><<<dim3(DD / 128, NROW / 128), 128, GSMEM>>>(
        h1_f, w2_h, msg_f, nullptr, DD, DFF);
    // 8. out += LN(mlp)
    ln_k<<<NROW, 256>>>(msg_f, out, g2, b2, out);
}

// round 17
// speedup vs baseline: 2.6340x; 1.0373x over previous
#include <cuda_runtime.h>
#include <cuda_fp16.h>
#include <math.h>
#include <stdint.h>

// Problem constants
#define BB   2
#define LL   8192
#define DD   1024
#define HH   8
#define DH   128
#define NROW (BB*LL)     // 16384
#define DFF  (2*DD)      // 2048
#define NKCH 32          // kv chunk count
#define KCHL (LL/NKCH)   // 256 l-rows per kv chunk
#define ATTN_EPS 1e-6f
#define LN_EPS   1e-5f

// ---------------------------------------------------------------------------
// Scratch (device globals: allocation-free per harness rules)
// ---------------------------------------------------------------------------
__device__ float g_kvp[BB*HH*NKCH*DH*DH];       // KV partials per L-chunk (fp32)
__device__ float g_ksp[BB*HH*NKCH*DH];          // Ksum partials (from kv_mma)
__device__ float g_ks[BB*HH*DH];                // Ksum

// f16 operands
__device__ __half g_x_h[NROW*DD];
__device__ __half g_feat_f[NROW*DD];            // feat(q) = elu(q)+1, f16
__device__ __half g_v_f[NROW*DD];               // q (value, unscaled), f16
__device__ __half g_kvt[BB*HH*DH*DH];           // KV^T [bh][v][d] f16
__device__ __half g_msg_f[NROW*DD];             // attention msg, then reused: mlp out
__device__ __half g_tmp_f[NROW*DD];             // msg@Wm f16 (LN1 input + W1 input)
__device__ __half g_h1_f[NROW*DFF];
// transposed weights [N, K] K-major, f16
__device__ __half g_wq_h[DD*DD];
__device__ __half g_wm_h[DD*DD];
__device__ __half g_w1_h[DFF*DD];
__device__ __half g_w2_h[DD*DFF];

// ---------------------------------------------------------------------------
// Helpers
// ---------------------------------------------------------------------------
__device__ __forceinline__ uint32_t smem_u32(const void* p) {
    uint32_t a;
    asm("{ .reg .u64 t; cvta.to.shared.u64 t, %1; cvt.u32.u64 %0, t; }" : "=r"(a) : "l"(p));
    return a;
}

__device__ __forceinline__ float featf(float v) {
    return v > 0.f ? v + 1.f : expf(v);
}

#define LDSM4(r0, r1, r2, r3, addr) \
    asm volatile("ldmatrix.sync.aligned.m8n8.x4.shared.b16 {%0,%1,%2,%3}, [%4];" \
                 : "=r"(r0), "=r"(r1), "=r"(r2), "=r"(r3) : "r"(addr))
#define LDSM4T(r0, r1, r2, r3, addr) \
    asm volatile("ldmatrix.sync.aligned.m8n8.x4.trans.shared.b16 {%0,%1,%2,%3}, [%4];" \
                 : "=r"(r0), "=r"(r1), "=r"(r2), "=r"(r3) : "r"(addr))

#define CP16(dst, src) \
    asm volatile("cp.async.cg.shared.global [%0], [%1], 16;" :: "r"(dst), "l"(src))
#define CP_COMMIT() asm volatile("cp.async.commit_group;" ::: "memory")
#define CP_WAIT2()  asm volatile("cp.async.wait_group 2;" ::: "memory")
#define CP_WAIT1()  asm volatile("cp.async.wait_group 1;" ::: "memory")
#define CP_WAIT0()  asm volatile("cp.async.wait_group 0;" ::: "memory")

__device__ __forceinline__ void mma16816(float* c, const uint32_t* a,
                                         uint32_t b0, uint32_t b1) {
    asm volatile("mma.sync.aligned.m16n8k16.row.col.f32.f16.f16.f32 "
                 "{%0,%1,%2,%3}, {%4,%5,%6,%7}, {%8,%9}, {%0,%1,%2,%3};"
                 : "+f"(c[0]), "+f"(c[1]), "+f"(c[2]), "+f"(c[3])
                 : "r"(a[0]), "r"(a[1]), "r"(a[2]), "r"(a[3]), "r"(b0), "r"(b1));
}

// ---------------------------------------------------------------------------
// HMMA GEMM: C = A @ B^T, B stored [N,K] K-major, f16 in / fp32 acc / f16 out.
// Block tile 128x128, K-chunk 64, 4 warps (2x2), warp tile 64x64, cp.async 3-stage.
// EPI: 1 = f16 Cf; 2 = relu then f16 Cf; 3 = f16 feat(C)->Cf and f16 C->Cf2.
// ---------------------------------------------------------------------------
#define SROW  144
#define GTILE (128 * SROW)       // 18432 B
#define GSTG  (2 * GTILE)        // A, B = 36864 B
#define GSMEM (3 * GSTG)         // 110592 B, three stages

template <int EPI>
__global__ void __launch_bounds__(128, 2)
hgemm_k(const __half* __restrict__ Ah, const __half* __restrict__ Bh,
        __half* __restrict__ Cf, __half* __restrict__ Cf2, int Nn, int K) {
    extern __shared__ __align__(16) char smem[];
    const uint32_t sb = smem_u32(smem);
    const int tid = threadIdx.x, warp = tid >> 5, lane = tid & 31;
    const int wm = warp >> 1, wn = warp & 1;
    const int m0 = blockIdx.y * 128, n0 = blockIdx.x * 128;

    float acc[4][8][4] = {};

    const uint32_t aoff = (uint32_t)(wm * 64 + (lane & 15)) * SROW + ((lane >> 4) << 4);
    const int nloc = (lane & 7) + ((lane >> 4) << 3);
    const uint32_t boff = (uint32_t)(wn * 64 + nloc) * SROW + (((lane >> 3) & 1) << 4);

    auto load_stage = [&](int s, int kc) {
        const uint32_t base = sb + (uint32_t)s * GSTG;
#pragma unroll
        for (int i = 0; i < 8; i++) {
            const int lin = i * 128 + tid;
            const int r = lin >> 3, seg = lin & 7;
            const uint32_t so = (uint32_t)r * SROW + seg * 16;
            CP16(base + so, Ah + (size_t)(m0 + r) * K + kc + seg * 8);
            CP16(base + GTILE + so, Bh + (size_t)(n0 + r) * K + kc + seg * 8);
        }
    };

    const int nch = K / 64;
    load_stage(0, 0);
    CP_COMMIT();
    if (nch > 1) {
        load_stage(1, 64);
        CP_COMMIT();
    }

    int st = 0, nst = (nch > 2) ? 2 : 0;
    for (int c = 0; c < nch; c++) {
        if (c + 2 < nch) {
            load_stage(nst, (c + 2) * 64);
            CP_COMMIT();
            CP_WAIT2();
        } else if (c + 1 < nch) {
            CP_WAIT1();
        } else {
            CP_WAIT0();
        }
        __syncthreads();
        const uint32_t base = sb + (uint32_t)st * GSTG;
#pragma unroll
        for (int ks = 0; ks < 4; ks++) {
            const uint32_t kso = (uint32_t)ks * 32;
            uint32_t ah[4][4], bh[4][4];
#pragma unroll
            for (int mt = 0; mt < 4; mt++)
                LDSM4(ah[mt][0], ah[mt][1], ah[mt][2], ah[mt][3],
                      base + aoff + (uint32_t)mt * 16 * SROW + kso);
#pragma unroll
            for (int p = 0; p < 4; p++)
                LDSM4(bh[p][0], bh[p][1], bh[p][2], bh[p][3],
                      base + GTILE + boff + (uint32_t)p * 16 * SROW + kso);
#pragma unroll
            for (int mt = 0; mt < 4; mt++)
#pragma unroll
                for (int p = 0; p < 4; p++) {
                    mma16816(acc[mt][p * 2 + 0], ah[mt], bh[p][0], bh[p][1]);
                    mma16816(acc[mt][p * 2 + 1], ah[mt], bh[p][2], bh[p][3]);
                }
        }
        __syncthreads();
        st = (st == 2) ? 0 : st + 1;
        nst = (nst == 2) ? 0 : nst + 1;
    }

    const int gid = lane >> 2, t4 = lane & 3;
#pragma unroll
    for (int mt = 0; mt < 4; mt++) {
#pragma unroll
        for (int nt = 0; nt < 8; nt++) {
            const float* c = acc[mt][nt];
            const int r0 = m0 + wm * 64 + mt * 16 + gid;
            const int cc = n0 + wn * 64 + nt * 8 + t4 * 2;
#pragma unroll
            for (int half_ = 0; half_ < 2; half_++) {
                const int r = r0 + half_ * 8;
                float v0 = c[half_ * 2 + 0], v1 = c[half_ * 2 + 1];
                if (EPI == 1 || EPI == 2) {
                    if (EPI == 2) { v0 = fmaxf(v0, 0.f); v1 = fmaxf(v1, 0.f); }
                    __half2 hh;
                    hh.x = __float2half(v0);
                    hh.y = __float2half(v1);
                    *(__half2*)(Cf + (size_t)r * Nn + cc) = hh;
                }
                if (EPI == 3) {
                    __half2 fh, vh;
                    fh.x = __float2half(featf(v0));
                    fh.y = __float2half(featf(v1));
                    vh.x = __float2half(v0);
                    vh.y = __float2half(v1);
                    *(__half2*)(Cf  + (size_t)r * Nn + cc) = fh;
                    *(__half2*)(Cf2 + (size_t)r * Nn + cc) = vh;
                }
            }
        }
    }
}

// ---------------------------------------------------------------------------
// KV MMA + fused Ksum partial (NKCH=32 chunks for occupancy)
// ---------------------------------------------------------------------------
#define TROW 272                 // 128 f16 + 8 pad = 272 bytes/row
#define TTILE (32 * TROW)        // 8704 B

__global__ void __launch_bounds__(128, 2) kv_mma_k() {
    __shared__ __align__(16) char smem[4 * TTILE];   // 2 stages x (F, V)
    const uint32_t sb = smem_u32(smem);
    const int ch = blockIdx.x, bh = blockIdx.y;
    const int b = bh >> 3, h = bh & 7;
    const int tid = threadIdx.x, warp = tid >> 5, lane = tid & 31;
    const int wm = warp >> 1, wn = warp & 1;
    float acc[4][8][4] = {};
    float ks_acc = 0.f;

    const uint32_t aoff = (uint32_t)((lane >> 4) * 8 + (lane & 7)) * TROW
                        + (uint32_t)(wm * 64 + ((lane >> 3) & 1) * 8) * 2;
    const uint32_t boff = (uint32_t)(((lane >> 3) & 1) * 8 + (lane & 7)) * TROW
                        + (uint32_t)(wn * 64 + (lane >> 4) * 8) * 2;

    auto load_stage = [&](int st, int l0) {
        const uint32_t base = sb + (uint32_t)st * 2 * TTILE;
#pragma unroll
        for (int i = 0; i < 4; i++) {
            const int lin = i * 128 + tid;
            const int row = lin >> 4, seg = lin & 15;
            const uint32_t so = (uint32_t)row * TROW + seg * 16;
            const size_t g = (size_t)(b * LL + l0 + row) * DD + h * DH + seg * 8;
            CP16(base + so, g_feat_f + g);
            CP16(base + TTILE + so, g_v_f + g);
        }
    };

    const int lbase = ch * KCHL;
    load_stage(0, lbase);
    CP_COMMIT();

    for (int c = 0; c < KCHL / 32; c++) {
        if (c + 1 < KCHL / 32) {
            load_stage((c + 1) & 1, lbase + (c + 1) * 32);
            CP_COMMIT();
            CP_WAIT1();
        } else {
            CP_WAIT0();
        }
        __syncthreads();
        const uint32_t base = sb + (uint32_t)(c & 1) * 2 * TTILE;
#pragma unroll
        for (int ks = 0; ks < 2; ks++) {
            const uint32_t kro = (uint32_t)ks * 16 * TROW;
            uint32_t a[4][4], bb[4][4];
#pragma unroll
            for (int mt = 0; mt < 4; mt++)
                LDSM4T(a[mt][0], a[mt][1], a[mt][2], a[mt][3],
                       base + kro + aoff + (uint32_t)mt * 32);
#pragma unroll
            for (int p = 0; p < 4; p++)
                LDSM4T(bb[p][0], bb[p][1], bb[p][2], bb[p][3],
                       base + TTILE + kro + boff + (uint32_t)p * 32);
#pragma unroll
            for (int mt = 0; mt < 4; mt++)
#pragma unroll
                for (int p = 0; p < 4; p++) {
                    mma16816(acc[mt][p * 2 + 0], a[mt], bb[p][0], bb[p][1]);
                    mma16816(acc[mt][p * 2 + 1], a[mt], bb[p][2], bb[p][3]);
                }
        }
        // fused Ksum partial: thread tid sums F smem column tid (32 rows)
        {
            const char* fbase = smem + (size_t)(c & 1) * 2 * TTILE + tid * 2;
#pragma unroll 8
            for (int r = 0; r < 32; r++)
                ks_acc += __half2float(*(const __half*)(fbase + r * TROW));
        }
        __syncthreads();
    }

    g_ksp[(bh * NKCH + ch) * DH + tid] = ks_acc;

    const int gid = lane >> 2, t4 = lane & 3;
    float* outp = g_kvp + ((size_t)bh * NKCH + ch) * (DH * DH);
#pragma unroll
    for (int mt = 0; mt < 4; mt++)
#pragma unroll
        for (int nt = 0; nt < 8; nt++) {
            const float* c = acc[mt][nt];
            const int d0 = wm * 64 + mt * 16 + gid;
            const int vv = wn * 64 + nt * 8 + t4 * 2;
#pragma unroll
            for (int half_ = 0; half_ < 2; half_++) {
                float2 f;
                f.x = c[half_ * 2 + 0];
                f.y = c[half_ * 2 + 1];
                *(float2*)(outp + (d0 + half_ * 8) * DH + vv) = f;
            }
        }
}

// Combined reduce: blocks [0,1024) -> KV partials -> KV^T f16;
//                  blocks [1024,1032) -> ksum partials -> Ksum
__global__ void attn_reduce_k() {
    if (blockIdx.x < 1024) {
        int o = blockIdx.x * 256 + threadIdx.x;    // BB*HH*16384
        int bh = o >> 14;
        int e = o & 16383;
        int v = e >> 7, d = e & 127;
        float s = 0.f;
        const float* p = g_kvp + (size_t)bh * NKCH * (DH * DH) + d * DH + v;
#pragma unroll
        for (int c = 0; c < NKCH; c++)
            s += p[(size_t)c * (DH * DH)];
        g_kvt[o] = __float2half(s);
    } else {
        int idx = (blockIdx.x - 1024) * 256 + threadIdx.x;
        int bh = idx >> 7;
        int i = idx & 127;
        float s = 0.f;
#pragma unroll
        for (int c = 0; c < NKCH; c++)
            s += g_ksp[(bh * NKCH + c) * DH + i];
        g_ks[idx] = s;
    }
}

// ---------------------------------------------------------------------------
// msg MMA + fused Z
// ---------------------------------------------------------------------------
#define MTILE (128 * TROW)       // 34816 B per array

__global__ void __launch_bounds__(128, 2) msg_mma_k() {
    extern __shared__ __align__(16) char smem[];
    __shared__ float sks[DH];
    __shared__ float sz[128];
    const uint32_t sb = smem_u32(smem);
    const int lb = blockIdx.x, bh = blockIdx.y;
    const int b = bh >> 3, h = bh & 7;
    const int l0 = lb * 128;
    const int tid = threadIdx.x, warp = tid >> 5, lane = tid & 31;
    const int wm = warp >> 1, wn = warp & 1;
    float acc[4][8][4] = {};

    const uint32_t aoff = (uint32_t)(wm * 64 + (lane & 15)) * TROW + ((lane >> 4) << 4);
    const int nloc = (lane & 7) + ((lane >> 4) << 3);
    const uint32_t boff = (uint32_t)(wn * 64 + nloc) * TROW + (((lane >> 3) & 1) << 4);

#pragma unroll
    for (int i = 0; i < 16; i++) {
        const int lin = i * 128 + tid;
        const int row = lin >> 4, seg = lin & 15;
        const uint32_t so = (uint32_t)row * TROW + seg * 16;
        CP16(sb + so, g_feat_f + (size_t)(b * LL + l0 + row) * DD + h * DH + seg * 8);
        CP16(sb + MTILE + so, g_kvt + (size_t)bh * (DH * DH) + row * DH + seg * 8);
    }
    sks[tid] = g_ks[bh * DH + tid];
    CP_COMMIT();
    CP_WAIT0();
    __syncthreads();

    // fused Z: thread tid dots F row tid with Ksum
    {
        const char* frow = smem + (size_t)tid * TROW;
        float dot = 0.f;
#pragma unroll
        for (int j = 0; j < DH; j += 2) {
            __half2 hv = *(const __half2*)(frow + j * 2);
            dot += __half2float(hv.x) * sks[j] + __half2float(hv.y) * sks[j + 1];
        }
        sz[tid] = 1.0f / (dot + ATTN_EPS);
    }

#pragma unroll
    for (int ks = 0; ks < 8; ks++) {
        const uint32_t kso = (uint32_t)ks * 32;
        uint32_t a[4][4], bb[4][4];
#pragma unroll
        for (int mt = 0; mt < 4; mt++)
            LDSM4(a[mt][0], a[mt][1], a[mt][2], a[mt][3],
                  sb + aoff + (uint32_t)mt * 16 * TROW + kso);
#pragma unroll
        for (int p = 0; p < 4; p++)
            LDSM4(bb[p][0], bb[p][1], bb[p][2], bb[p][3],
                  sb + MTILE + boff + (uint32_t)p * 16 * TROW + kso);
#pragma unroll
        for (int mt = 0; mt < 4; mt++)
#pragma unroll
            for (int p = 0; p < 4; p++) {
                mma16816(acc[mt][p * 2 + 0], a[mt], bb[p][0], bb[p][1]);
                mma16816(acc[mt][p * 2 + 1], a[mt], bb[p][2], bb[p][3]);
            }
    }
    __syncthreads();

    const int gid = lane >> 2, t4 = lane & 3;
#pragma unroll
    for (int mt = 0; mt < 4; mt++)
#pragma unroll
        for (int nt = 0; nt < 8; nt++) {
            const float* c = acc[mt][nt];
            const int lr = wm * 64 + mt * 16 + gid;
            const int cc = wn * 64 + nt * 8 + t4 * 2;
#pragma unroll
            for (int half_ = 0; half_ < 2; half_++) {
                const int lloc = lr + half_ * 8;
                const int n = b * LL + l0 + lloc;
                const float z = sz[lloc];
                __half2 hh;
                hh.x = __float2half(c[half_ * 2 + 0] * z);
                hh.y = __float2half(c[half_ * 2 + 1] * z);
                *(__half2*)(g_msg_f + (size_t)n * DD + h * DH + cc) = hh;
            }
        }
}

// ---------------------------------------------------------------------------
// Conversion kernels
// ---------------------------------------------------------------------------
__global__ void cvt_k(const float* __restrict__ in, __half* __restrict__ o, int n) {
    int i = blockIdx.x * 256 + threadIdx.x;
    if (i < n) o[i] = __float2half(in[i]);
}

// All 4 weight transposes in one launch.
__global__ void wtrans_all_k(const float* __restrict__ Wq, const float* __restrict__ Wm,
                             const float* __restrict__ W1, const float* __restrict__ W2,
                             __half* __restrict__ Tq, __half* __restrict__ Tm,
                             __half* __restrict__ T1, __half* __restrict__ T2) {
    __shared__ float t[32][33];
    int bid = blockIdx.x;
    const float* W;
    __half* T;
    int K, N, bx, by;
    if (bid < 1024) {
        W = Wq; T = Tq; K = DD; N = DD;
        bx = bid & 31; by = bid >> 5;
    } else if (bid < 3072) {
        bid -= 1024;
        W = W1; T = T1; K = DD; N = DFF;
        bx = bid & 63; by = bid >> 6;
    } else if (bid < 4096) {
        bid -= 3072;
        W = Wm; T = Tm; K = DD; N = DD;
        bx = bid & 31; by = bid >> 5;
    } else {
        bid -= 4096;
        W = W2; T = T2; K = DFF; N = DD;
        bx = bid & 31; by = bid >> 5;
    }
    const int k0 = by * 32, n0 = bx * 32;
    const int tx = threadIdx.x, ty = threadIdx.y;
#pragma unroll
    for (int i = 0; i < 4; i++)
        t[ty + i * 8][tx] = W[(size_t)(k0 + ty + i * 8) * N + n0 + tx];
    __syncthreads();
#pragma unroll
    for (int i = 0; i < 4; i++)
        T[(size_t)(n0 + ty + i * 8) * K + k0 + tx] = __float2half(t[tx][ty + i * 8]);
}

// ---------------------------------------------------------------------------
// Double LayerNorm + residual: out[n,:] = x[n,:] + LN(t1)*g1+b1 + LN(t2)*g2+b2
// ---------------------------------------------------------------------------
__device__ __forceinline__ float warpReduceSum(float v) {
#pragma unroll
    for (int o = 16; o > 0; o >>= 1) v += __shfl_xor_sync(0xffffffffu, v, o);
    return v;
}

__global__ void __launch_bounds__(256) ln2_k(const __half* __restrict__ t1,
                                             const __half* __restrict__ t2,
                                             const float* __restrict__ x,
                                             const float* __restrict__ g1,
                                             const float* __restrict__ b1,
                                             const float* __restrict__ g2,
                                             const float* __restrict__ b2,
                                             float* __restrict__ out) {
    const int n = blockIdx.x;
    __shared__ float row1[DD], row2[DD];
    __shared__ float rs[4][8];
    __shared__ float sstat[4];   // mu1, rstd1, mu2, rstd2
    const __half* tp1 = t1 + (size_t)n * DD;
    const __half* tp2 = t2 + (size_t)n * DD;
    float s1 = 0.f, q1 = 0.f, s2 = 0.f, q2 = 0.f;
    for (int d = threadIdx.x * 2; d < DD; d += 512) {
        __half2 h1 = *(const __half2*)(tp1 + d);
        __half2 h2 = *(const __half2*)(tp2 + d);
        float a0 = __half2float(h1.x), a1 = __half2float(h1.y);
        float c0 = __half2float(h2.x), c1 = __half2float(h2.y);
        row1[d] = a0; row1[d + 1] = a1;
        row2[d] = c0; row2[d + 1] = c1;
        s1 += a0 + a1;
        q1 = fmaf(a0, a0, fmaf(a1, a1, q1));
        s2 += c0 + c1;
        q2 = fmaf(c0, c0, fmaf(c1, c1, q2));
    }
    s1 = warpReduceSum(s1);
    q1 = warpReduceSum(q1);
    s2 = warpReduceSum(s2);
    q2 = warpReduceSum(q2);
    int lane = threadIdx.x & 31, wid = threadIdx.x >> 5;
    if (lane == 0) { rs[0][wid] = s1; rs[1][wid] = q1; rs[2][wid] = s2; rs[3][wid] = q2; }
    __syncthreads();
    if (threadIdx.x < 32) {
        int which = threadIdx.x >> 3;       // 0..3
        float v = rs[which][threadIdx.x & 7];
#pragma unroll
        for (int o = 4; o > 0; o >>= 1) v += __shfl_xor_sync(0xffffffffu, v, o);
        if ((threadIdx.x & 7) == 0) {
            if (which == 0 || which == 2) {
                sstat[which] = v * (1.0f / DD);        // mu
            } else {
                rs[which][0] = v;                      // sumsq stash
            }
        }
    }
    __syncthreads();
    if (threadIdx.x == 0) {
        float mu1 = sstat[0];
        float var1 = rs[1][0] * (1.0f / DD) - mu1 * mu1;
        sstat[1] = rsqrtf(var1 + LN_EPS);
        float mu2 = sstat[2];
        float var2 = rs[3][0] * (1.0f / DD) - mu2 * mu2;
        sstat[3] = rsqrtf(var2 + LN_EPS);
    }
    __syncthreads();
    const float mu1 = sstat[0], rstd1 = sstat[1], mu2 = sstat[2], rstd2 = sstat[3];
    const float* xp = x + (size_t)n * DD;
    float* op = out + (size_t)n * DD;
    for (int d = threadIdx.x; d < DD; d += 256) {
        float v = xp[d]
                + (row1[d] - mu1) * rstd1 * g1[d] + b1[d]
                + (row2[d] - mu2) * rstd2 * g2[d] + b2[d];
        op[d] = v;
    }
}

// ---------------------------------------------------------------------------
extern "C" void kernel_launch(void* const* d_in, const int* in_sizes, int n_in,
                              void* d_out, int out_size) {
    (void)in_sizes; (void)n_in; (void)out_size;
    const float* x  = (const float*)d_in[0];
    const float* Wq = (const float*)d_in[1];
    const float* Wm = (const float*)d_in[2];
    const float* W1 = (const float*)d_in[3];
    const float* W2 = (const float*)d_in[4];
    const float* g1 = (const float*)d_in[5];
    const float* b1 = (const float*)d_in[6];
    const float* g2 = (const float*)d_in[7];
    const float* b2 = (const float*)d_in[8];
    float* out = (float*)d_out;

    __half *x_h, *feat_f, *v_f, *msg_f, *tmp_f, *h1_f;
    __half *wq_h, *wm_h, *w1_h, *w2_h;
    cudaGetSymbolAddress((void**)&x_h,    g_x_h);
    cudaGetSymbolAddress((void**)&feat_f, g_feat_f);
    cudaGetSymbolAddress((void**)&v_f,    g_v_f);
    cudaGetSymbolAddress((void**)&msg_f,  g_msg_f);
    cudaGetSymbolAddress((void**)&tmp_f,  g_tmp_f);
    cudaGetSymbolAddress((void**)&h1_f,   g_h1_f);
    cudaGetSymbolAddress((void**)&wq_h,   g_wq_h);
    cudaGetSymbolAddress((void**)&wm_h,   g_wm_h);
    cudaGetSymbolAddress((void**)&w1_h,   g_w1_h);
    cudaGetSymbolAddress((void**)&w2_h,   g_w2_h);

    const int SMM = 2 * MTILE;       // 69632 B (msg, dynamic; +static sks/sz)
    cudaFuncSetAttribute(hgemm_k<1>, cudaFuncAttributeMaxDynamicSharedMemorySize, GSMEM);
    cudaFuncSetAttribute(hgemm_k<2>, cudaFuncAttributeMaxDynamicSharedMemorySize, GSMEM);
    cudaFuncSetAttribute(hgemm_k<3>, cudaFuncAttributeMaxDynamicSharedMemorySize, GSMEM);
    cudaFuncSetAttribute(msg_mma_k, cudaFuncAttributeMaxDynamicSharedMemorySize, SMM);

    // 0. Convert inputs
    cvt_k<<<(NROW * DD + 255) / 256, 256>>>(x, x_h, NROW * DD);
    wtrans_all_k<<<6144, dim3(32, 8)>>>(Wq, Wm, W1, W2, wq_h, wm_h, w1_h, w2_h);

    // 1. q = x @ Wq, epilogue emits feat(q) f16 + q f16
    hgemm_k<3><<<dim3(DD / 128, NROW / 128), 128, GSMEM>>>(
        x_h, wq_h, feat_f, v_f, DD, DD);
    // 2. attention: KV MMA (fused ksum partials), combined reduce
    kv_mma_k<<<dim3(NKCH, BB * HH), 128>>>();
    attn_reduce_k<<<1032, 256>>>();
    // 3. msg (tensor-core, fused Z, f16 out)
    msg_mma_k<<<dim3(LL / 128, BB * HH), 128, SMM>>>();
    // 4. tmp_f = msg @ Wm (f16) -- the rebinded "msg"
    hgemm_k<1><<<dim3(DD / 128, NROW / 128), 128, GSMEM>>>(
        msg_f, wm_h, tmp_f, nullptr, DD, DD);
    // 5. h1 = relu(tmp_f @ W1) (f16)
    hgemm_k<2><<<dim3(DFF / 128, NROW / 128), 128, GSMEM>>>(
        tmp_f, w1_h, h1_f, nullptr, DFF, DD);
    // 6. mlp = h1 @ W2 (f16, reuse msg_f buffer)
    hgemm_k<1><<<dim3(DD / 128, NROW / 128), 128, GSMEM>>>(
        h1_f, w2_h, msg_f, nullptr, DD, DFF);
    // 7. out = x + LN(tmp_f) + LN(mlp)   (both LayerNorms fused)
    ln2_k<<<NROW, 256>>>(tmp_f, msg_f, x, g1, b1, g2, b2, out);
}